// round 1
// baseline (speedup 1.0000x reference)
#include <cuda_runtime.h>
#include <math.h>

#define NB    16
#define CIN   512
#define NPIX  1024
#define HEADS 8
#define DIMH  64
#define HID   512
#define K3    1536   // 3*HID

// Scratch (allocation-free, device globals)
__device__ float g_wn_qkv[K3 * CIN];                    //  3.1 MB
__device__ float g_wn_out[CIN * HID];                   //  1.0 MB
__device__ float g_qkv[(size_t)NB * K3 * NPIX];         // 100.7 MB
__device__ float g_attn[(size_t)NB * HID * NPIX];       // 33.6 MB

// ---------------------------------------------------------------------------
// Weight normalization: wn[r][c] = w[r][c] / (eps*sqrt(cols) + ||w[r]||)
// (folds Karras forced weight-norm and the conv's 1/sqrt(fan_in))
// ---------------------------------------------------------------------------
__global__ void __launch_bounds__(256) wnorm_kernel(const float* __restrict__ w,
                                                    float* __restrict__ wn, int cols)
{
    int r = blockIdx.x;
    const float* wr = w + (size_t)r * cols;
    float s = 0.f;
    for (int i = threadIdx.x; i < cols; i += 256) { float v = wr[i]; s += v * v; }
    __shared__ float red[8];
#pragma unroll
    for (int off = 16; off; off >>= 1) s += __shfl_xor_sync(0xffffffffu, s, off);
    if ((threadIdx.x & 31) == 0) red[threadIdx.x >> 5] = s;
    __syncthreads();
    if (threadIdx.x == 0) {
        float v = 0.f;
#pragma unroll
        for (int i = 0; i < 8; i++) v += red[i];
        red[0] = v;
    }
    __syncthreads();
    float inv = 1.f / (1e-4f * sqrtf((float)cols) + sqrtf(red[0]));
    for (int i = threadIdx.x; i < cols; i += 256)
        wn[(size_t)r * cols + i] = wr[i] * inv;
}

// ---------------------------------------------------------------------------
// SGEMM: C[b] = A(MDxKD) * B[b](KDxND), batched over B on blockIdx.z.
// 128x128 block tile, BK=8, 8x8 microtile (split 4+4 for conflict-free LDS.128).
// RESID: C = (acc*0.7 + X*0.3)/sqrt(0.58)  (MPAdd epilogue)
// ---------------------------------------------------------------------------
template<int MD, bool RESID>
__global__ void __launch_bounds__(256) sgemm_kernel(const float* __restrict__ A,
                                                    const float* __restrict__ Bm,
                                                    float* __restrict__ Cm,
                                                    const float* __restrict__ X)
{
    constexpr int ND = 1024, KD = 512;
    const int b   = blockIdx.z;
    const int bm0 = blockIdx.y * 128;
    const int bn0 = blockIdx.x * 128;
    const float* Bb = Bm + (size_t)b * KD * ND;
    float* Cb = Cm + (size_t)b * MD * ND;

    __shared__ float As[8][132];
    __shared__ float Bs[8][132];
    float acc[8][8];
#pragma unroll
    for (int i = 0; i < 8; i++)
#pragma unroll
        for (int j = 0; j < 8; j++) acc[i][j] = 0.f;

    const int tid  = threadIdx.x;
    const int tr   = tid >> 4, tc = tid & 15;
    const int arow = tid >> 1, aseg = (tid & 1) * 4;
    const int brow = tid >> 5, bseg = (tid & 31) * 4;

    const float* Aptr = A  + (size_t)(bm0 + arow) * KD + aseg;
    const float* Bptr = Bb + (size_t)brow * ND + bn0 + bseg;

    for (int k0 = 0; k0 < KD; k0 += 8) {
        float4 av = *(const float4*)(Aptr + k0);
        float4 bv = *(const float4*)(Bptr + (size_t)k0 * ND);
        __syncthreads();
        As[aseg + 0][arow] = av.x;
        As[aseg + 1][arow] = av.y;
        As[aseg + 2][arow] = av.z;
        As[aseg + 3][arow] = av.w;
        *(float4*)&Bs[brow][bseg] = bv;
        __syncthreads();
#pragma unroll
        for (int k = 0; k < 8; ++k) {
            float4 a0 = *(const float4*)&As[k][tr * 4];
            float4 a1 = *(const float4*)&As[k][64 + tr * 4];
            float4 b0 = *(const float4*)&Bs[k][tc * 4];
            float4 b1 = *(const float4*)&Bs[k][64 + tc * 4];
            float ar[8] = {a0.x, a0.y, a0.z, a0.w, a1.x, a1.y, a1.z, a1.w};
            float br[8] = {b0.x, b0.y, b0.z, b0.w, b1.x, b1.y, b1.z, b1.w};
#pragma unroll
            for (int i = 0; i < 8; i++)
#pragma unroll
                for (int j = 0; j < 8; j++)
                    acc[i][j] += ar[i] * br[j];
        }
    }

    const float a_out = 0.9191450300f;  // 0.7 / sqrt(0.58)
    const float a_x   = 0.3939192986f;  // 0.3 / sqrt(0.58)
#pragma unroll
    for (int ih = 0; ih < 2; ++ih) {
#pragma unroll
        for (int i = 0; i < 4; ++i) {
            int row = bm0 + ih * 64 + tr * 4 + i;
#pragma unroll
            for (int jh = 0; jh < 2; ++jh) {
                int col = bn0 + jh * 64 + tc * 4;
                float4 v;
                v.x = acc[ih * 4 + i][jh * 4 + 0];
                v.y = acc[ih * 4 + i][jh * 4 + 1];
                v.z = acc[ih * 4 + i][jh * 4 + 2];
                v.w = acc[ih * 4 + i][jh * 4 + 3];
                if (RESID) {
                    float4 xv = *(const float4*)&X[((size_t)b * MD + row) * ND + col];
                    v.x = v.x * a_out + xv.x * a_x;
                    v.y = v.y * a_out + xv.y * a_x;
                    v.z = v.z * a_out + xv.z * a_x;
                    v.w = v.w * a_out + xv.w * a_x;
                }
                *(float4*)&Cb[(size_t)row * ND + col] = v;
            }
        }
    }
}

// ---------------------------------------------------------------------------
// Attention: per (b, h, 64-query tile). Online softmax over 4 mem tokens +
// 1024 spatial keys in 64-wide tiles. pixel_norm fused into tile loads;
// the 1/sqrt(64) sim scale is folded into q's norm factor.
// ---------------------------------------------------------------------------
#define ALD 65   // shared row stride (odd -> low bank conflicts)

__global__ void __launch_bounds__(256) attn_kernel(const float* __restrict__ mem_kv,
                                                   const float* __restrict__ qkv,
                                                   float* __restrict__ attn_out)
{
    extern __shared__ float smf[];
    float* qs = smf;
    float* ks = smf + 64 * ALD;
    float* vs = smf + 2 * 64 * ALD;
    float* ps = smf + 3 * 64 * ALD;

    const int b = blockIdx.z, h = blockIdx.y, i0 = blockIdx.x * 64;
    const int tid = threadIdx.x;
    const float* qbase = qkv + ((size_t)b * K3 + h * DIMH) * NPIX;
    const float* kbase = qbase + (size_t)HID * NPIX;
    const float* vbase = qbase + (size_t)2 * HID * NPIX;

    // Load Q tile [query i][dim d] (coalesced over i)
    {
        int i = tid & 63, d0 = tid >> 6;
#pragma unroll
        for (int d = d0; d < 64; d += 4)
            qs[i * ALD + d] = qbase[(size_t)d * NPIX + i0 + i];
    }
    __syncthreads();
    // pixel_norm q; fold 1/8 scale: net factor = 1/max(||q||, eps)
    {
        int row = tid >> 2, part = tid & 3;
        float s = 0.f;
#pragma unroll
        for (int d = part * 16; d < part * 16 + 16; ++d) {
            float v = qs[row * ALD + d]; s += v * v;
        }
        s += __shfl_xor_sync(0xffffffffu, s, 1);
        s += __shfl_xor_sync(0xffffffffu, s, 2);
        float sc = 1.f / fmaxf(sqrtf(s), 1e-4f);
#pragma unroll
        for (int d = part * 16; d < part * 16 + 16; ++d)
            qs[row * ALD + d] *= sc;
    }
    __syncthreads();

    const int ti = tid >> 4, tj = tid & 15;
    const int r0 = ti * 4, c0 = tj * 4;

    float o[4][4];
#pragma unroll
    for (int i = 0; i < 4; i++)
#pragma unroll
        for (int j = 0; j < 4; j++) o[i][j] = 0.f;
    float mr[4] = {-1e30f, -1e30f, -1e30f, -1e30f};
    float lr[4] = {0.f, 0.f, 0.f, 0.f};

    for (int t = 0; t <= 16; ++t) {
        __syncthreads();   // prior PV consumers done before overwriting ks/vs/ps
        if (t == 0) {
            int r = tid >> 6, d = tid & 63;
            ks[r * ALD + d] = mem_kv[((size_t)h * 4 + r) * 64 + d];
            vs[r * ALD + d] = mem_kv[2048 + ((size_t)h * 4 + r) * 64 + d];
            for (int idx = tid; idx < 60 * 64; idx += 256) {
                int j = 4 + idx / 64, d2 = idx & 63;
                ks[j * ALD + d2] = 0.f;
                vs[j * ALD + d2] = 0.f;
            }
        } else {
            int j = tid & 63, d0 = tid >> 6;
            int jg = (t - 1) * 64 + j;
#pragma unroll
            for (int d = d0; d < 64; d += 4) {
                ks[j * ALD + d] = kbase[(size_t)d * NPIX + jg];
                vs[j * ALD + d] = vbase[(size_t)d * NPIX + jg];
            }
        }
        __syncthreads();
        // pixel_norm k and v rows (factor sqrt(64)=8)
        {
            int row = tid >> 2, part = tid & 3;
            float s1 = 0.f, s2 = 0.f;
#pragma unroll
            for (int d = part * 16; d < part * 16 + 16; ++d) {
                float kv = ks[row * ALD + d]; s1 += kv * kv;
                float vv = vs[row * ALD + d]; s2 += vv * vv;
            }
            s1 += __shfl_xor_sync(0xffffffffu, s1, 1);
            s1 += __shfl_xor_sync(0xffffffffu, s1, 2);
            s2 += __shfl_xor_sync(0xffffffffu, s2, 1);
            s2 += __shfl_xor_sync(0xffffffffu, s2, 2);
            float sc1 = 8.f / fmaxf(sqrtf(s1), 1e-4f);
            float sc2 = 8.f / fmaxf(sqrtf(s2), 1e-4f);
#pragma unroll
            for (int d = part * 16; d < part * 16 + 16; ++d) {
                ks[row * ALD + d] *= sc1;
                vs[row * ALD + d] *= sc2;
            }
        }
        __syncthreads();

        // S = q_hat . k_hat (scale already folded into q)
        float s[4][4];
#pragma unroll
        for (int i = 0; i < 4; i++)
#pragma unroll
            for (int j = 0; j < 4; j++) s[i][j] = 0.f;
#pragma unroll 8
        for (int d = 0; d < 64; ++d) {
            float qa[4], kb[4];
#pragma unroll
            for (int i = 0; i < 4; i++) qa[i] = qs[(r0 + i) * ALD + d];
#pragma unroll
            for (int j = 0; j < 4; j++) kb[j] = ks[(c0 + j) * ALD + d];
#pragma unroll
            for (int i = 0; i < 4; i++)
#pragma unroll
                for (int j = 0; j < 4; j++)
                    s[i][j] += qa[i] * kb[j];
        }
        if (t == 0 && tj != 0) {
#pragma unroll
            for (int i = 0; i < 4; i++)
#pragma unroll
                for (int j = 0; j < 4; j++) s[i][j] = -1e30f;
        }

        // row max across the 16 tj threads
        float tm[4];
#pragma unroll
        for (int i = 0; i < 4; i++)
            tm[i] = fmaxf(fmaxf(s[i][0], s[i][1]), fmaxf(s[i][2], s[i][3]));
#pragma unroll
        for (int off = 1; off < 16; off <<= 1)
#pragma unroll
            for (int i = 0; i < 4; i++)
                tm[i] = fmaxf(tm[i], __shfl_xor_sync(0xffffffffu, tm[i], off));

        float nm[4], al[4], rs[4];
#pragma unroll
        for (int i = 0; i < 4; i++) {
            nm[i] = fmaxf(mr[i], tm[i]);
            al[i] = __expf(mr[i] - nm[i]);
            float r = 0.f;
#pragma unroll
            for (int j = 0; j < 4; j++) {
                float p = __expf(s[i][j] - nm[i]);
                ps[(r0 + i) * ALD + c0 + j] = p;
                r += p;
            }
            rs[i] = r;
        }
#pragma unroll
        for (int off = 1; off < 16; off <<= 1)
#pragma unroll
            for (int i = 0; i < 4; i++)
                rs[i] += __shfl_xor_sync(0xffffffffu, rs[i], off);
#pragma unroll
        for (int i = 0; i < 4; i++) {
            lr[i] = lr[i] * al[i] + rs[i];
            mr[i] = nm[i];
#pragma unroll
            for (int j = 0; j < 4; j++) o[i][j] *= al[i];
        }
        __syncthreads();   // ps visible to all

        // O += P . V   (thread owns rows r0..r0+3, d-cols c0..c0+3)
        int jl = (t == 0) ? 4 : 64;
#pragma unroll 4
        for (int j = 0; j < jl; ++j) {
            float pv[4], vv[4];
#pragma unroll
            for (int i = 0; i < 4; i++) pv[i] = ps[(r0 + i) * ALD + j];
#pragma unroll
            for (int dd = 0; dd < 4; dd++) vv[dd] = vs[j * ALD + c0 + dd];
#pragma unroll
            for (int i = 0; i < 4; i++)
#pragma unroll
                for (int dd = 0; dd < 4; dd++)
                    o[i][dd] += pv[i] * vv[dd];
        }
    }

    __syncthreads();
    // stage O/l through shared for coalesced store
#pragma unroll
    for (int i = 0; i < 4; i++) {
        float inv_l = 1.f / lr[i];
#pragma unroll
        for (int dd = 0; dd < 4; dd++)
            ps[(r0 + i) * ALD + c0 + dd] = o[i][dd] * inv_l;
    }
    __syncthreads();
    {
        int i = tid & 63, d0 = tid >> 6;
        float* ob = attn_out + ((size_t)b * HID + h * DIMH) * NPIX;
#pragma unroll
        for (int d = d0; d < 64; d += 4)
            ob[(size_t)d * NPIX + i0 + i] = ps[i * ALD + d];
    }
}

// ---------------------------------------------------------------------------
extern "C" void kernel_launch(void* const* d_in, const int* in_sizes, int n_in,
                              void* d_out, int out_size)
{
    const float* x      = (const float*)d_in[0];  // [16,512,32,32]
    const float* w_qkv  = (const float*)d_in[1];  // [1536,512]
    const float* w_out  = (const float*)d_in[2];  // [512,512]
    const float* mem_kv = (const float*)d_in[3];  // [2,8,4,64]
    float* out = (float*)d_out;                   // [16,512,32,32]

    float *wnq, *wno, *qkv, *attn;
    cudaGetSymbolAddress((void**)&wnq,  g_wn_qkv);
    cudaGetSymbolAddress((void**)&wno,  g_wn_out);
    cudaGetSymbolAddress((void**)&qkv,  g_qkv);
    cudaGetSymbolAddress((void**)&attn, g_attn);

    const int attn_smem = 4 * 64 * ALD * (int)sizeof(float);  // 66,560 B
    cudaFuncSetAttribute(attn_kernel, cudaFuncAttributeMaxDynamicSharedMemorySize,
                         attn_smem);

    wnorm_kernel<<<K3,  256>>>(w_qkv, wnq, CIN);
    wnorm_kernel<<<CIN, 256>>>(w_out, wno, HID);

    // QKV projection: C[b](1536x1024) = Wn(1536x512) * X[b](512x1024)
    sgemm_kernel<K3, false><<<dim3(1024 / 128, K3 / 128, NB), 256>>>(wnq, x, qkv, nullptr);

    // Attention
    attn_kernel<<<dim3(NPIX / 64, HEADS, NB), 256, attn_smem>>>(mem_kv, qkv, attn);

    // Output projection + MPAdd residual
    sgemm_kernel<CIN, true><<<dim3(1024 / 128, CIN / 128, NB), 256>>>(wno, attn, out, x);
}

// round 3
// speedup vs baseline: 1.8788x; 1.8788x over previous
#include <cuda_runtime.h>
#include <math.h>
#include <stdint.h>

#define NB    16
#define CIN   512
#define NPIX  1024
#define HEADS 8
#define DIMH  64
#define HID   512
#define K3    1536   // 3*HID

// Scratch (allocation-free, device globals)
__device__ float g_wn_qkv[K3 * CIN];                    //  3.1 MB
__device__ float g_wn_out[CIN * HID];                   //  1.0 MB
__device__ float g_qkv[(size_t)NB * K3 * NPIX];         // 100.7 MB
__device__ float g_attn[(size_t)NB * HID * NPIX];       // 33.6 MB

// ---------------------------------------------------------------------------
// helpers
// ---------------------------------------------------------------------------
__device__ __forceinline__ float cvt_tf32(float x) {
    uint32_t u;
    asm("cvt.rna.tf32.f32 %0, %1;" : "=r"(u) : "f"(x));
    return __uint_as_float(u);
}

__device__ __forceinline__ float ex2f(float x) {
    float y;
    asm("ex2.approx.f32 %0, %1;" : "=f"(y) : "f"(x));
    return y;
}

// D += A(16x8) * B(8x8), tf32 inputs (stored as float bit patterns), f32 accum
__device__ __forceinline__ void mma_tf32(float (&d)[4],
                                         const float a0, const float a1,
                                         const float a2, const float a3,
                                         const float b0, const float b1) {
    asm volatile(
        "mma.sync.aligned.m16n8k8.row.col.f32.tf32.tf32.f32 "
        "{%0,%1,%2,%3}, {%4,%5,%6,%7}, {%8,%9}, {%0,%1,%2,%3};"
        : "+f"(d[0]), "+f"(d[1]), "+f"(d[2]), "+f"(d[3])
        : "r"(__float_as_uint(a0)), "r"(__float_as_uint(a1)),
          "r"(__float_as_uint(a2)), "r"(__float_as_uint(a3)),
          "r"(__float_as_uint(b0)), "r"(__float_as_uint(b1)));
}

// ---------------------------------------------------------------------------
// Weight normalization: wn[r][c] = w[r][c] / (eps*sqrt(cols) + ||w[r]||)
// ---------------------------------------------------------------------------
__global__ void __launch_bounds__(256) wnorm_kernel(const float* __restrict__ w,
                                                    float* __restrict__ wn, int cols)
{
    int r = blockIdx.x;
    const float* wr = w + (size_t)r * cols;
    float s = 0.f;
    for (int i = threadIdx.x; i < cols; i += 256) { float v = wr[i]; s += v * v; }
    __shared__ float red[8];
#pragma unroll
    for (int off = 16; off; off >>= 1) s += __shfl_xor_sync(0xffffffffu, s, off);
    if ((threadIdx.x & 31) == 0) red[threadIdx.x >> 5] = s;
    __syncthreads();
    if (threadIdx.x == 0) {
        float v = 0.f;
#pragma unroll
        for (int i = 0; i < 8; i++) v += red[i];
        red[0] = v;
    }
    __syncthreads();
    float inv = 1.f / (1e-4f * sqrtf((float)cols) + sqrtf(red[0]));
    for (int i = threadIdx.x; i < cols; i += 256)
        wn[(size_t)r * cols + i] = wr[i] * inv;
}

// ---------------------------------------------------------------------------
// tf32 tensor-core GEMM: C[b](MDx1024) = A(MDx512) * B[b](512x1024)
// block 128x128, BK=16, 8 warps (2m x 4n), warp tile 64x32 (4 mt x 4 nt of m16n8)
// RESID: C = acc*0.7/sqrt(0.58) + X*0.3/sqrt(0.58)
// ---------------------------------------------------------------------------
#define SA 132   // As/Bs row stride (floats)

template<int MD, bool RESID>
__global__ void __launch_bounds__(256) sgemm_tc(const float* __restrict__ A,
                                                const float* __restrict__ Bm,
                                                float* __restrict__ Cm,
                                                const float* __restrict__ X)
{
    constexpr int ND = 1024, KD = 512;
    const int b   = blockIdx.z;
    const int bm0 = blockIdx.y * 128;
    const int bn0 = blockIdx.x * 128;
    const float* Bb = Bm + (size_t)b * KD * ND;
    float* Cb = Cm + (size_t)b * MD * ND;

    __shared__ float As[16][SA];   // [k][m]
    __shared__ float Bs[16][SA];   // [k][n]

    const int tid = threadIdx.x;
    const int w   = tid >> 5;
    const int lane = tid & 31;
    const int g  = lane >> 2;      // group id 0..7
    const int tg = lane & 3;       // thread in group 0..3
    const int m_off = (w >> 2) * 64;   // 0 or 64
    const int n_off = (w & 3) * 32;    // 0..96

    float acc[4][4][4];
#pragma unroll
    for (int i = 0; i < 4; i++)
#pragma unroll
        for (int j = 0; j < 4; j++)
#pragma unroll
            for (int r = 0; r < 4; r++) acc[i][j][r] = 0.f;

    // global load mapping
    const int am  = tid >> 1;             // A row (two threads per row)  0..127
    const int akq = (tid & 1) * 8;        // A k-quad base (8 floats via 2 float4)
    const int br  = tid >> 5;             // B k-row 0..7 (second pass +8)
    const int bc4 = (tid & 31) * 4;       // B col quad

    for (int k0 = 0; k0 < KD; k0 += 16) {
        float4 av0 = *(const float4*)(A + (size_t)(bm0 + am) * KD + k0 + akq);
        float4 av1 = *(const float4*)(A + (size_t)(bm0 + am) * KD + k0 + akq + 4);
        float4 bv0 = *(const float4*)(Bb + (size_t)(k0 + br) * ND + bn0 + bc4);
        float4 bv1 = *(const float4*)(Bb + (size_t)(k0 + br + 8) * ND + bn0 + bc4);
        __syncthreads();
        As[akq + 0][am] = cvt_tf32(av0.x);
        As[akq + 1][am] = cvt_tf32(av0.y);
        As[akq + 2][am] = cvt_tf32(av0.z);
        As[akq + 3][am] = cvt_tf32(av0.w);
        As[akq + 4][am] = cvt_tf32(av1.x);
        As[akq + 5][am] = cvt_tf32(av1.y);
        As[akq + 6][am] = cvt_tf32(av1.z);
        As[akq + 7][am] = cvt_tf32(av1.w);
        float4 t0 = make_float4(cvt_tf32(bv0.x), cvt_tf32(bv0.y), cvt_tf32(bv0.z), cvt_tf32(bv0.w));
        float4 t1 = make_float4(cvt_tf32(bv1.x), cvt_tf32(bv1.y), cvt_tf32(bv1.z), cvt_tf32(bv1.w));
        *(float4*)&Bs[br][bc4]     = t0;
        *(float4*)&Bs[br + 8][bc4] = t1;
        __syncthreads();

#pragma unroll
        for (int ks = 0; ks < 16; ks += 8) {
            float a[4][4];
#pragma unroll
            for (int mt = 0; mt < 4; mt++) {
                int m = m_off + mt * 16 + g;
                a[mt][0] = As[ks + tg][m];
                a[mt][1] = As[ks + tg][m + 8];
                a[mt][2] = As[ks + 4 + tg][m];
                a[mt][3] = As[ks + 4 + tg][m + 8];
            }
#pragma unroll
            for (int nt = 0; nt < 4; nt++) {
                int n = n_off + nt * 8 + g;
                float b0 = Bs[ks + tg][n];
                float b1 = Bs[ks + 4 + tg][n];
#pragma unroll
                for (int mt = 0; mt < 4; mt++)
                    mma_tf32(acc[mt][nt], a[mt][0], a[mt][1], a[mt][2], a[mt][3], b0, b1);
            }
        }
    }

    const float a_out = 0.9191450300f;  // 0.7 / sqrt(0.58)
    const float a_x   = 0.3939192986f;  // 0.3 / sqrt(0.58)
#pragma unroll
    for (int mt = 0; mt < 4; mt++) {
        int r1 = bm0 + m_off + mt * 16 + g;
        int r2 = r1 + 8;
#pragma unroll
        for (int nt = 0; nt < 4; nt++) {
            int col = bn0 + n_off + nt * 8 + 2 * tg;
            float2 v1 = make_float2(acc[mt][nt][0], acc[mt][nt][1]);
            float2 v2 = make_float2(acc[mt][nt][2], acc[mt][nt][3]);
            if (RESID) {
                float2 x1 = *(const float2*)&X[((size_t)b * MD + r1) * ND + col];
                float2 x2 = *(const float2*)&X[((size_t)b * MD + r2) * ND + col];
                v1.x = v1.x * a_out + x1.x * a_x;  v1.y = v1.y * a_out + x1.y * a_x;
                v2.x = v2.x * a_out + x2.x * a_x;  v2.y = v2.y * a_out + x2.y * a_x;
            }
            *(float2*)&Cb[(size_t)r1 * ND + col] = v1;
            *(float2*)&Cb[(size_t)r2 * ND + col] = v2;
        }
    }
}

// ---------------------------------------------------------------------------
// Flash attention with tf32 mma. Block: 64 queries, 4 warps (warp = 16 queries).
// Online softmax over 1 mem-kv tile (4 valid keys) + 16 spatial tiles of 64.
// pixel_norm fused; log2e folded into q scale so softmax uses ex2.approx.
// smem: Qs[m][d] s68, Ks[d][key] s72, Vs[d][key] s72, Ps[m][key] s68.
// ---------------------------------------------------------------------------
#define QLD 68
#define KLD 72

__global__ void __launch_bounds__(128) attn_tc(const float* __restrict__ mem_kv,
                                               const float* __restrict__ qkv,
                                               float* __restrict__ attn_out)
{
    extern __shared__ float smf[];
    float* qs = smf;                      // 64*68
    float* ps = qs + 64 * QLD;            // 64*68
    float* ks = ps + 64 * QLD;            // 64*72
    float* vs = ks + 64 * KLD;            // 64*72

    const int b = blockIdx.z, h = blockIdx.y, i0 = blockIdx.x * 64;
    const int tid  = threadIdx.x;
    const int lane = tid & 31;
    const int g  = lane >> 2;
    const int tg = lane & 3;
    const int m0 = (tid >> 5) * 16;       // warp query base

    const float* qbase = qkv + ((size_t)b * K3 + h * DIMH) * NPIX;
    const float* kbase = qbase + (size_t)HID * NPIX;
    const float* vbase = qbase + (size_t)2 * HID * NPIX;

    // ---- load + norm Q (scale = log2e / max(||q||, eps); folds 1/sqrt(d) too)
    for (int idx = tid; idx < 64 * 64; idx += 128) {
        int m = idx & 63, d = idx >> 6;
        qs[m * QLD + d] = qbase[(size_t)d * NPIX + i0 + m];
    }
    __syncthreads();
    if (tid < 64) {
        int m = tid;
        float s = 0.f;
#pragma unroll 8
        for (int d = 0; d < 64; ++d) { float v = qs[m * QLD + d]; s += v * v; }
        float sc = 1.4426950408889634f / fmaxf(sqrtf(s), 1e-4f);
#pragma unroll 8
        for (int d = 0; d < 64; ++d) qs[m * QLD + d] = cvt_tf32(qs[m * QLD + d] * sc);
    }
    __syncthreads();

    float oacc[8][4];
#pragma unroll
    for (int nt = 0; nt < 8; nt++)
#pragma unroll
        for (int r = 0; r < 4; r++) oacc[nt][r] = 0.f;
    float mrow[2] = {-1e30f, -1e30f};
    float lrow[2] = {0.f, 0.f};

    for (int t = 0; t <= 16; ++t) {
        __syncthreads();   // prior PV consumers done before overwriting ks/vs/ps
        if (t == 0) {
            // mem-kv tile: 4 valid keys, rest zeroed
            for (int idx = tid; idx < 64 * 64; idx += 128) {
                int d = idx >> 6, key = idx & 63;
                if (key >= 4) { ks[d * KLD + key] = 0.f; vs[d * KLD + key] = 0.f; }
            }
            for (int idx = tid; idx < 4 * 64; idx += 128) {
                int key = idx >> 6, d = idx & 63;
                ks[d * KLD + key] = mem_kv[((size_t)h * 4 + key) * 64 + d];
                vs[d * KLD + key] = mem_kv[2048 + ((size_t)h * 4 + key) * 64 + d];
            }
        } else {
            int jg0 = (t - 1) * 64;
            for (int idx = tid; idx < 64 * 64; idx += 128) {
                int key = idx & 63, d = idx >> 6;
                ks[d * KLD + key] = kbase[(size_t)d * NPIX + jg0 + key];
                vs[d * KLD + key] = vbase[(size_t)d * NPIX + jg0 + key];
            }
        }
        __syncthreads();
        // pixel_norm columns (per key): threads 0-63 -> K, 64-127 -> V
        {
            int key = tid & 63;
            float* base = (tid < 64) ? ks : vs;
            float s = 0.f;
#pragma unroll 8
            for (int d = 0; d < 64; ++d) { float v = base[d * KLD + key]; s += v * v; }
            float sc = 8.f / fmaxf(sqrtf(s), 1e-4f);
#pragma unroll 8
            for (int d = 0; d < 64; ++d)
                base[d * KLD + key] = cvt_tf32(base[d * KLD + key] * sc);
        }
        __syncthreads();

        // ---- S = Q . K^T  (m16 x n64 per warp)
        float sacc[8][4];
#pragma unroll
        for (int nt = 0; nt < 8; nt++)
#pragma unroll
            for (int r = 0; r < 4; r++) sacc[nt][r] = 0.f;
#pragma unroll
        for (int kk = 0; kk < 8; kk++) {
            float a0 = qs[(m0 + g) * QLD + kk * 8 + tg];
            float a1 = qs[(m0 + g + 8) * QLD + kk * 8 + tg];
            float a2 = qs[(m0 + g) * QLD + kk * 8 + tg + 4];
            float a3 = qs[(m0 + g + 8) * QLD + kk * 8 + tg + 4];
#pragma unroll
            for (int nt = 0; nt < 8; nt++) {
                float b0 = ks[(kk * 8 + tg) * KLD + nt * 8 + g];
                float b1 = ks[(kk * 8 + tg + 4) * KLD + nt * 8 + g];
                mma_tf32(sacc[nt], a0, a1, a2, a3, b0, b1);
            }
        }
        if (t == 0) {
#pragma unroll
            for (int nt = 0; nt < 8; nt++) {
                int c0 = nt * 8 + 2 * tg;
                if (c0 >= 4)     { sacc[nt][0] = -1e30f; sacc[nt][2] = -1e30f; }
                if (c0 + 1 >= 4) { sacc[nt][1] = -1e30f; sacc[nt][3] = -1e30f; }
            }
        }

        // ---- online softmax (rows g and g+8 of this warp's 16)
        float tm0 = -1e30f, tm1 = -1e30f;
#pragma unroll
        for (int nt = 0; nt < 8; nt++) {
            tm0 = fmaxf(tm0, fmaxf(sacc[nt][0], sacc[nt][1]));
            tm1 = fmaxf(tm1, fmaxf(sacc[nt][2], sacc[nt][3]));
        }
        tm0 = fmaxf(tm0, __shfl_xor_sync(0xffffffffu, tm0, 1));
        tm0 = fmaxf(tm0, __shfl_xor_sync(0xffffffffu, tm0, 2));
        tm1 = fmaxf(tm1, __shfl_xor_sync(0xffffffffu, tm1, 1));
        tm1 = fmaxf(tm1, __shfl_xor_sync(0xffffffffu, tm1, 2));

        float mn0 = fmaxf(mrow[0], tm0), mn1 = fmaxf(mrow[1], tm1);
        float al0 = ex2f(mrow[0] - mn0), al1 = ex2f(mrow[1] - mn1);
        float rs0 = 0.f, rs1 = 0.f;
#pragma unroll
        for (int nt = 0; nt < 8; nt++) {
            int c = nt * 8 + 2 * tg;
            float p00 = ex2f(sacc[nt][0] - mn0);
            float p01 = ex2f(sacc[nt][1] - mn0);
            float p10 = ex2f(sacc[nt][2] - mn1);
            float p11 = ex2f(sacc[nt][3] - mn1);
            rs0 += p00 + p01;  rs1 += p10 + p11;
            ps[(m0 + g) * QLD + c]     = cvt_tf32(p00);
            ps[(m0 + g) * QLD + c + 1] = cvt_tf32(p01);
            ps[(m0 + g + 8) * QLD + c]     = cvt_tf32(p10);
            ps[(m0 + g + 8) * QLD + c + 1] = cvt_tf32(p11);
        }
        rs0 += __shfl_xor_sync(0xffffffffu, rs0, 1);
        rs0 += __shfl_xor_sync(0xffffffffu, rs0, 2);
        rs1 += __shfl_xor_sync(0xffffffffu, rs1, 1);
        rs1 += __shfl_xor_sync(0xffffffffu, rs1, 2);
        lrow[0] = lrow[0] * al0 + rs0;  mrow[0] = mn0;
        lrow[1] = lrow[1] * al1 + rs1;  mrow[1] = mn1;
#pragma unroll
        for (int nt = 0; nt < 8; nt++) {
            oacc[nt][0] *= al0;  oacc[nt][1] *= al0;
            oacc[nt][2] *= al1;  oacc[nt][3] *= al1;
        }
        __syncwarp();   // ps rows m0..m0+15 written & read within this warp only

        // ---- O += P . V  (m16 x d64 per warp)
        // B-frag element: V[key = kk*8+tg(+4)][d = nt*8+g]; vs is [d][key].
#pragma unroll
        for (int kk = 0; kk < 8; kk++) {
            float a0 = ps[(m0 + g) * QLD + kk * 8 + tg];
            float a1 = ps[(m0 + g + 8) * QLD + kk * 8 + tg];
            float a2 = ps[(m0 + g) * QLD + kk * 8 + tg + 4];
            float a3 = ps[(m0 + g + 8) * QLD + kk * 8 + tg + 4];
#pragma unroll
            for (int nt = 0; nt < 8; nt++) {
                float b0 = vs[(nt * 8 + g) * KLD + kk * 8 + tg];
                float b1 = vs[(nt * 8 + g) * KLD + kk * 8 + tg + 4];
                mma_tf32(oacc[nt], a0, a1, a2, a3, b0, b1);
            }
        }
    }

    // ---- epilogue: stage O/l via ps, then coalesced store
    __syncthreads();
    {
        float il0 = 1.f / lrow[0], il1 = 1.f / lrow[1];
#pragma unroll
        for (int nt = 0; nt < 8; nt++) {
            int c = nt * 8 + 2 * tg;
            *(float2*)&ps[(m0 + g) * QLD + c] =
                make_float2(oacc[nt][0] * il0, oacc[nt][1] * il0);
            *(float2*)&ps[(m0 + g + 8) * QLD + c] =
                make_float2(oacc[nt][2] * il1, oacc[nt][3] * il1);
        }
    }
    __syncthreads();
    {
        float* ob = attn_out + ((size_t)b * HID + h * DIMH) * NPIX;
        for (int idx = tid; idx < 64 * 64; idx += 128) {
            int m = idx & 63, d = idx >> 6;
            ob[(size_t)d * NPIX + i0 + m] = ps[m * QLD + d];
        }
    }
}

// ---------------------------------------------------------------------------
extern "C" void kernel_launch(void* const* d_in, const int* in_sizes, int n_in,
                              void* d_out, int out_size)
{
    const float* x      = (const float*)d_in[0];  // [16,512,32,32]
    const float* w_qkv  = (const float*)d_in[1];  // [1536,512]
    const float* w_out  = (const float*)d_in[2];  // [512,512]
    const float* mem_kv = (const float*)d_in[3];  // [2,8,4,64]
    float* out = (float*)d_out;                   // [16,512,32,32]

    float *wnq, *wno, *qkv, *attn;
    cudaGetSymbolAddress((void**)&wnq,  g_wn_qkv);
    cudaGetSymbolAddress((void**)&wno,  g_wn_out);
    cudaGetSymbolAddress((void**)&qkv,  g_qkv);
    cudaGetSymbolAddress((void**)&attn, g_attn);

    const int attn_smem = (2 * 64 * QLD + 2 * 64 * KLD) * (int)sizeof(float); // 71680
    cudaFuncSetAttribute(attn_tc, cudaFuncAttributeMaxDynamicSharedMemorySize,
                         attn_smem);

    wnorm_kernel<<<K3,  256>>>(w_qkv, wnq, CIN);
    wnorm_kernel<<<CIN, 256>>>(w_out, wno, HID);

    // QKV projection: C[b](1536x1024) = Wn(1536x512) * X[b](512x1024)
    sgemm_tc<K3, false><<<dim3(1024 / 128, K3 / 128, NB), 256>>>(wnq, x, qkv, nullptr);

    // Attention
    attn_tc<<<dim3(NPIX / 64, HEADS, NB), 128, attn_smem>>>(mem_kv, qkv, attn);

    // Output projection + MPAdd residual
    sgemm_tc<CIN, true><<<dim3(1024 / 128, CIN / 128, NB), 256>>>(wno, attn, out, x);
}

// round 5
// speedup vs baseline: 2.9969x; 1.5951x over previous
#include <cuda_runtime.h>
#include <cuda_fp16.h>
#include <math.h>
#include <stdint.h>

#define NB    16
#define CIN   512
#define NPIX  1024
#define HEADS 8
#define DIMH  64
#define HID   512
#define K3    1536   // 3*HID

// Scratch (allocation-free, device globals)
__device__ float  g_wn_qkv[K3 * CIN];
__device__ float  g_wn_out[CIN * HID];
__device__ float  g_qkv[(size_t)NB * K3 * NPIX];          // fp32 QKV (channel-major)
__device__ float  g_attn[(size_t)NB * HID * NPIX];        // fp32 attn out (channel-major)
__device__ __half g_qn[(size_t)NB * HEADS * NPIX * DIMH]; // normalized q [b,h,n,d]
__device__ __half g_kn[(size_t)NB * HEADS * NPIX * DIMH];
__device__ __half g_vn[(size_t)NB * HEADS * NPIX * DIMH];
__device__ __half g_km[HEADS * 4 * DIMH];                 // normalized mem k
__device__ __half g_vm[HEADS * 4 * DIMH];

// ---------------------------------------------------------------------------
// helpers
// ---------------------------------------------------------------------------
__device__ __forceinline__ float cvt_tf32(float x) {
    uint32_t u;
    asm("cvt.rna.tf32.f32 %0, %1;" : "=r"(u) : "f"(x));
    return __uint_as_float(u);
}
__device__ __forceinline__ float ex2f(float x) {
    float y;
    asm("ex2.approx.f32 %0, %1;" : "=f"(y) : "f"(x));
    return y;
}
__device__ __forceinline__ void mma_tf32(float (&d)[4],
                                         const float a0, const float a1,
                                         const float a2, const float a3,
                                         const float b0, const float b1) {
    asm volatile(
        "mma.sync.aligned.m16n8k8.row.col.f32.tf32.tf32.f32 "
        "{%0,%1,%2,%3}, {%4,%5,%6,%7}, {%8,%9}, {%0,%1,%2,%3};"
        : "+f"(d[0]), "+f"(d[1]), "+f"(d[2]), "+f"(d[3])
        : "r"(__float_as_uint(a0)), "r"(__float_as_uint(a1)),
          "r"(__float_as_uint(a2)), "r"(__float_as_uint(a3)),
          "r"(__float_as_uint(b0)), "r"(__float_as_uint(b1)));
}
__device__ __forceinline__ void mma_f16(float (&d)[4],
                                        uint32_t a0, uint32_t a1, uint32_t a2, uint32_t a3,
                                        uint32_t b0, uint32_t b1) {
    asm volatile(
        "mma.sync.aligned.m16n8k16.row.col.f32.f16.f16.f32 "
        "{%0,%1,%2,%3}, {%4,%5,%6,%7}, {%8,%9}, {%0,%1,%2,%3};"
        : "+f"(d[0]), "+f"(d[1]), "+f"(d[2]), "+f"(d[3])
        : "r"(a0), "r"(a1), "r"(a2), "r"(a3), "r"(b0), "r"(b1));
}
__device__ __forceinline__ void ldsm_x4(uint32_t& r0, uint32_t& r1, uint32_t& r2,
                                        uint32_t& r3, uint32_t addr) {
    asm volatile("ldmatrix.sync.aligned.m8n8.x4.shared.b16 {%0,%1,%2,%3}, [%4];"
                 : "=r"(r0), "=r"(r1), "=r"(r2), "=r"(r3) : "r"(addr));
}
__device__ __forceinline__ void ldsm_x4t(uint32_t& r0, uint32_t& r1, uint32_t& r2,
                                         uint32_t& r3, uint32_t addr) {
    asm volatile("ldmatrix.sync.aligned.m8n8.x4.trans.shared.b16 {%0,%1,%2,%3}, [%4];"
                 : "=r"(r0), "=r"(r1), "=r"(r2), "=r"(r3) : "r"(addr));
}

// ---------------------------------------------------------------------------
// Weight normalization: wn[r][c] = w[r][c] / (eps*sqrt(cols) + ||w[r]||)
// ---------------------------------------------------------------------------
__global__ void __launch_bounds__(256) wnorm_kernel(const float* __restrict__ w,
                                                    float* __restrict__ wn, int cols)
{
    int r = blockIdx.x;
    const float* wr = w + (size_t)r * cols;
    float s = 0.f;
    for (int i = threadIdx.x; i < cols; i += 256) { float v = wr[i]; s += v * v; }
    __shared__ float red[8];
#pragma unroll
    for (int off = 16; off; off >>= 1) s += __shfl_xor_sync(0xffffffffu, s, off);
    if ((threadIdx.x & 31) == 0) red[threadIdx.x >> 5] = s;
    __syncthreads();
    if (threadIdx.x == 0) {
        float v = 0.f;
#pragma unroll
        for (int i = 0; i < 8; i++) v += red[i];
        red[0] = v;
    }
    __syncthreads();
    float inv = 1.f / (1e-4f * sqrtf((float)cols) + sqrtf(red[0]));
    for (int i = threadIdx.x; i < cols; i += 256)
        wn[(size_t)r * cols + i] = wr[i] * inv;
}

// ---------------------------------------------------------------------------
// norm_qkv: pixel-norm Q/K/V once, transpose [d][n] -> [n][d], write fp16.
// q scale = log2e/max(||q||,eps); k,v scale = 8/max(||.||,eps).
// block = (128-pixel tile, head, batch), 256 threads
// ---------------------------------------------------------------------------
__global__ void __launch_bounds__(256) norm_qkv(const float* __restrict__ qkv,
                                                __half* __restrict__ qn,
                                                __half* __restrict__ kn,
                                                __half* __restrict__ vn)
{
    __shared__ float sm[64 * 129];
    __shared__ float scl[128];
    const int b = blockIdx.z, h = blockIdx.y, n0 = blockIdx.x * 128;
    const int tid = threadIdx.x;
#pragma unroll
    for (int comp = 0; comp < 3; comp++) {
        const float* src = qkv + ((size_t)b * K3 + comp * HID + h * DIMH) * NPIX + n0;
        __half* dst = (comp == 0 ? qn : comp == 1 ? kn : vn) +
                      ((size_t)(b * HEADS + h) * NPIX + n0) * DIMH;
        __syncthreads();
        for (int idx = tid; idx < 64 * 128; idx += 256) {
            int d = idx >> 7, n = idx & 127;
            sm[d * 129 + n] = src[(size_t)d * NPIX + n];
        }
        __syncthreads();
        if (tid < 128) {
            float s = 0.f;
#pragma unroll 8
            for (int d = 0; d < 64; d++) { float v = sm[d * 129 + tid]; s += v * v; }
            float nrm = fmaxf(sqrtf(s), 1e-4f);
            scl[tid] = (comp == 0 ? 1.4426950408889634f : 8.f) / nrm;
        }
        __syncthreads();
        for (int idx = tid; idx < 128 * 32; idx += 256) {
            int n = idx >> 5, w = idx & 31;
            float s = scl[n];
            __half2 hv = __floats2half2_rn(sm[(2 * w) * 129 + n] * s,
                                           sm[(2 * w + 1) * 129 + n] * s);
            *(__half2*)(dst + (size_t)n * 64 + 2 * w) = hv;
        }
    }
}

// tiny: normalize mem_kv (2*8*4 rows of 64)
__global__ void norm_memkv(const float* __restrict__ mem_kv,
                           __half* __restrict__ km, __half* __restrict__ vm)
{
    int t = threadIdx.x;
    if (t >= 64) return;
    int part = t >> 5, r = t & 31;  // r = h*4+key
    const float* src = mem_kv + part * 2048 + r * 64;
    float s = 0.f;
#pragma unroll 8
    for (int d = 0; d < 64; d++) { float v = src[d]; s += v * v; }
    float sc = 8.f / fmaxf(sqrtf(s), 1e-4f);
    __half* dst = (part ? vm : km) + r * 64;
#pragma unroll 8
    for (int d = 0; d < 64; d++) dst[d] = __float2half(src[d] * sc);
}

// ---------------------------------------------------------------------------
// tf32 tensor-core GEMM (unchanged from round 3)
// ---------------------------------------------------------------------------
#define SA 132

template<int MD, bool RESID>
__global__ void __launch_bounds__(256) sgemm_tc(const float* __restrict__ A,
                                                const float* __restrict__ Bm,
                                                float* __restrict__ Cm,
                                                const float* __restrict__ X)
{
    constexpr int ND = 1024, KD = 512;
    const int b   = blockIdx.z;
    const int bm0 = blockIdx.y * 128;
    const int bn0 = blockIdx.x * 128;
    const float* Bb = Bm + (size_t)b * KD * ND;
    float* Cb = Cm + (size_t)b * MD * ND;

    __shared__ float As[16][SA];
    __shared__ float Bs[16][SA];

    const int tid = threadIdx.x;
    const int w   = tid >> 5;
    const int lane = tid & 31;
    const int g  = lane >> 2;
    const int tg = lane & 3;
    const int m_off = (w >> 2) * 64;
    const int n_off = (w & 3) * 32;

    float acc[4][4][4];
#pragma unroll
    for (int i = 0; i < 4; i++)
#pragma unroll
        for (int j = 0; j < 4; j++)
#pragma unroll
            for (int r = 0; r < 4; r++) acc[i][j][r] = 0.f;

    const int am  = tid >> 1;
    const int akq = (tid & 1) * 8;
    const int br  = tid >> 5;
    const int bc4 = (tid & 31) * 4;

    for (int k0 = 0; k0 < KD; k0 += 16) {
        float4 av0 = *(const float4*)(A + (size_t)(bm0 + am) * KD + k0 + akq);
        float4 av1 = *(const float4*)(A + (size_t)(bm0 + am) * KD + k0 + akq + 4);
        float4 bv0 = *(const float4*)(Bb + (size_t)(k0 + br) * ND + bn0 + bc4);
        float4 bv1 = *(const float4*)(Bb + (size_t)(k0 + br + 8) * ND + bn0 + bc4);
        __syncthreads();
        As[akq + 0][am] = cvt_tf32(av0.x);
        As[akq + 1][am] = cvt_tf32(av0.y);
        As[akq + 2][am] = cvt_tf32(av0.z);
        As[akq + 3][am] = cvt_tf32(av0.w);
        As[akq + 4][am] = cvt_tf32(av1.x);
        As[akq + 5][am] = cvt_tf32(av1.y);
        As[akq + 6][am] = cvt_tf32(av1.z);
        As[akq + 7][am] = cvt_tf32(av1.w);
        float4 t0 = make_float4(cvt_tf32(bv0.x), cvt_tf32(bv0.y), cvt_tf32(bv0.z), cvt_tf32(bv0.w));
        float4 t1 = make_float4(cvt_tf32(bv1.x), cvt_tf32(bv1.y), cvt_tf32(bv1.z), cvt_tf32(bv1.w));
        *(float4*)&Bs[br][bc4]     = t0;
        *(float4*)&Bs[br + 8][bc4] = t1;
        __syncthreads();

#pragma unroll
        for (int ks = 0; ks < 16; ks += 8) {
            float a[4][4];
#pragma unroll
            for (int mt = 0; mt < 4; mt++) {
                int m = m_off + mt * 16 + g;
                a[mt][0] = As[ks + tg][m];
                a[mt][1] = As[ks + tg][m + 8];
                a[mt][2] = As[ks + 4 + tg][m];
                a[mt][3] = As[ks + 4 + tg][m + 8];
            }
#pragma unroll
            for (int nt = 0; nt < 4; nt++) {
                int n = n_off + nt * 8 + g;
                float b0 = Bs[ks + tg][n];
                float b1 = Bs[ks + 4 + tg][n];
#pragma unroll
                for (int mt = 0; mt < 4; mt++)
                    mma_tf32(acc[mt][nt], a[mt][0], a[mt][1], a[mt][2], a[mt][3], b0, b1);
            }
        }
    }

    const float a_out = 0.9191450300f;
    const float a_x   = 0.3939192986f;
#pragma unroll
    for (int mt = 0; mt < 4; mt++) {
        int r1 = bm0 + m_off + mt * 16 + g;
        int r2 = r1 + 8;
#pragma unroll
        for (int nt = 0; nt < 4; nt++) {
            int col = bn0 + n_off + nt * 8 + 2 * tg;
            float2 v1 = make_float2(acc[mt][nt][0], acc[mt][nt][1]);
            float2 v2 = make_float2(acc[mt][nt][2], acc[mt][nt][3]);
            if (RESID) {
                float2 x1 = *(const float2*)&X[((size_t)b * MD + r1) * ND + col];
                float2 x2 = *(const float2*)&X[((size_t)b * MD + r2) * ND + col];
                v1.x = v1.x * a_out + x1.x * a_x;  v1.y = v1.y * a_out + x1.y * a_x;
                v2.x = v2.x * a_out + x2.x * a_x;  v2.y = v2.y * a_out + x2.y * a_x;
            }
            *(float2*)&Cb[(size_t)r1 * ND + col] = v1;
            *(float2*)&Cb[(size_t)r2 * ND + col] = v2;
        }
    }
}

// ---------------------------------------------------------------------------
// fp16 flash attention with ldmatrix. Inputs pre-normalized fp16 [b,h,n,d].
// Block: 64 queries, 4 warps (warp = 16 queries). 17 key tiles of 64.
// smem tiles 64x64 fp16 with XOR swizzle: 16B chunk c of row r stored at c^(r&7).
// Qs[0,8K) Ps[8K,16K) Ks[16K,24K) Vs[24K,32K); epilogue fp32 overlays 8K+.
// ---------------------------------------------------------------------------
__global__ void __launch_bounds__(128) attn_f16(const __half* __restrict__ qn,
                                                const __half* __restrict__ kn,
                                                const __half* __restrict__ vn,
                                                const __half* __restrict__ km,
                                                const __half* __restrict__ vm,
                                                float* __restrict__ attn_out)
{
    __shared__ char smc[32768];
    const uint32_t sb = (uint32_t)__cvta_generic_to_shared(smc);
    const uint32_t QS = sb, PS = sb + 8192, KS = sb + 16384, VS = sb + 24576;

    const int b = blockIdx.z, h = blockIdx.y, i0 = blockIdx.x * 64;
    const int tid = threadIdx.x, lane = tid & 31;
    const int g = lane >> 2, tg = lane & 3;
    const int m0 = (tid >> 5) * 16;

    const __half* qh = qn + ((size_t)(b * HEADS + h) * NPIX + i0) * DIMH;
    const __half* kh = kn + (size_t)(b * HEADS + h) * NPIX * DIMH;
    const __half* vh = vn + (size_t)(b * HEADS + h) * NPIX * DIMH;

    // ---- load Q tile (64 rows x 8 chunks of 16B), swizzled
    for (int idx = tid; idx < 512; idx += 128) {
        int r = idx >> 3, c = idx & 7;
        uint4 v = *(const uint4*)(qh + r * 64 + c * 8);
        *(uint4*)(smc + r * 128 + ((c ^ (r & 7)) << 4)) = v;
    }
    __syncthreads();

    // ---- Q fragments (invariant across tiles): aq[kc] = {a0,a1,a2,a3}
    uint32_t aq[4][4];
    {
        int mat = lane >> 3, rr = lane & 7;
        int qrow = m0 + (mat & 1) * 8 + rr;
#pragma unroll
        for (int kc = 0; kc < 4; kc++) {
            int ch = 2 * kc + (mat >> 1);
            uint32_t addr = QS + qrow * 128 + ((ch ^ (qrow & 7)) << 4);
            ldsm_x4(aq[kc][0], aq[kc][1], aq[kc][2], aq[kc][3], addr);
        }
    }

    float oacc[8][4];
#pragma unroll
    for (int nt = 0; nt < 8; nt++)
#pragma unroll
        for (int r = 0; r < 4; r++) oacc[nt][r] = 0.f;
    float mrow[2] = {-1e30f, -1e30f};
    float lrow[2] = {0.f, 0.f};

    for (int t = 0; t <= 16; ++t) {
        __syncthreads();   // previous tile's PV consumers done
        if (t == 0) {
            for (int idx = tid; idx < 512; idx += 128) {
                int r = idx >> 3, c = idx & 7;
                uint4 kv = make_uint4(0, 0, 0, 0), vv = make_uint4(0, 0, 0, 0);
                if (r < 4) {
                    kv = *(const uint4*)(km + (h * 4 + r) * 64 + c * 8);
                    vv = *(const uint4*)(vm + (h * 4 + r) * 64 + c * 8);
                }
                uint32_t off = r * 128 + ((c ^ (r & 7)) << 4);
                *(uint4*)(smc + 16384 + off) = kv;
                *(uint4*)(smc + 24576 + off) = vv;
            }
        } else {
            const __half* kt = kh + (size_t)(t - 1) * 64 * 64;
            const __half* vt = vh + (size_t)(t - 1) * 64 * 64;
            for (int idx = tid; idx < 512; idx += 128) {
                int r = idx >> 3, c = idx & 7;
                uint32_t off = r * 128 + ((c ^ (r & 7)) << 4);
                *(uint4*)(smc + 16384 + off) = *(const uint4*)(kt + r * 64 + c * 8);
                *(uint4*)(smc + 24576 + off) = *(const uint4*)(vt + r * 64 + c * 8);
            }
        }
        __syncthreads();

        // ---- S = Q.K^T (m16 x n64 per warp), fp16 k16 mma
        float sacc[8][4];
#pragma unroll
        for (int nt = 0; nt < 8; nt++)
#pragma unroll
            for (int r = 0; r < 4; r++) sacc[nt][r] = 0.f;
        {
            int mat = lane >> 3, rr = lane & 7;
#pragma unroll
            for (int np = 0; np < 4; np++) {
                int key = (2 * np + (mat >> 1)) * 8 + rr;
#pragma unroll
                for (int kc = 0; kc < 4; kc++) {
                    int ch = 2 * kc + (mat & 1);
                    uint32_t addr = KS + key * 128 + ((ch ^ (key & 7)) << 4);
                    uint32_t b0, b1, b2, b3;
                    ldsm_x4(b0, b1, b2, b3, addr);
                    mma_f16(sacc[2 * np],     aq[kc][0], aq[kc][1], aq[kc][2], aq[kc][3], b0, b1);
                    mma_f16(sacc[2 * np + 1], aq[kc][0], aq[kc][1], aq[kc][2], aq[kc][3], b2, b3);
                }
            }
        }
        if (t == 0) {
#pragma unroll
            for (int nt = 0; nt < 8; nt++) {
                int c0 = nt * 8 + 2 * tg;
                if (c0 >= 4)     { sacc[nt][0] = -1e30f; sacc[nt][2] = -1e30f; }
                if (c0 + 1 >= 4) { sacc[nt][1] = -1e30f; sacc[nt][3] = -1e30f; }
            }
        }

        // ---- online softmax (rows m0+g and m0+g+8)
        float tm0 = -1e30f, tm1 = -1e30f;
#pragma unroll
        for (int nt = 0; nt < 8; nt++) {
            tm0 = fmaxf(tm0, fmaxf(sacc[nt][0], sacc[nt][1]));
            tm1 = fmaxf(tm1, fmaxf(sacc[nt][2], sacc[nt][3]));
        }
        tm0 = fmaxf(tm0, __shfl_xor_sync(0xffffffffu, tm0, 1));
        tm0 = fmaxf(tm0, __shfl_xor_sync(0xffffffffu, tm0, 2));
        tm1 = fmaxf(tm1, __shfl_xor_sync(0xffffffffu, tm1, 1));
        tm1 = fmaxf(tm1, __shfl_xor_sync(0xffffffffu, tm1, 2));

        float mn0 = fmaxf(mrow[0], tm0), mn1 = fmaxf(mrow[1], tm1);
        float al0 = ex2f(mrow[0] - mn0), al1 = ex2f(mrow[1] - mn1);
        float rs0 = 0.f, rs1 = 0.f;
        const int row0 = m0 + g, row1 = m0 + g + 8;
#pragma unroll
        for (int nt = 0; nt < 8; nt++) {
            float p00 = ex2f(sacc[nt][0] - mn0);
            float p01 = ex2f(sacc[nt][1] - mn0);
            float p10 = ex2f(sacc[nt][2] - mn1);
            float p11 = ex2f(sacc[nt][3] - mn1);
            rs0 += p00 + p01;  rs1 += p10 + p11;
            uint32_t a0 = PS + row0 * 128 + ((nt ^ (row0 & 7)) << 4) + (tg << 2);
            uint32_t a1 = PS + row1 * 128 + ((nt ^ (row1 & 7)) << 4) + (tg << 2);
            __half2 h0 = __floats2half2_rn(p00, p01);
            __half2 h1 = __floats2half2_rn(p10, p11);
            asm volatile("st.shared.b32 [%0], %1;" :: "r"(a0), "r"(*(uint32_t*)&h0));
            asm volatile("st.shared.b32 [%0], %1;" :: "r"(a1), "r"(*(uint32_t*)&h1));
        }
        rs0 += __shfl_xor_sync(0xffffffffu, rs0, 1);
        rs0 += __shfl_xor_sync(0xffffffffu, rs0, 2);
        rs1 += __shfl_xor_sync(0xffffffffu, rs1, 1);
        rs1 += __shfl_xor_sync(0xffffffffu, rs1, 2);
        lrow[0] = lrow[0] * al0 + rs0;  mrow[0] = mn0;
        lrow[1] = lrow[1] * al1 + rs1;  mrow[1] = mn1;
#pragma unroll
        for (int nt = 0; nt < 8; nt++) {
            oacc[nt][0] *= al0;  oacc[nt][1] *= al0;
            oacc[nt][2] *= al1;  oacc[nt][3] *= al1;
        }
        __syncwarp();   // Ps rows m0..m0+15 are warp-private

        // ---- O += P.V (m16 x d64 per warp); V B-frags via trans ldmatrix
        {
            int mat = lane >> 3, rr = lane & 7;
#pragma unroll
            for (int kc = 0; kc < 4; kc++) {
                int prow = m0 + (mat & 1) * 8 + rr;
                int pch = 2 * kc + (mat >> 1);
                uint32_t paddr = PS + prow * 128 + ((pch ^ (prow & 7)) << 4);
                uint32_t a0, a1, a2, a3;
                ldsm_x4(a0, a1, a2, a3, paddr);
                int key = kc * 16 + (mat & 1) * 8 + rr;
#pragma unroll
                for (int np = 0; np < 4; np++) {
                    int ch = 2 * np + (mat >> 1);
                    uint32_t vaddr = VS + key * 128 + ((ch ^ (key & 7)) << 4);
                    uint32_t b0, b1, b2, b3;
                    ldsm_x4t(b0, b1, b2, b3, vaddr);
                    mma_f16(oacc[2 * np],     a0, a1, a2, a3, b0, b1);
                    mma_f16(oacc[2 * np + 1], a0, a1, a2, a3, b2, b3);
                }
            }
        }
    }

    // ---- epilogue: normalize, stage fp32 (overlays Ps/Ks), coalesced store
    __syncthreads();
    float* fs = (float*)(smc + 8192);   // 64 x stride 66 = 16.9 KB
    {
        float il0 = 1.f / lrow[0], il1 = 1.f / lrow[1];
        const int row0 = m0 + g, row1 = m0 + g + 8;
#pragma unroll
        for (int nt = 0; nt < 8; nt++) {
            int c = nt * 8 + 2 * tg;
            fs[row0 * 66 + c]     = oacc[nt][0] * il0;
            fs[row0 * 66 + c + 1] = oacc[nt][1] * il0;
            fs[row1 * 66 + c]     = oacc[nt][2] * il1;
            fs[row1 * 66 + c + 1] = oacc[nt][3] * il1;
        }
    }
    __syncthreads();
    {
        float* ob = attn_out + ((size_t)b * HID + h * DIMH) * NPIX;
        for (int idx = tid; idx < 64 * 64; idx += 128) {
            int m = idx & 63, d = idx >> 6;
            ob[(size_t)d * NPIX + i0 + m] = fs[m * 66 + d];
        }
    }
}

// ---------------------------------------------------------------------------
extern "C" void kernel_launch(void* const* d_in, const int* in_sizes, int n_in,
                              void* d_out, int out_size)
{
    const float* x      = (const float*)d_in[0];  // [16,512,32,32]
    const float* w_qkv  = (const float*)d_in[1];  // [1536,512]
    const float* w_out  = (const float*)d_in[2];  // [512,512]
    const float* mem_kv = (const float*)d_in[3];  // [2,8,4,64]
    float* out = (float*)d_out;                   // [16,512,32,32]

    float *wnq, *wno, *qkv, *attn;
    __half *qn, *kn, *vn, *km, *vm;
    cudaGetSymbolAddress((void**)&wnq,  g_wn_qkv);
    cudaGetSymbolAddress((void**)&wno,  g_wn_out);
    cudaGetSymbolAddress((void**)&qkv,  g_qkv);
    cudaGetSymbolAddress((void**)&attn, g_attn);
    cudaGetSymbolAddress((void**)&qn,   g_qn);
    cudaGetSymbolAddress((void**)&kn,   g_kn);
    cudaGetSymbolAddress((void**)&vn,   g_vn);
    cudaGetSymbolAddress((void**)&km,   g_km);
    cudaGetSymbolAddress((void**)&vm,   g_vm);

    wnorm_kernel<<<K3,  256>>>(w_qkv, wnq, CIN);
    wnorm_kernel<<<CIN, 256>>>(w_out, wno, HID);

    // QKV projection: C[b](1536x1024) = Wn(1536x512) * X[b](512x1024)
    sgemm_tc<K3, false><<<dim3(1024 / 128, K3 / 128, NB), 256>>>(wnq, x, qkv, nullptr);

    // Normalize q/k/v (+ mem_kv) into fp16 [b,h,n,d]
    norm_memkv<<<1, 64>>>(mem_kv, km, vm);
    norm_qkv<<<dim3(NPIX / 128, HEADS, NB), 256>>>(qkv, qn, kn, vn);

    // Attention
    attn_f16<<<dim3(NPIX / 64, HEADS, NB), 128>>>(qn, kn, vn, km, vm, attn);

    // Output projection + MPAdd residual
    sgemm_tc<CIN, true><<<dim3(1024 / 128, CIN / 128, NB), 256>>>(wno, attn, out, x);
}

// round 6
// speedup vs baseline: 4.8035x; 1.6028x over previous
#include <cuda_runtime.h>
#include <cuda_fp16.h>
#include <math.h>
#include <stdint.h>

#define NB    16
#define CIN   512
#define NPIX  1024
#define HEADS 8
#define DIMH  64
#define HID   512
#define K3    1536   // 3*HID

// Scratch (allocation-free, device globals)
__device__ __half g_wn_qkv[K3 * CIN];                     // fp16 normalized w_qkv
__device__ __half g_wn_out[CIN * HID];                    // fp16 normalized w_out
__device__ __half g_qkv[(size_t)NB * K3 * NPIX];          // fp16 QKV (channel-major)
__device__ __half g_attn[(size_t)NB * HID * NPIX];        // fp16 attn out (channel-major)
__device__ __half g_qn[(size_t)NB * HEADS * NPIX * DIMH]; // normalized q [b,h,n,d]
__device__ __half g_kn[(size_t)NB * HEADS * NPIX * DIMH];
__device__ __half g_vn[(size_t)NB * HEADS * NPIX * DIMH];
__device__ __half g_km[HEADS * 4 * DIMH];
__device__ __half g_vm[HEADS * 4 * DIMH];

// ---------------------------------------------------------------------------
// helpers
// ---------------------------------------------------------------------------
__device__ __forceinline__ float ex2f(float x) {
    float y;
    asm("ex2.approx.f32 %0, %1;" : "=f"(y) : "f"(x));
    return y;
}
__device__ __forceinline__ void mma_f16(float (&d)[4],
                                        uint32_t a0, uint32_t a1, uint32_t a2, uint32_t a3,
                                        uint32_t b0, uint32_t b1) {
    asm volatile(
        "mma.sync.aligned.m16n8k16.row.col.f32.f16.f16.f32 "
        "{%0,%1,%2,%3}, {%4,%5,%6,%7}, {%8,%9}, {%0,%1,%2,%3};"
        : "+f"(d[0]), "+f"(d[1]), "+f"(d[2]), "+f"(d[3])
        : "r"(a0), "r"(a1), "r"(a2), "r"(a3), "r"(b0), "r"(b1));
}
__device__ __forceinline__ void ldsm_x4(uint32_t& r0, uint32_t& r1, uint32_t& r2,
                                        uint32_t& r3, uint32_t addr) {
    asm volatile("ldmatrix.sync.aligned.m8n8.x4.shared.b16 {%0,%1,%2,%3}, [%4];"
                 : "=r"(r0), "=r"(r1), "=r"(r2), "=r"(r3) : "r"(addr));
}
__device__ __forceinline__ void ldsm_x4t(uint32_t& r0, uint32_t& r1, uint32_t& r2,
                                         uint32_t& r3, uint32_t addr) {
    asm volatile("ldmatrix.sync.aligned.m8n8.x4.trans.shared.b16 {%0,%1,%2,%3}, [%4];"
                 : "=r"(r0), "=r"(r1), "=r"(r2), "=r"(r3) : "r"(addr));
}

// ---------------------------------------------------------------------------
// Merged weight normalization (both weights have fan-in 512):
// wn[r][c] = w[r][c] / (eps*sqrt(512) + ||w[r]||), written fp16.
// Blocks [0,K3) -> w_qkv, [K3,K3+CIN) -> w_out.
// ---------------------------------------------------------------------------
__global__ void __launch_bounds__(256) wnorm2_kernel(const float* __restrict__ w_qkv,
                                                     const float* __restrict__ w_out,
                                                     __half* __restrict__ wnq,
                                                     __half* __restrict__ wno)
{
    int r = blockIdx.x;
    const float* wr;
    __half* out;
    if (r < K3) { wr = w_qkv + (size_t)r * CIN;        out = wnq + (size_t)r * CIN; }
    else        { wr = w_out + (size_t)(r - K3) * HID; out = wno + (size_t)(r - K3) * HID; }
    float s = 0.f;
    for (int i = threadIdx.x; i < 512; i += 256) { float v = wr[i]; s += v * v; }
    __shared__ float red[8];
#pragma unroll
    for (int off = 16; off; off >>= 1) s += __shfl_xor_sync(0xffffffffu, s, off);
    if ((threadIdx.x & 31) == 0) red[threadIdx.x >> 5] = s;
    __syncthreads();
    if (threadIdx.x == 0) {
        float v = 0.f;
#pragma unroll
        for (int i = 0; i < 8; i++) v += red[i];
        red[0] = v;
    }
    __syncthreads();
    float inv = 1.f / (1e-4f * 22.627416998f + sqrtf(red[0]));  // eps*sqrt(512)
    for (int i = threadIdx.x; i < 512; i += 256)
        out[i] = __float2half(wr[i] * inv);
}

// ---------------------------------------------------------------------------
// norm_qkv: pixel-norm Q/K/V once (fp16 in), transpose [d][n]->[n][d], fp16 out.
// q scale = log2e/max(||q||,eps); k,v scale = 8/max(||.||,eps).
// ---------------------------------------------------------------------------
__global__ void __launch_bounds__(256) norm_qkv(const __half* __restrict__ qkv,
                                                __half* __restrict__ qn,
                                                __half* __restrict__ kn,
                                                __half* __restrict__ vn)
{
    __shared__ float sm[64 * 129];
    __shared__ float scl[128];
    const int b = blockIdx.z, h = blockIdx.y, n0 = blockIdx.x * 128;
    const int tid = threadIdx.x;
#pragma unroll
    for (int comp = 0; comp < 3; comp++) {
        const __half* src = qkv + ((size_t)b * K3 + comp * HID + h * DIMH) * NPIX + n0;
        __half* dst = (comp == 0 ? qn : comp == 1 ? kn : vn) +
                      ((size_t)(b * HEADS + h) * NPIX + n0) * DIMH;
        __syncthreads();
        for (int idx = tid; idx < 64 * 128; idx += 256) {
            int d = idx >> 7, n = idx & 127;
            sm[d * 129 + n] = __half2float(src[(size_t)d * NPIX + n]);
        }
        __syncthreads();
        if (tid < 128) {
            float s = 0.f;
#pragma unroll 8
            for (int d = 0; d < 64; d++) { float v = sm[d * 129 + tid]; s += v * v; }
            float nrm = fmaxf(sqrtf(s), 1e-4f);
            scl[tid] = (comp == 0 ? 1.4426950408889634f : 8.f) / nrm;
        }
        __syncthreads();
        for (int idx = tid; idx < 128 * 32; idx += 256) {
            int n = idx >> 5, w = idx & 31;
            float s = scl[n];
            __half2 hv = __floats2half2_rn(sm[(2 * w) * 129 + n] * s,
                                           sm[(2 * w + 1) * 129 + n] * s);
            *(__half2*)(dst + (size_t)n * 64 + 2 * w) = hv;
        }
    }
}

// tiny: normalize mem_kv (2*8*4 rows of 64)
__global__ void norm_memkv(const float* __restrict__ mem_kv,
                           __half* __restrict__ km, __half* __restrict__ vm)
{
    int t = threadIdx.x;
    if (t >= 64) return;
    int part = t >> 5, r = t & 31;  // r = h*4+key
    const float* src = mem_kv + part * 2048 + r * 64;
    float s = 0.f;
#pragma unroll 8
    for (int d = 0; d < 64; d++) { float v = src[d]; s += v * v; }
    float sc = 8.f / fmaxf(sqrtf(s), 1e-4f);
    __half* dst = (part ? vm : km) + r * 64;
#pragma unroll 8
    for (int d = 0; d < 64; d++) dst[d] = __float2half(src[d] * sc);
}

// ---------------------------------------------------------------------------
// fp16 tensor-core GEMM: C[b](MDx1024) = A(MDx512) * B[b](512x1024)
// A fp16 row-major [m][k]; B [k][n] fp32 (BHALF=0) or fp16 (BHALF=1).
// Block 128x128, BK=64, 8 warps (2m x 4n), warp 64x32, m16n8k16 + ldmatrix.
// smem: As [m=128][k=64] fp16 rows 128B swizzle c^(r&7) (16KB);
//       Bs [k=64][n=128] fp16 rows 256B swizzle low3(c)^(k&7) (16KB).
// Reg-prefetch pipeline: load k0+64 while computing k0.
// OUTH: write fp16 C. RESID: C = acc*0.7/sqrt(.58) + X*0.3/sqrt(.58) (fp32 out).
// ---------------------------------------------------------------------------
template<int MD, bool RESID, bool BHALF, bool OUTH>
__global__ void __launch_bounds__(256) hgemm_tc(const __half* __restrict__ A,
                                                const void* __restrict__ Bm,
                                                void* __restrict__ Cm,
                                                const float* __restrict__ X)
{
    constexpr int ND = 1024, KD = 512;
    __shared__ char smc[32768];
    const uint32_t sb = (uint32_t)__cvta_generic_to_shared(smc);
    const uint32_t AS = sb, BS = sb + 16384;

    const int b   = blockIdx.z;
    const int bm0 = blockIdx.y * 128;
    const int bn0 = blockIdx.x * 128;
    const __half* Bh = (const __half*)Bm + (size_t)b * KD * ND;
    const float*  Bf = (const float*)Bm + (size_t)b * KD * ND;

    const int tid = threadIdx.x;
    const int w = tid >> 5, lane = tid & 31;
    const int g = lane >> 2, tg = lane & 3;
    const int mat = lane >> 3, rr = lane & 7;
    const int m_off = (w >> 2) * 64;
    const int n_off = (w & 3) * 32;

    float acc[4][4][4];
#pragma unroll
    for (int i = 0; i < 4; i++)
#pragma unroll
        for (int j = 0; j < 4; j++)
#pragma unroll
            for (int r = 0; r < 4; r++) acc[i][j][r] = 0.f;

    // staging maps: A 1024 chunks (128r x 8c), B 1024 chunks (64r x 16c)
    int ar[4], ac[4], br_[4], bc[4];
#pragma unroll
    for (int i = 0; i < 4; i++) {
        int cid = i * 256 + tid;
        ar[i] = cid >> 3;  ac[i] = cid & 7;
        br_[i] = cid >> 4; bc[i] = cid & 15;
    }

    uint4 aR[4], bR[4];
    float4 bF0[4], bF1[4];

    // prologue loads (k0 = 0)
#pragma unroll
    for (int i = 0; i < 4; i++) {
        aR[i] = *(const uint4*)(A + (size_t)(bm0 + ar[i]) * KD + ac[i] * 8);
        if (BHALF) {
            bR[i] = *(const uint4*)(Bh + (size_t)br_[i] * ND + bn0 + bc[i] * 8);
        } else {
            bF0[i] = *(const float4*)(Bf + (size_t)br_[i] * ND + bn0 + bc[i] * 8);
            bF1[i] = *(const float4*)(Bf + (size_t)br_[i] * ND + bn0 + bc[i] * 8 + 4);
        }
    }

    for (int it = 0; it < 8; ++it) {
        __syncthreads();
        // store staged regs -> smem (fp16, swizzled)
#pragma unroll
        for (int i = 0; i < 4; i++) {
            *(uint4*)(smc + ar[i] * 128 + ((ac[i] ^ (ar[i] & 7)) << 4)) = aR[i];
            uint32_t boff = 16384 + br_[i] * 256 +
                            (((bc[i] & 8) | ((bc[i] & 7) ^ (br_[i] & 7))) << 4);
            if (BHALF) {
                *(uint4*)(smc + boff) = bR[i];
            } else {
                __half2 h0 = __floats2half2_rn(bF0[i].x, bF0[i].y);
                __half2 h1 = __floats2half2_rn(bF0[i].z, bF0[i].w);
                __half2 h2 = __floats2half2_rn(bF1[i].x, bF1[i].y);
                __half2 h3 = __floats2half2_rn(bF1[i].z, bF1[i].w);
                uint4 pk;
                pk.x = *(uint32_t*)&h0; pk.y = *(uint32_t*)&h1;
                pk.z = *(uint32_t*)&h2; pk.w = *(uint32_t*)&h3;
                *(uint4*)(smc + boff) = pk;
            }
        }
        __syncthreads();

        // prefetch next k-slab while computing this one
        if (it < 7) {
            int k0 = (it + 1) * 64;
#pragma unroll
            for (int i = 0; i < 4; i++) {
                aR[i] = *(const uint4*)(A + (size_t)(bm0 + ar[i]) * KD + k0 + ac[i] * 8);
                if (BHALF) {
                    bR[i] = *(const uint4*)(Bh + (size_t)(k0 + br_[i]) * ND + bn0 + bc[i] * 8);
                } else {
                    bF0[i] = *(const float4*)(Bf + (size_t)(k0 + br_[i]) * ND + bn0 + bc[i] * 8);
                    bF1[i] = *(const float4*)(Bf + (size_t)(k0 + br_[i]) * ND + bn0 + bc[i] * 8 + 4);
                }
            }
        }

        // compute 4 x k16
#pragma unroll
        for (int kk = 0; kk < 4; kk++) {
            uint32_t af[4][4];
#pragma unroll
            for (int mt = 0; mt < 4; mt++) {
                int row = m_off + mt * 16 + (mat & 1) * 8 + rr;
                int ch = kk * 2 + (mat >> 1);
                ldsm_x4(af[mt][0], af[mt][1], af[mt][2], af[mt][3],
                        AS + row * 128 + ((ch ^ (row & 7)) << 4));
            }
#pragma unroll
            for (int np = 0; np < 2; np++) {
                int row = kk * 16 + (mat & 1) * 8 + rr;
                int c = (n_off >> 3) + np * 2 + (mat >> 1);
                uint32_t b0, b1, b2, b3;
                ldsm_x4t(b0, b1, b2, b3,
                         BS + row * 256 + (((c & 8) | ((c & 7) ^ (row & 7))) << 4));
#pragma unroll
                for (int mt = 0; mt < 4; mt++) {
                    mma_f16(acc[mt][np * 2],     af[mt][0], af[mt][1], af[mt][2], af[mt][3], b0, b1);
                    mma_f16(acc[mt][np * 2 + 1], af[mt][0], af[mt][1], af[mt][2], af[mt][3], b2, b3);
                }
            }
        }
    }

    // epilogue
    const float a_out = 0.9191450300f;  // 0.7 / sqrt(0.58)
    const float a_x   = 0.3939192986f;  // 0.3 / sqrt(0.58)
#pragma unroll
    for (int mt = 0; mt < 4; mt++) {
        int r1 = bm0 + m_off + mt * 16 + g;
        int r2 = r1 + 8;
#pragma unroll
        for (int nt = 0; nt < 4; nt++) {
            int col = bn0 + n_off + nt * 8 + 2 * tg;
            float2 v1 = make_float2(acc[mt][nt][0], acc[mt][nt][1]);
            float2 v2 = make_float2(acc[mt][nt][2], acc[mt][nt][3]);
            if (RESID) {
                float2 x1 = *(const float2*)&X[((size_t)b * MD + r1) * ND + col];
                float2 x2 = *(const float2*)&X[((size_t)b * MD + r2) * ND + col];
                v1.x = v1.x * a_out + x1.x * a_x;  v1.y = v1.y * a_out + x1.y * a_x;
                v2.x = v2.x * a_out + x2.x * a_x;  v2.y = v2.y * a_out + x2.y * a_x;
            }
            if (OUTH) {
                __half* Cb = (__half*)Cm + (size_t)b * MD * ND;
                *(__half2*)&Cb[(size_t)r1 * ND + col] = __floats2half2_rn(v1.x, v1.y);
                *(__half2*)&Cb[(size_t)r2 * ND + col] = __floats2half2_rn(v2.x, v2.y);
            } else {
                float* Cb = (float*)Cm + (size_t)b * MD * ND;
                *(float2*)&Cb[(size_t)r1 * ND + col] = v1;
                *(float2*)&Cb[(size_t)r2 * ND + col] = v2;
            }
        }
    }
}

// ---------------------------------------------------------------------------
// fp16 flash attention with ldmatrix (validated round 5); attn out now fp16.
// ---------------------------------------------------------------------------
__global__ void __launch_bounds__(128) attn_f16(const __half* __restrict__ qn,
                                                const __half* __restrict__ kn,
                                                const __half* __restrict__ vn,
                                                const __half* __restrict__ km,
                                                const __half* __restrict__ vm,
                                                __half* __restrict__ attn_out)
{
    __shared__ char smc[32768];
    const uint32_t sb = (uint32_t)__cvta_generic_to_shared(smc);
    const uint32_t QS = sb, PS = sb + 8192, KS = sb + 16384, VS = sb + 24576;

    const int b = blockIdx.z, h = blockIdx.y, i0 = blockIdx.x * 64;
    const int tid = threadIdx.x, lane = tid & 31;
    const int g = lane >> 2, tg = lane & 3;
    const int m0 = (tid >> 5) * 16;

    const __half* qh = qn + ((size_t)(b * HEADS + h) * NPIX + i0) * DIMH;
    const __half* kh = kn + (size_t)(b * HEADS + h) * NPIX * DIMH;
    const __half* vh = vn + (size_t)(b * HEADS + h) * NPIX * DIMH;

    for (int idx = tid; idx < 512; idx += 128) {
        int r = idx >> 3, c = idx & 7;
        uint4 v = *(const uint4*)(qh + r * 64 + c * 8);
        *(uint4*)(smc + r * 128 + ((c ^ (r & 7)) << 4)) = v;
    }
    __syncthreads();

    uint32_t aq[4][4];
    {
        int mat = lane >> 3, rr = lane & 7;
        int qrow = m0 + (mat & 1) * 8 + rr;
#pragma unroll
        for (int kc = 0; kc < 4; kc++) {
            int ch = 2 * kc + (mat >> 1);
            uint32_t addr = QS + qrow * 128 + ((ch ^ (qrow & 7)) << 4);
            ldsm_x4(aq[kc][0], aq[kc][1], aq[kc][2], aq[kc][3], addr);
        }
    }

    float oacc[8][4];
#pragma unroll
    for (int nt = 0; nt < 8; nt++)
#pragma unroll
        for (int r = 0; r < 4; r++) oacc[nt][r] = 0.f;
    float mrow[2] = {-1e30f, -1e30f};
    float lrow[2] = {0.f, 0.f};

    for (int t = 0; t <= 16; ++t) {
        __syncthreads();
        if (t == 0) {
            for (int idx = tid; idx < 512; idx += 128) {
                int r = idx >> 3, c = idx & 7;
                uint4 kv = make_uint4(0, 0, 0, 0), vv = make_uint4(0, 0, 0, 0);
                if (r < 4) {
                    kv = *(const uint4*)(km + (h * 4 + r) * 64 + c * 8);
                    vv = *(const uint4*)(vm + (h * 4 + r) * 64 + c * 8);
                }
                uint32_t off = r * 128 + ((c ^ (r & 7)) << 4);
                *(uint4*)(smc + 16384 + off) = kv;
                *(uint4*)(smc + 24576 + off) = vv;
            }
        } else {
            const __half* kt = kh + (size_t)(t - 1) * 64 * 64;
            const __half* vt = vh + (size_t)(t - 1) * 64 * 64;
            for (int idx = tid; idx < 512; idx += 128) {
                int r = idx >> 3, c = idx & 7;
                uint32_t off = r * 128 + ((c ^ (r & 7)) << 4);
                *(uint4*)(smc + 16384 + off) = *(const uint4*)(kt + r * 64 + c * 8);
                *(uint4*)(smc + 24576 + off) = *(const uint4*)(vt + r * 64 + c * 8);
            }
        }
        __syncthreads();

        float sacc[8][4];
#pragma unroll
        for (int nt = 0; nt < 8; nt++)
#pragma unroll
            for (int r = 0; r < 4; r++) sacc[nt][r] = 0.f;
        {
            int mat = lane >> 3, rr = lane & 7;
#pragma unroll
            for (int np = 0; np < 4; np++) {
                int key = (2 * np + (mat >> 1)) * 8 + rr;
#pragma unroll
                for (int kc = 0; kc < 4; kc++) {
                    int ch = 2 * kc + (mat & 1);
                    uint32_t addr = KS + key * 128 + ((ch ^ (key & 7)) << 4);
                    uint32_t b0, b1, b2, b3;
                    ldsm_x4(b0, b1, b2, b3, addr);
                    mma_f16(sacc[2 * np],     aq[kc][0], aq[kc][1], aq[kc][2], aq[kc][3], b0, b1);
                    mma_f16(sacc[2 * np + 1], aq[kc][0], aq[kc][1], aq[kc][2], aq[kc][3], b2, b3);
                }
            }
        }
        if (t == 0) {
#pragma unroll
            for (int nt = 0; nt < 8; nt++) {
                int c0 = nt * 8 + 2 * tg;
                if (c0 >= 4)     { sacc[nt][0] = -1e30f; sacc[nt][2] = -1e30f; }
                if (c0 + 1 >= 4) { sacc[nt][1] = -1e30f; sacc[nt][3] = -1e30f; }
            }
        }

        float tm0 = -1e30f, tm1 = -1e30f;
#pragma unroll
        for (int nt = 0; nt < 8; nt++) {
            tm0 = fmaxf(tm0, fmaxf(sacc[nt][0], sacc[nt][1]));
            tm1 = fmaxf(tm1, fmaxf(sacc[nt][2], sacc[nt][3]));
        }
        tm0 = fmaxf(tm0, __shfl_xor_sync(0xffffffffu, tm0, 1));
        tm0 = fmaxf(tm0, __shfl_xor_sync(0xffffffffu, tm0, 2));
        tm1 = fmaxf(tm1, __shfl_xor_sync(0xffffffffu, tm1, 1));
        tm1 = fmaxf(tm1, __shfl_xor_sync(0xffffffffu, tm1, 2));

        float mn0 = fmaxf(mrow[0], tm0), mn1 = fmaxf(mrow[1], tm1);
        float al0 = ex2f(mrow[0] - mn0), al1 = ex2f(mrow[1] - mn1);
        float rs0 = 0.f, rs1 = 0.f;
        const int row0 = m0 + g, row1 = m0 + g + 8;
#pragma unroll
        for (int nt = 0; nt < 8; nt++) {
            float p00 = ex2f(sacc[nt][0] - mn0);
            float p01 = ex2f(sacc[nt][1] - mn0);
            float p10 = ex2f(sacc[nt][2] - mn1);
            float p11 = ex2f(sacc[nt][3] - mn1);
            rs0 += p00 + p01;  rs1 += p10 + p11;
            uint32_t a0 = PS + row0 * 128 + ((nt ^ (row0 & 7)) << 4) + (tg << 2);
            uint32_t a1 = PS + row1 * 128 + ((nt ^ (row1 & 7)) << 4) + (tg << 2);
            __half2 h0 = __floats2half2_rn(p00, p01);
            __half2 h1 = __floats2half2_rn(p10, p11);
            asm volatile("st.shared.b32 [%0], %1;" :: "r"(a0), "r"(*(uint32_t*)&h0));
            asm volatile("st.shared.b32 [%0], %1;" :: "r"(a1), "r"(*(uint32_t*)&h1));
        }
        rs0 += __shfl_xor_sync(0xffffffffu, rs0, 1);
        rs0 += __shfl_xor_sync(0xffffffffu, rs0, 2);
        rs1 += __shfl_xor_sync(0xffffffffu, rs1, 1);
        rs1 += __shfl_xor_sync(0xffffffffu, rs1, 2);
        lrow[0] = lrow[0] * al0 + rs0;  mrow[0] = mn0;
        lrow[1] = lrow[1] * al1 + rs1;  mrow[1] = mn1;
#pragma unroll
        for (int nt = 0; nt < 8; nt++) {
            oacc[nt][0] *= al0;  oacc[nt][1] *= al0;
            oacc[nt][2] *= al1;  oacc[nt][3] *= al1;
        }
        __syncwarp();

        {
            int mat = lane >> 3, rr = lane & 7;
#pragma unroll
            for (int kc = 0; kc < 4; kc++) {
                int prow = m0 + (mat & 1) * 8 + rr;
                int pch = 2 * kc + (mat >> 1);
                uint32_t paddr = PS + prow * 128 + ((pch ^ (prow & 7)) << 4);
                uint32_t a0, a1, a2, a3;
                ldsm_x4(a0, a1, a2, a3, paddr);
                int key = kc * 16 + (mat & 1) * 8 + rr;
#pragma unroll
                for (int np = 0; np < 4; np++) {
                    int ch = 2 * np + (mat >> 1);
                    uint32_t vaddr = VS + key * 128 + ((ch ^ (key & 7)) << 4);
                    uint32_t b0, b1, b2, b3;
                    ldsm_x4t(b0, b1, b2, b3, vaddr);
                    mma_f16(oacc[2 * np],     a0, a1, a2, a3, b0, b1);
                    mma_f16(oacc[2 * np + 1], a0, a1, a2, a3, b2, b3);
                }
            }
        }
    }

    __syncthreads();
    float* fs = (float*)(smc + 8192);
    {
        float il0 = 1.f / lrow[0], il1 = 1.f / lrow[1];
        const int row0 = m0 + g, row1 = m0 + g + 8;
#pragma unroll
        for (int nt = 0; nt < 8; nt++) {
            int c = nt * 8 + 2 * tg;
            fs[row0 * 66 + c]     = oacc[nt][0] * il0;
            fs[row0 * 66 + c + 1] = oacc[nt][1] * il0;
            fs[row1 * 66 + c]     = oacc[nt][2] * il1;
            fs[row1 * 66 + c + 1] = oacc[nt][3] * il1;
        }
    }
    __syncthreads();
    {
        __half* ob = attn_out + ((size_t)b * HID + h * DIMH) * NPIX;
        for (int idx = tid; idx < 64 * 64; idx += 128) {
            int m = idx & 63, d = idx >> 6;
            ob[(size_t)d * NPIX + i0 + m] = __float2half(fs[m * 66 + d]);
        }
    }
}

// ---------------------------------------------------------------------------
extern "C" void kernel_launch(void* const* d_in, const int* in_sizes, int n_in,
                              void* d_out, int out_size)
{
    const float* x      = (const float*)d_in[0];  // [16,512,32,32]
    const float* w_qkv  = (const float*)d_in[1];  // [1536,512]
    const float* w_out  = (const float*)d_in[2];  // [512,512]
    const float* mem_kv = (const float*)d_in[3];  // [2,8,4,64]
    float* out = (float*)d_out;                   // [16,512,32,32]

    __half *wnq, *wno, *qkv, *attn, *qn, *kn, *vn, *km, *vm;
    cudaGetSymbolAddress((void**)&wnq,  g_wn_qkv);
    cudaGetSymbolAddress((void**)&wno,  g_wn_out);
    cudaGetSymbolAddress((void**)&qkv,  g_qkv);
    cudaGetSymbolAddress((void**)&attn, g_attn);
    cudaGetSymbolAddress((void**)&qn,   g_qn);
    cudaGetSymbolAddress((void**)&kn,   g_kn);
    cudaGetSymbolAddress((void**)&vn,   g_vn);
    cudaGetSymbolAddress((void**)&km,   g_km);
    cudaGetSymbolAddress((void**)&vm,   g_vm);

    // merged weight norms (fp16 out)
    wnorm2_kernel<<<K3 + CIN, 256>>>(w_qkv, w_out, wnq, wno);

    // QKV projection (B = x fp32, C = fp16 qkv)
    hgemm_tc<K3, false, false, true><<<dim3(8, K3 / 128, NB), 256>>>(wnq, x, qkv, nullptr);

    // Normalize q/k/v (+ mem_kv) into fp16 [b,h,n,d]
    norm_memkv<<<1, 64>>>(mem_kv, km, vm);
    norm_qkv<<<dim3(NPIX / 128, HEADS, NB), 256>>>(qkv, qn, kn, vn);

    // Attention (fp16 out)
    attn_f16<<<dim3(NPIX / 64, HEADS, NB), 128>>>(qn, kn, vn, km, vm, attn);

    // Output projection + MPAdd residual (B = attn fp16, C = fp32 out)
    hgemm_tc<CIN, true, true, false><<<dim3(8, CIN / 128, NB), 256>>>(wno, attn, out, x);
}

// round 7
// speedup vs baseline: 5.2891x; 1.1011x over previous
#include <cuda_runtime.h>
#include <cuda_fp16.h>
#include <math.h>
#include <stdint.h>

#define NB    16
#define CIN   512
#define NPIX  1024
#define HEADS 8
#define DIMH  64
#define HID   512
#define K3    1536   // 3*HID

// Scratch (allocation-free, device globals)
__device__ __half g_wn_qkv[K3 * CIN];                     // fp16 normalized w_qkv
__device__ __half g_wn_out[CIN * HID];                    // fp16 normalized w_out
__device__ __half g_attn[(size_t)NB * HID * NPIX];        // fp16 attn out (channel-major)
__device__ __half g_qn[(size_t)NB * HEADS * NPIX * DIMH]; // normalized q [b,h,n,d]
__device__ __half g_kn[(size_t)NB * HEADS * NPIX * DIMH];
__device__ __half g_vn[(size_t)NB * HEADS * NPIX * DIMH];
__device__ __half g_km[HEADS * 4 * DIMH];
__device__ __half g_vm[HEADS * 4 * DIMH];

// ---------------------------------------------------------------------------
// helpers
// ---------------------------------------------------------------------------
__device__ __forceinline__ float ex2f(float x) {
    float y;
    asm("ex2.approx.f32 %0, %1;" : "=f"(y) : "f"(x));
    return y;
}
__device__ __forceinline__ void mma_f16(float (&d)[4],
                                        uint32_t a0, uint32_t a1, uint32_t a2, uint32_t a3,
                                        uint32_t b0, uint32_t b1) {
    asm volatile(
        "mma.sync.aligned.m16n8k16.row.col.f32.f16.f16.f32 "
        "{%0,%1,%2,%3}, {%4,%5,%6,%7}, {%8,%9}, {%0,%1,%2,%3};"
        : "+f"(d[0]), "+f"(d[1]), "+f"(d[2]), "+f"(d[3])
        : "r"(a0), "r"(a1), "r"(a2), "r"(a3), "r"(b0), "r"(b1));
}
__device__ __forceinline__ void ldsm_x4(uint32_t& r0, uint32_t& r1, uint32_t& r2,
                                        uint32_t& r3, uint32_t addr) {
    asm volatile("ldmatrix.sync.aligned.m8n8.x4.shared.b16 {%0,%1,%2,%3}, [%4];"
                 : "=r"(r0), "=r"(r1), "=r"(r2), "=r"(r3) : "r"(addr));
}
__device__ __forceinline__ void ldsm_x4t(uint32_t& r0, uint32_t& r1, uint32_t& r2,
                                         uint32_t& r3, uint32_t addr) {
    asm volatile("ldmatrix.sync.aligned.m8n8.x4.trans.shared.b16 {%0,%1,%2,%3}, [%4];"
                 : "=r"(r0), "=r"(r1), "=r"(r2), "=r"(r3) : "r"(addr));
}

// ---------------------------------------------------------------------------
// Weight norm (both weights fan-in 512) + mem_kv norm, one launch.
// Blocks [0,K3) -> w_qkv rows; [K3,K3+CIN) -> w_out rows;
// [K3+CIN, K3+CIN+64) -> mem_kv rows (part=row>>5, head*4+key = row&31).
// ---------------------------------------------------------------------------
__global__ void __launch_bounds__(256) prep_kernel(const float* __restrict__ w_qkv,
                                                   const float* __restrict__ w_out,
                                                   const float* __restrict__ mem_kv,
                                                   __half* __restrict__ wnq,
                                                   __half* __restrict__ wno,
                                                   __half* __restrict__ km,
                                                   __half* __restrict__ vm)
{
    int r = blockIdx.x;
    if (r >= K3 + CIN) {
        // mem_kv row: 64 elems, warp 0 only
        if (threadIdx.x < 32) {
            int row = r - (K3 + CIN);
            int part = row >> 5, rk = row & 31;
            const float* src = mem_kv + part * 2048 + rk * 64;
            float v0 = src[threadIdx.x], v1 = src[threadIdx.x + 32];
            float s = v0 * v0 + v1 * v1;
#pragma unroll
            for (int off = 16; off; off >>= 1) s += __shfl_xor_sync(0xffffffffu, s, off);
            float sc = 8.f / fmaxf(sqrtf(s), 1e-4f);
            __half* dst = (part ? vm : km) + rk * 64;
            dst[threadIdx.x]      = __float2half(v0 * sc);
            dst[threadIdx.x + 32] = __float2half(v1 * sc);
        }
        return;
    }
    const float* wr;
    __half* out;
    if (r < K3) { wr = w_qkv + (size_t)r * CIN;        out = wnq + (size_t)r * CIN; }
    else        { wr = w_out + (size_t)(r - K3) * HID; out = wno + (size_t)(r - K3) * HID; }
    float s = 0.f;
    for (int i = threadIdx.x; i < 512; i += 256) { float v = wr[i]; s += v * v; }
    __shared__ float red[8];
#pragma unroll
    for (int off = 16; off; off >>= 1) s += __shfl_xor_sync(0xffffffffu, s, off);
    if ((threadIdx.x & 31) == 0) red[threadIdx.x >> 5] = s;
    __syncthreads();
    if (threadIdx.x == 0) {
        float v = 0.f;
#pragma unroll
        for (int i = 0; i < 8; i++) v += red[i];
        red[0] = v;
    }
    __syncthreads();
    float inv = 1.f / (1e-4f * 22.627416998f + sqrtf(red[0]));  // eps*sqrt(512)
    for (int i = threadIdx.x; i < 512; i += 256)
        out[i] = __float2half(wr[i] * inv);
}

// ---------------------------------------------------------------------------
// QKV GEMM with FUSED pixel-norm epilogue.
// C[b](1536x1024) = Wn(1536x512,fp16) * X[b](512x1024,fp32), then per output
// column (pixel) and per 64-row head-slab: ||.|| over d in fp32 accumulators,
// scale (log2e for q, 8 for k/v), write fp16 [b,h,pix,d] to qn/kn/vn.
// Warp tile is 64 rows = exactly one head slab.
// ---------------------------------------------------------------------------
__global__ void __launch_bounds__(256) hgemm_qkv(const __half* __restrict__ A,
                                                 const float* __restrict__ Bf0,
                                                 __half* __restrict__ qn,
                                                 __half* __restrict__ kn,
                                                 __half* __restrict__ vn)
{
    constexpr int ND = 1024, KD = 512;
    __shared__ char smc[32768];
    const uint32_t sb = (uint32_t)__cvta_generic_to_shared(smc);
    const uint32_t AS = sb, BS = sb + 16384;

    const int b   = blockIdx.z;
    const int bm0 = blockIdx.y * 128;
    const int bn0 = blockIdx.x * 128;
    const float* Bf = Bf0 + (size_t)b * KD * ND;

    const int tid = threadIdx.x;
    const int w = tid >> 5, lane = tid & 31;
    const int g = lane >> 2, tg = lane & 3;
    const int mat = lane >> 3, rr = lane & 7;
    const int m_off = (w >> 2) * 64;
    const int n_off = (w & 3) * 32;

    float acc[4][4][4];
#pragma unroll
    for (int i = 0; i < 4; i++)
#pragma unroll
        for (int j = 0; j < 4; j++)
#pragma unroll
            for (int r = 0; r < 4; r++) acc[i][j][r] = 0.f;

    int ar[4], ac[4], br_[4], bc[4];
#pragma unroll
    for (int i = 0; i < 4; i++) {
        int cid = i * 256 + tid;
        ar[i] = cid >> 3;  ac[i] = cid & 7;
        br_[i] = cid >> 4; bc[i] = cid & 15;
    }

    uint4 aR[4];
    float4 bF0[4], bF1[4];
#pragma unroll
    for (int i = 0; i < 4; i++) {
        aR[i]  = *(const uint4*)(A + (size_t)(bm0 + ar[i]) * KD + ac[i] * 8);
        bF0[i] = *(const float4*)(Bf + (size_t)br_[i] * ND + bn0 + bc[i] * 8);
        bF1[i] = *(const float4*)(Bf + (size_t)br_[i] * ND + bn0 + bc[i] * 8 + 4);
    }

    for (int it = 0; it < 8; ++it) {
        __syncthreads();
#pragma unroll
        for (int i = 0; i < 4; i++) {
            *(uint4*)(smc + ar[i] * 128 + ((ac[i] ^ (ar[i] & 7)) << 4)) = aR[i];
            uint32_t boff = 16384 + br_[i] * 256 +
                            (((bc[i] & 8) | ((bc[i] & 7) ^ (br_[i] & 7))) << 4);
            __half2 h0 = __floats2half2_rn(bF0[i].x, bF0[i].y);
            __half2 h1 = __floats2half2_rn(bF0[i].z, bF0[i].w);
            __half2 h2 = __floats2half2_rn(bF1[i].x, bF1[i].y);
            __half2 h3 = __floats2half2_rn(bF1[i].z, bF1[i].w);
            uint4 pk;
            pk.x = *(uint32_t*)&h0; pk.y = *(uint32_t*)&h1;
            pk.z = *(uint32_t*)&h2; pk.w = *(uint32_t*)&h3;
            *(uint4*)(smc + boff) = pk;
        }
        __syncthreads();

        if (it < 7) {
            int k0 = (it + 1) * 64;
#pragma unroll
            for (int i = 0; i < 4; i++) {
                aR[i]  = *(const uint4*)(A + (size_t)(bm0 + ar[i]) * KD + k0 + ac[i] * 8);
                bF0[i] = *(const float4*)(Bf + (size_t)(k0 + br_[i]) * ND + bn0 + bc[i] * 8);
                bF1[i] = *(const float4*)(Bf + (size_t)(k0 + br_[i]) * ND + bn0 + bc[i] * 8 + 4);
            }
        }

#pragma unroll
        for (int kk = 0; kk < 4; kk++) {
            uint32_t af[4][4];
#pragma unroll
            for (int mt = 0; mt < 4; mt++) {
                int row = m_off + mt * 16 + (mat & 1) * 8 + rr;
                int ch = kk * 2 + (mat >> 1);
                ldsm_x4(af[mt][0], af[mt][1], af[mt][2], af[mt][3],
                        AS + row * 128 + ((ch ^ (row & 7)) << 4));
            }
#pragma unroll
            for (int np = 0; np < 2; np++) {
                int row = kk * 16 + (mat & 1) * 8 + rr;
                int c = (n_off >> 3) + np * 2 + (mat >> 1);
                uint32_t b0, b1, b2, b3;
                ldsm_x4t(b0, b1, b2, b3,
                         BS + row * 256 + (((c & 8) | ((c & 7) ^ (row & 7))) << 4));
#pragma unroll
                for (int mt = 0; mt < 4; mt++) {
                    mma_f16(acc[mt][np * 2],     af[mt][0], af[mt][1], af[mt][2], af[mt][3], b0, b1);
                    mma_f16(acc[mt][np * 2 + 1], af[mt][0], af[mt][1], af[mt][2], af[mt][3], b2, b3);
                }
            }
        }
    }

    // ---- fused pixel-norm epilogue ----
    // warp covers global rows [bm0+m_off, +64) = one head slab of one component
    __syncthreads();   // all warps done reading As/Bs before staging reuse
    const int gr0  = bm0 + m_off;
    const int comp = gr0 >> 9;             // 0=q, 1=k, 2=v
    const int head = (gr0 & 511) >> 6;
    const float sc_num = (comp == 0) ? 1.4426950408889634f : 8.f;
    __half* st = (__half*)(smc + w * 4096); // warp-private [col 0..31][d 0..63]

#pragma unroll
    for (int nt = 0; nt < 4; nt++) {
        float ss0 = 0.f, ss1 = 0.f;
#pragma unroll
        for (int mt = 0; mt < 4; mt++) {
            ss0 += acc[mt][nt][0] * acc[mt][nt][0] + acc[mt][nt][2] * acc[mt][nt][2];
            ss1 += acc[mt][nt][1] * acc[mt][nt][1] + acc[mt][nt][3] * acc[mt][nt][3];
        }
#pragma unroll
        for (int off = 4; off <= 16; off <<= 1) {   // sum across the 8 g-lanes
            ss0 += __shfl_xor_sync(0xffffffffu, ss0, off);
            ss1 += __shfl_xor_sync(0xffffffffu, ss1, off);
        }
        float s0 = sc_num / fmaxf(sqrtf(ss0), 1e-4f);
        float s1 = sc_num / fmaxf(sqrtf(ss1), 1e-4f);
        int c0 = nt * 8 + 2 * tg;
#pragma unroll
        for (int mt = 0; mt < 4; mt++) {
            int r = mt * 16 + g;
            st[c0 * 64 + r]           = __float2half(acc[mt][nt][0] * s0);
            st[c0 * 64 + r + 8]       = __float2half(acc[mt][nt][2] * s0);
            st[(c0 + 1) * 64 + r]     = __float2half(acc[mt][nt][1] * s1);
            st[(c0 + 1) * 64 + r + 8] = __float2half(acc[mt][nt][3] * s1);
        }
    }
    __syncwarp();
    __half* dst = (comp == 0 ? qn : comp == 1 ? kn : vn) +
                  ((size_t)(b * HEADS + head) * NPIX + bn0 + n_off) * DIMH;
#pragma unroll 8
    for (int c = 0; c < 32; c++) {
        __half2 v = *(__half2*)(st + c * 64 + lane * 2);
        *(__half2*)(dst + (size_t)c * DIMH + lane * 2) = v;
    }
}

// ---------------------------------------------------------------------------
// fp16 GEMM for output projection: out = (Wo*attn)*0.7/sqrt(.58) + x*0.3/sqrt(.58)
// A fp16 [512][512], B fp16 [b][512][1024], C fp32.
// ---------------------------------------------------------------------------
__global__ void __launch_bounds__(256) hgemm_out(const __half* __restrict__ A,
                                                 const __half* __restrict__ Bm,
                                                 float* __restrict__ Cm,
                                                 const float* __restrict__ X)
{
    constexpr int ND = 1024, KD = 512, MD = CIN;
    __shared__ char smc[32768];
    const uint32_t sb = (uint32_t)__cvta_generic_to_shared(smc);
    const uint32_t AS = sb, BS = sb + 16384;

    const int b   = blockIdx.z;
    const int bm0 = blockIdx.y * 128;
    const int bn0 = blockIdx.x * 128;
    const __half* Bh = Bm + (size_t)b * KD * ND;
    float* Cb = Cm + (size_t)b * MD * ND;

    const int tid = threadIdx.x;
    const int w = tid >> 5, lane = tid & 31;
    const int g = lane >> 2, tg = lane & 3;
    const int mat = lane >> 3, rr = lane & 7;
    const int m_off = (w >> 2) * 64;
    const int n_off = (w & 3) * 32;

    float acc[4][4][4];
#pragma unroll
    for (int i = 0; i < 4; i++)
#pragma unroll
        for (int j = 0; j < 4; j++)
#pragma unroll
            for (int r = 0; r < 4; r++) acc[i][j][r] = 0.f;

    int ar[4], ac[4], br_[4], bc[4];
#pragma unroll
    for (int i = 0; i < 4; i++) {
        int cid = i * 256 + tid;
        ar[i] = cid >> 3;  ac[i] = cid & 7;
        br_[i] = cid >> 4; bc[i] = cid & 15;
    }

    uint4 aR[4], bR[4];
#pragma unroll
    for (int i = 0; i < 4; i++) {
        aR[i] = *(const uint4*)(A + (size_t)(bm0 + ar[i]) * KD + ac[i] * 8);
        bR[i] = *(const uint4*)(Bh + (size_t)br_[i] * ND + bn0 + bc[i] * 8);
    }

    for (int it = 0; it < 8; ++it) {
        __syncthreads();
#pragma unroll
        for (int i = 0; i < 4; i++) {
            *(uint4*)(smc + ar[i] * 128 + ((ac[i] ^ (ar[i] & 7)) << 4)) = aR[i];
            uint32_t boff = 16384 + br_[i] * 256 +
                            (((bc[i] & 8) | ((bc[i] & 7) ^ (br_[i] & 7))) << 4);
            *(uint4*)(smc + boff) = bR[i];
        }
        __syncthreads();

        if (it < 7) {
            int k0 = (it + 1) * 64;
#pragma unroll
            for (int i = 0; i < 4; i++) {
                aR[i] = *(const uint4*)(A + (size_t)(bm0 + ar[i]) * KD + k0 + ac[i] * 8);
                bR[i] = *(const uint4*)(Bh + (size_t)(k0 + br_[i]) * ND + bn0 + bc[i] * 8);
            }
        }

#pragma unroll
        for (int kk = 0; kk < 4; kk++) {
            uint32_t af[4][4];
#pragma unroll
            for (int mt = 0; mt < 4; mt++) {
                int row = m_off + mt * 16 + (mat & 1) * 8 + rr;
                int ch = kk * 2 + (mat >> 1);
                ldsm_x4(af[mt][0], af[mt][1], af[mt][2], af[mt][3],
                        AS + row * 128 + ((ch ^ (row & 7)) << 4));
            }
#pragma unroll
            for (int np = 0; np < 2; np++) {
                int row = kk * 16 + (mat & 1) * 8 + rr;
                int c = (n_off >> 3) + np * 2 + (mat >> 1);
                uint32_t b0, b1, b2, b3;
                ldsm_x4t(b0, b1, b2, b3,
                         BS + row * 256 + (((c & 8) | ((c & 7) ^ (row & 7))) << 4));
#pragma unroll
                for (int mt = 0; mt < 4; mt++) {
                    mma_f16(acc[mt][np * 2],     af[mt][0], af[mt][1], af[mt][2], af[mt][3], b0, b1);
                    mma_f16(acc[mt][np * 2 + 1], af[mt][0], af[mt][1], af[mt][2], af[mt][3], b2, b3);
                }
            }
        }
    }

    const float a_out = 0.9191450300f;  // 0.7 / sqrt(0.58)
    const float a_x   = 0.3939192986f;  // 0.3 / sqrt(0.58)
#pragma unroll
    for (int mt = 0; mt < 4; mt++) {
        int r1 = bm0 + m_off + mt * 16 + g;
        int r2 = r1 + 8;
#pragma unroll
        for (int nt = 0; nt < 4; nt++) {
            int col = bn0 + n_off + nt * 8 + 2 * tg;
            float2 v1 = make_float2(acc[mt][nt][0], acc[mt][nt][1]);
            float2 v2 = make_float2(acc[mt][nt][2], acc[mt][nt][3]);
            float2 x1 = *(const float2*)&X[((size_t)b * MD + r1) * ND + col];
            float2 x2 = *(const float2*)&X[((size_t)b * MD + r2) * ND + col];
            v1.x = v1.x * a_out + x1.x * a_x;  v1.y = v1.y * a_out + x1.y * a_x;
            v2.x = v2.x * a_out + x2.x * a_x;  v2.y = v2.y * a_out + x2.y * a_x;
            *(float2*)&Cb[(size_t)r1 * ND + col] = v1;
            *(float2*)&Cb[(size_t)r2 * ND + col] = v2;
        }
    }
}

// ---------------------------------------------------------------------------
// fp16 flash attention with ldmatrix (validated rounds 5-6).
// ---------------------------------------------------------------------------
__global__ void __launch_bounds__(128) attn_f16(const __half* __restrict__ qn,
                                                const __half* __restrict__ kn,
                                                const __half* __restrict__ vn,
                                                const __half* __restrict__ km,
                                                const __half* __restrict__ vm,
                                                __half* __restrict__ attn_out)
{
    __shared__ char smc[32768];
    const uint32_t sb = (uint32_t)__cvta_generic_to_shared(smc);
    const uint32_t QS = sb, PS = sb + 8192, KS = sb + 16384, VS = sb + 24576;

    const int b = blockIdx.z, h = blockIdx.y, i0 = blockIdx.x * 64;
    const int tid = threadIdx.x, lane = tid & 31;
    const int g = lane >> 2, tg = lane & 3;
    const int m0 = (tid >> 5) * 16;

    const __half* qh = qn + ((size_t)(b * HEADS + h) * NPIX + i0) * DIMH;
    const __half* kh = kn + (size_t)(b * HEADS + h) * NPIX * DIMH;
    const __half* vh = vn + (size_t)(b * HEADS + h) * NPIX * DIMH;

    for (int idx = tid; idx < 512; idx += 128) {
        int r = idx >> 3, c = idx & 7;
        uint4 v = *(const uint4*)(qh + r * 64 + c * 8);
        *(uint4*)(smc + r * 128 + ((c ^ (r & 7)) << 4)) = v;
    }
    __syncthreads();

    uint32_t aq[4][4];
    {
        int mat = lane >> 3, rr = lane & 7;
        int qrow = m0 + (mat & 1) * 8 + rr;
#pragma unroll
        for (int kc = 0; kc < 4; kc++) {
            int ch = 2 * kc + (mat >> 1);
            uint32_t addr = QS + qrow * 128 + ((ch ^ (qrow & 7)) << 4);
            ldsm_x4(aq[kc][0], aq[kc][1], aq[kc][2], aq[kc][3], addr);
        }
    }

    float oacc[8][4];
#pragma unroll
    for (int nt = 0; nt < 8; nt++)
#pragma unroll
        for (int r = 0; r < 4; r++) oacc[nt][r] = 0.f;
    float mrow[2] = {-1e30f, -1e30f};
    float lrow[2] = {0.f, 0.f};

    for (int t = 0; t <= 16; ++t) {
        __syncthreads();
        if (t == 0) {
            for (int idx = tid; idx < 512; idx += 128) {
                int r = idx >> 3, c = idx & 7;
                uint4 kv = make_uint4(0, 0, 0, 0), vv = make_uint4(0, 0, 0, 0);
                if (r < 4) {
                    kv = *(const uint4*)(km + (h * 4 + r) * 64 + c * 8);
                    vv = *(const uint4*)(vm + (h * 4 + r) * 64 + c * 8);
                }
                uint32_t off = r * 128 + ((c ^ (r & 7)) << 4);
                *(uint4*)(smc + 16384 + off) = kv;
                *(uint4*)(smc + 24576 + off) = vv;
            }
        } else {
            const __half* kt = kh + (size_t)(t - 1) * 64 * 64;
            const __half* vt = vh + (size_t)(t - 1) * 64 * 64;
            for (int idx = tid; idx < 512; idx += 128) {
                int r = idx >> 3, c = idx & 7;
                uint32_t off = r * 128 + ((c ^ (r & 7)) << 4);
                *(uint4*)(smc + 16384 + off) = *(const uint4*)(kt + r * 64 + c * 8);
                *(uint4*)(smc + 24576 + off) = *(const uint4*)(vt + r * 64 + c * 8);
            }
        }
        __syncthreads();

        float sacc[8][4];
#pragma unroll
        for (int nt = 0; nt < 8; nt++)
#pragma unroll
            for (int r = 0; r < 4; r++) sacc[nt][r] = 0.f;
        {
            int mat = lane >> 3, rr = lane & 7;
#pragma unroll
            for (int np = 0; np < 4; np++) {
                int key = (2 * np + (mat >> 1)) * 8 + rr;
#pragma unroll
                for (int kc = 0; kc < 4; kc++) {
                    int ch = 2 * kc + (mat & 1);
                    uint32_t addr = KS + key * 128 + ((ch ^ (key & 7)) << 4);
                    uint32_t b0, b1, b2, b3;
                    ldsm_x4(b0, b1, b2, b3, addr);
                    mma_f16(sacc[2 * np],     aq[kc][0], aq[kc][1], aq[kc][2], aq[kc][3], b0, b1);
                    mma_f16(sacc[2 * np + 1], aq[kc][0], aq[kc][1], aq[kc][2], aq[kc][3], b2, b3);
                }
            }
        }
        if (t == 0) {
#pragma unroll
            for (int nt = 0; nt < 8; nt++) {
                int c0 = nt * 8 + 2 * tg;
                if (c0 >= 4)     { sacc[nt][0] = -1e30f; sacc[nt][2] = -1e30f; }
                if (c0 + 1 >= 4) { sacc[nt][1] = -1e30f; sacc[nt][3] = -1e30f; }
            }
        }

        float tm0 = -1e30f, tm1 = -1e30f;
#pragma unroll
        for (int nt = 0; nt < 8; nt++) {
            tm0 = fmaxf(tm0, fmaxf(sacc[nt][0], sacc[nt][1]));
            tm1 = fmaxf(tm1, fmaxf(sacc[nt][2], sacc[nt][3]));
        }
        tm0 = fmaxf(tm0, __shfl_xor_sync(0xffffffffu, tm0, 1));
        tm0 = fmaxf(tm0, __shfl_xor_sync(0xffffffffu, tm0, 2));
        tm1 = fmaxf(tm1, __shfl_xor_sync(0xffffffffu, tm1, 1));
        tm1 = fmaxf(tm1, __shfl_xor_sync(0xffffffffu, tm1, 2));

        float mn0 = fmaxf(mrow[0], tm0), mn1 = fmaxf(mrow[1], tm1);
        float al0 = ex2f(mrow[0] - mn0), al1 = ex2f(mrow[1] - mn1);
        float rs0 = 0.f, rs1 = 0.f;
        const int row0 = m0 + g, row1 = m0 + g + 8;
#pragma unroll
        for (int nt = 0; nt < 8; nt++) {
            float p00 = ex2f(sacc[nt][0] - mn0);
            float p01 = ex2f(sacc[nt][1] - mn0);
            float p10 = ex2f(sacc[nt][2] - mn1);
            float p11 = ex2f(sacc[nt][3] - mn1);
            rs0 += p00 + p01;  rs1 += p10 + p11;
            uint32_t a0 = PS + row0 * 128 + ((nt ^ (row0 & 7)) << 4) + (tg << 2);
            uint32_t a1 = PS + row1 * 128 + ((nt ^ (row1 & 7)) << 4) + (tg << 2);
            __half2 h0 = __floats2half2_rn(p00, p01);
            __half2 h1 = __floats2half2_rn(p10, p11);
            asm volatile("st.shared.b32 [%0], %1;" :: "r"(a0), "r"(*(uint32_t*)&h0));
            asm volatile("st.shared.b32 [%0], %1;" :: "r"(a1), "r"(*(uint32_t*)&h1));
        }
        rs0 += __shfl_xor_sync(0xffffffffu, rs0, 1);
        rs0 += __shfl_xor_sync(0xffffffffu, rs0, 2);
        rs1 += __shfl_xor_sync(0xffffffffu, rs1, 1);
        rs1 += __shfl_xor_sync(0xffffffffu, rs1, 2);
        lrow[0] = lrow[0] * al0 + rs0;  mrow[0] = mn0;
        lrow[1] = lrow[1] * al1 + rs1;  mrow[1] = mn1;
#pragma unroll
        for (int nt = 0; nt < 8; nt++) {
            oacc[nt][0] *= al0;  oacc[nt][1] *= al0;
            oacc[nt][2] *= al1;  oacc[nt][3] *= al1;
        }
        __syncwarp();

        {
            int mat = lane >> 3, rr = lane & 7;
#pragma unroll
            for (int kc = 0; kc < 4; kc++) {
                int prow = m0 + (mat & 1) * 8 + rr;
                int pch = 2 * kc + (mat >> 1);
                uint32_t paddr = PS + prow * 128 + ((pch ^ (prow & 7)) << 4);
                uint32_t a0, a1, a2, a3;
                ldsm_x4(a0, a1, a2, a3, paddr);
                int key = kc * 16 + (mat & 1) * 8 + rr;
#pragma unroll
                for (int np = 0; np < 4; np++) {
                    int ch = 2 * np + (mat >> 1);
                    uint32_t vaddr = VS + key * 128 + ((ch ^ (key & 7)) << 4);
                    uint32_t b0, b1, b2, b3;
                    ldsm_x4t(b0, b1, b2, b3, vaddr);
                    mma_f16(oacc[2 * np],     a0, a1, a2, a3, b0, b1);
                    mma_f16(oacc[2 * np + 1], a0, a1, a2, a3, b2, b3);
                }
            }
        }
    }

    __syncthreads();
    float* fs = (float*)(smc + 8192);
    {
        float il0 = 1.f / lrow[0], il1 = 1.f / lrow[1];
        const int row0 = m0 + g, row1 = m0 + g + 8;
#pragma unroll
        for (int nt = 0; nt < 8; nt++) {
            int c = nt * 8 + 2 * tg;
            fs[row0 * 66 + c]     = oacc[nt][0] * il0;
            fs[row0 * 66 + c + 1] = oacc[nt][1] * il0;
            fs[row1 * 66 + c]     = oacc[nt][2] * il1;
            fs[row1 * 66 + c + 1] = oacc[nt][3] * il1;
        }
    }
    __syncthreads();
    {
        __half* ob = attn_out + ((size_t)b * HID + h * DIMH) * NPIX;
        for (int idx = tid; idx < 64 * 64; idx += 128) {
            int m = idx & 63, d = idx >> 6;
            ob[(size_t)d * NPIX + i0 + m] = __float2half(fs[m * 66 + d]);
        }
    }
}

// ---------------------------------------------------------------------------
extern "C" void kernel_launch(void* const* d_in, const int* in_sizes, int n_in,
                              void* d_out, int out_size)
{
    const float* x      = (const float*)d_in[0];  // [16,512,32,32]
    const float* w_qkv  = (const float*)d_in[1];  // [1536,512]
    const float* w_out  = (const float*)d_in[2];  // [512,512]
    const float* mem_kv = (const float*)d_in[3];  // [2,8,4,64]
    float* out = (float*)d_out;                   // [16,512,32,32]

    __half *wnq, *wno, *attn, *qn, *kn, *vn, *km, *vm;
    cudaGetSymbolAddress((void**)&wnq,  g_wn_qkv);
    cudaGetSymbolAddress((void**)&wno,  g_wn_out);
    cudaGetSymbolAddress((void**)&attn, g_attn);
    cudaGetSymbolAddress((void**)&qn,   g_qn);
    cudaGetSymbolAddress((void**)&kn,   g_kn);
    cudaGetSymbolAddress((void**)&vn,   g_vn);
    cudaGetSymbolAddress((void**)&km,   g_km);
    cudaGetSymbolAddress((void**)&vm,   g_vm);

    // weight norms + mem_kv norm, one launch
    prep_kernel<<<K3 + CIN + 64, 256>>>(w_qkv, w_out, mem_kv, wnq, wno, km, vm);

    // QKV projection with fused pixel-norm -> qn/kn/vn fp16 [b,h,n,d]
    hgemm_qkv<<<dim3(8, K3 / 128, NB), 256>>>(wnq, x, qn, kn, vn);

    // Attention (fp16 out)
    attn_f16<<<dim3(NPIX / 64, HEADS, NB), 128>>>(qn, kn, vn, km, vm, attn);

    // Output projection + MPAdd residual
    hgemm_out<<<dim3(8, CIN / 128, NB), 256>>>(wno, attn, out, x);
}

// round 8
// speedup vs baseline: 6.2528x; 1.1822x over previous
#include <cuda_runtime.h>
#include <cuda_fp16.h>
#include <math.h>
#include <stdint.h>

#define NB    16
#define CIN   512
#define NPIX  1024
#define HEADS 8
#define DIMH  64
#define HID   512
#define K3    1536   // 3*HID

// Scratch (allocation-free, device globals)
__device__ __half g_wn_qkv[K3 * CIN];
__device__ __half g_wn_out[CIN * HID];
__device__ __half g_attn[(size_t)NB * HID * NPIX];
__device__ __half g_qn[(size_t)NB * HEADS * NPIX * DIMH];
__device__ __half g_kn[(size_t)NB * HEADS * NPIX * DIMH];
__device__ __half g_vn[(size_t)NB * HEADS * NPIX * DIMH];
__device__ __half g_km[HEADS * 4 * DIMH];
__device__ __half g_vm[HEADS * 4 * DIMH];

// ---------------------------------------------------------------------------
// helpers
// ---------------------------------------------------------------------------
__device__ __forceinline__ float ex2f(float x) {
    float y;
    asm("ex2.approx.f32 %0, %1;" : "=f"(y) : "f"(x));
    return y;
}
__device__ __forceinline__ void mma_f16(float (&d)[4],
                                        uint32_t a0, uint32_t a1, uint32_t a2, uint32_t a3,
                                        uint32_t b0, uint32_t b1) {
    asm volatile(
        "mma.sync.aligned.m16n8k16.row.col.f32.f16.f16.f32 "
        "{%0,%1,%2,%3}, {%4,%5,%6,%7}, {%8,%9}, {%0,%1,%2,%3};"
        : "+f"(d[0]), "+f"(d[1]), "+f"(d[2]), "+f"(d[3])
        : "r"(a0), "r"(a1), "r"(a2), "r"(a3), "r"(b0), "r"(b1));
}
__device__ __forceinline__ void ldsm_x4(uint32_t& r0, uint32_t& r1, uint32_t& r2,
                                        uint32_t& r3, uint32_t addr) {
    asm volatile("ldmatrix.sync.aligned.m8n8.x4.shared.b16 {%0,%1,%2,%3}, [%4];"
                 : "=r"(r0), "=r"(r1), "=r"(r2), "=r"(r3) : "r"(addr));
}
__device__ __forceinline__ void ldsm_x4t(uint32_t& r0, uint32_t& r1, uint32_t& r2,
                                         uint32_t& r3, uint32_t addr) {
    asm volatile("ldmatrix.sync.aligned.m8n8.x4.trans.shared.b16 {%0,%1,%2,%3}, [%4];"
                 : "=r"(r0), "=r"(r1), "=r"(r2), "=r"(r3) : "r"(addr));
}
__device__ __forceinline__ void cp16(uint32_t s, const void* g) {
    asm volatile("cp.async.cg.shared.global [%0], [%1], 16;" :: "r"(s), "l"(g));
}
__device__ __forceinline__ void cp16z(uint32_t s, const void* g, int sz) {
    asm volatile("cp.async.cg.shared.global [%0], [%1], 16, %2;"
                 :: "r"(s), "l"(g), "r"(sz));
}

// ---------------------------------------------------------------------------
// Weight norm (fan-in 512) + mem_kv norm, one launch.
// ---------------------------------------------------------------------------
__global__ void __launch_bounds__(256) prep_kernel(const float* __restrict__ w_qkv,
                                                   const float* __restrict__ w_out,
                                                   const float* __restrict__ mem_kv,
                                                   __half* __restrict__ wnq,
                                                   __half* __restrict__ wno,
                                                   __half* __restrict__ km,
                                                   __half* __restrict__ vm)
{
    int r = blockIdx.x;
    if (r >= K3 + CIN) {
        if (threadIdx.x < 32) {
            int row = r - (K3 + CIN);
            int part = row >> 5, rk = row & 31;
            const float* src = mem_kv + part * 2048 + rk * 64;
            float v0 = src[threadIdx.x], v1 = src[threadIdx.x + 32];
            float s = v0 * v0 + v1 * v1;
#pragma unroll
            for (int off = 16; off; off >>= 1) s += __shfl_xor_sync(0xffffffffu, s, off);
            float sc = 8.f / fmaxf(sqrtf(s), 1e-4f);
            __half* dst = (part ? vm : km) + rk * 64;
            dst[threadIdx.x]      = __float2half(v0 * sc);
            dst[threadIdx.x + 32] = __float2half(v1 * sc);
        }
        return;
    }
    const float* wr;
    __half* out;
    if (r < K3) { wr = w_qkv + (size_t)r * CIN;        out = wnq + (size_t)r * CIN; }
    else        { wr = w_out + (size_t)(r - K3) * HID; out = wno + (size_t)(r - K3) * HID; }
    float s = 0.f;
    for (int i = threadIdx.x; i < 512; i += 256) { float v = wr[i]; s += v * v; }
    __shared__ float red[8];
#pragma unroll
    for (int off = 16; off; off >>= 1) s += __shfl_xor_sync(0xffffffffu, s, off);
    if ((threadIdx.x & 31) == 0) red[threadIdx.x >> 5] = s;
    __syncthreads();
    if (threadIdx.x == 0) {
        float v = 0.f;
#pragma unroll
        for (int i = 0; i < 8; i++) v += red[i];
        red[0] = v;
    }
    __syncthreads();
    float inv = 1.f / (1e-4f * 22.627416998f + sqrtf(red[0]));
    for (int i = threadIdx.x; i < 512; i += 256)
        out[i] = __float2half(wr[i] * inv);
}

// ---------------------------------------------------------------------------
// QKV GEMM with fused pixel-norm epilogue (validated round 7).
// ---------------------------------------------------------------------------
__global__ void __launch_bounds__(256) hgemm_qkv(const __half* __restrict__ A,
                                                 const float* __restrict__ Bf0,
                                                 __half* __restrict__ qn,
                                                 __half* __restrict__ kn,
                                                 __half* __restrict__ vn)
{
    constexpr int ND = 1024, KD = 512;
    __shared__ char smc[32768];
    const uint32_t sb = (uint32_t)__cvta_generic_to_shared(smc);
    const uint32_t AS = sb, BS = sb + 16384;

    const int b   = blockIdx.z;
    const int bm0 = blockIdx.y * 128;
    const int bn0 = blockIdx.x * 128;
    const float* Bf = Bf0 + (size_t)b * KD * ND;

    const int tid = threadIdx.x;
    const int w = tid >> 5, lane = tid & 31;
    const int g = lane >> 2, tg = lane & 3;
    const int mat = lane >> 3, rr = lane & 7;
    const int m_off = (w >> 2) * 64;
    const int n_off = (w & 3) * 32;

    float acc[4][4][4];
#pragma unroll
    for (int i = 0; i < 4; i++)
#pragma unroll
        for (int j = 0; j < 4; j++)
#pragma unroll
            for (int r = 0; r < 4; r++) acc[i][j][r] = 0.f;

    int ar[4], ac[4], br_[4], bc[4];
#pragma unroll
    for (int i = 0; i < 4; i++) {
        int cid = i * 256 + tid;
        ar[i] = cid >> 3;  ac[i] = cid & 7;
        br_[i] = cid >> 4; bc[i] = cid & 15;
    }

    uint4 aR[4];
    float4 bF0[4], bF1[4];
#pragma unroll
    for (int i = 0; i < 4; i++) {
        aR[i]  = *(const uint4*)(A + (size_t)(bm0 + ar[i]) * KD + ac[i] * 8);
        bF0[i] = *(const float4*)(Bf + (size_t)br_[i] * ND + bn0 + bc[i] * 8);
        bF1[i] = *(const float4*)(Bf + (size_t)br_[i] * ND + bn0 + bc[i] * 8 + 4);
    }

    for (int it = 0; it < 8; ++it) {
        __syncthreads();
#pragma unroll
        for (int i = 0; i < 4; i++) {
            *(uint4*)(smc + ar[i] * 128 + ((ac[i] ^ (ar[i] & 7)) << 4)) = aR[i];
            uint32_t boff = 16384 + br_[i] * 256 +
                            (((bc[i] & 8) | ((bc[i] & 7) ^ (br_[i] & 7))) << 4);
            __half2 h0 = __floats2half2_rn(bF0[i].x, bF0[i].y);
            __half2 h1 = __floats2half2_rn(bF0[i].z, bF0[i].w);
            __half2 h2 = __floats2half2_rn(bF1[i].x, bF1[i].y);
            __half2 h3 = __floats2half2_rn(bF1[i].z, bF1[i].w);
            uint4 pk;
            pk.x = *(uint32_t*)&h0; pk.y = *(uint32_t*)&h1;
            pk.z = *(uint32_t*)&h2; pk.w = *(uint32_t*)&h3;
            *(uint4*)(smc + boff) = pk;
        }
        __syncthreads();

        if (it < 7) {
            int k0 = (it + 1) * 64;
#pragma unroll
            for (int i = 0; i < 4; i++) {
                aR[i]  = *(const uint4*)(A + (size_t)(bm0 + ar[i]) * KD + k0 + ac[i] * 8);
                bF0[i] = *(const float4*)(Bf + (size_t)(k0 + br_[i]) * ND + bn0 + bc[i] * 8);
                bF1[i] = *(const float4*)(Bf + (size_t)(k0 + br_[i]) * ND + bn0 + bc[i] * 8 + 4);
            }
        }

#pragma unroll
        for (int kk = 0; kk < 4; kk++) {
            uint32_t af[4][4];
#pragma unroll
            for (int mt = 0; mt < 4; mt++) {
                int row = m_off + mt * 16 + (mat & 1) * 8 + rr;
                int ch = kk * 2 + (mat >> 1);
                ldsm_x4(af[mt][0], af[mt][1], af[mt][2], af[mt][3],
                        AS + row * 128 + ((ch ^ (row & 7)) << 4));
            }
#pragma unroll
            for (int np = 0; np < 2; np++) {
                int row = kk * 16 + (mat & 1) * 8 + rr;
                int c = (n_off >> 3) + np * 2 + (mat >> 1);
                uint32_t b0, b1, b2, b3;
                ldsm_x4t(b0, b1, b2, b3,
                         BS + row * 256 + (((c & 8) | ((c & 7) ^ (row & 7))) << 4));
#pragma unroll
                for (int mt = 0; mt < 4; mt++) {
                    mma_f16(acc[mt][np * 2],     af[mt][0], af[mt][1], af[mt][2], af[mt][3], b0, b1);
                    mma_f16(acc[mt][np * 2 + 1], af[mt][0], af[mt][1], af[mt][2], af[mt][3], b2, b3);
                }
            }
        }
    }

    __syncthreads();
    const int gr0  = bm0 + m_off;
    const int comp = gr0 >> 9;
    const int head = (gr0 & 511) >> 6;
    const float sc_num = (comp == 0) ? 1.4426950408889634f : 8.f;
    __half* st = (__half*)(smc + w * 4096);

#pragma unroll
    for (int nt = 0; nt < 4; nt++) {
        float ss0 = 0.f, ss1 = 0.f;
#pragma unroll
        for (int mt = 0; mt < 4; mt++) {
            ss0 += acc[mt][nt][0] * acc[mt][nt][0] + acc[mt][nt][2] * acc[mt][nt][2];
            ss1 += acc[mt][nt][1] * acc[mt][nt][1] + acc[mt][nt][3] * acc[mt][nt][3];
        }
#pragma unroll
        for (int off = 4; off <= 16; off <<= 1) {
            ss0 += __shfl_xor_sync(0xffffffffu, ss0, off);
            ss1 += __shfl_xor_sync(0xffffffffu, ss1, off);
        }
        float s0 = sc_num / fmaxf(sqrtf(ss0), 1e-4f);
        float s1 = sc_num / fmaxf(sqrtf(ss1), 1e-4f);
        int c0 = nt * 8 + 2 * tg;
#pragma unroll
        for (int mt = 0; mt < 4; mt++) {
            int r = mt * 16 + g;
            st[c0 * 64 + r]           = __float2half(acc[mt][nt][0] * s0);
            st[c0 * 64 + r + 8]       = __float2half(acc[mt][nt][2] * s0);
            st[(c0 + 1) * 64 + r]     = __float2half(acc[mt][nt][1] * s1);
            st[(c0 + 1) * 64 + r + 8] = __float2half(acc[mt][nt][3] * s1);
        }
    }
    __syncwarp();
    __half* dst = (comp == 0 ? qn : comp == 1 ? kn : vn) +
                  ((size_t)(b * HEADS + head) * NPIX + bn0 + n_off) * DIMH;
#pragma unroll 8
    for (int c = 0; c < 32; c++) {
        __half2 v = *(__half2*)(st + c * 64 + lane * 2);
        *(__half2*)(dst + (size_t)c * DIMH + lane * 2) = v;
    }
}

// ---------------------------------------------------------------------------
// Output projection GEMM + MPAdd (validated round 7).
// ---------------------------------------------------------------------------
__global__ void __launch_bounds__(256) hgemm_out(const __half* __restrict__ A,
                                                 const __half* __restrict__ Bm,
                                                 float* __restrict__ Cm,
                                                 const float* __restrict__ X)
{
    constexpr int ND = 1024, KD = 512, MD = CIN;
    __shared__ char smc[32768];
    const uint32_t sb = (uint32_t)__cvta_generic_to_shared(smc);
    const uint32_t AS = sb, BS = sb + 16384;

    const int b   = blockIdx.z;
    const int bm0 = blockIdx.y * 128;
    const int bn0 = blockIdx.x * 128;
    const __half* Bh = Bm + (size_t)b * KD * ND;
    float* Cb = Cm + (size_t)b * MD * ND;

    const int tid = threadIdx.x;
    const int w = tid >> 5, lane = tid & 31;
    const int g = lane >> 2, tg = lane & 3;
    const int mat = lane >> 3, rr = lane & 7;
    const int m_off = (w >> 2) * 64;
    const int n_off = (w & 3) * 32;

    float acc[4][4][4];
#pragma unroll
    for (int i = 0; i < 4; i++)
#pragma unroll
        for (int j = 0; j < 4; j++)
#pragma unroll
            for (int r = 0; r < 4; r++) acc[i][j][r] = 0.f;

    int ar[4], ac[4], br_[4], bc[4];
#pragma unroll
    for (int i = 0; i < 4; i++) {
        int cid = i * 256 + tid;
        ar[i] = cid >> 3;  ac[i] = cid & 7;
        br_[i] = cid >> 4; bc[i] = cid & 15;
    }

    uint4 aR[4], bR[4];
#pragma unroll
    for (int i = 0; i < 4; i++) {
        aR[i] = *(const uint4*)(A + (size_t)(bm0 + ar[i]) * KD + ac[i] * 8);
        bR[i] = *(const uint4*)(Bh + (size_t)br_[i] * ND + bn0 + bc[i] * 8);
    }

    for (int it = 0; it < 8; ++it) {
        __syncthreads();
#pragma unroll
        for (int i = 0; i < 4; i++) {
            *(uint4*)(smc + ar[i] * 128 + ((ac[i] ^ (ar[i] & 7)) << 4)) = aR[i];
            uint32_t boff = 16384 + br_[i] * 256 +
                            (((bc[i] & 8) | ((bc[i] & 7) ^ (br_[i] & 7))) << 4);
            *(uint4*)(smc + boff) = bR[i];
        }
        __syncthreads();

        if (it < 7) {
            int k0 = (it + 1) * 64;
#pragma unroll
            for (int i = 0; i < 4; i++) {
                aR[i] = *(const uint4*)(A + (size_t)(bm0 + ar[i]) * KD + k0 + ac[i] * 8);
                bR[i] = *(const uint4*)(Bh + (size_t)(k0 + br_[i]) * ND + bn0 + bc[i] * 8);
            }
        }

#pragma unroll
        for (int kk = 0; kk < 4; kk++) {
            uint32_t af[4][4];
#pragma unroll
            for (int mt = 0; mt < 4; mt++) {
                int row = m_off + mt * 16 + (mat & 1) * 8 + rr;
                int ch = kk * 2 + (mat >> 1);
                ldsm_x4(af[mt][0], af[mt][1], af[mt][2], af[mt][3],
                        AS + row * 128 + ((ch ^ (row & 7)) << 4));
            }
#pragma unroll
            for (int np = 0; np < 2; np++) {
                int row = kk * 16 + (mat & 1) * 8 + rr;
                int c = (n_off >> 3) + np * 2 + (mat >> 1);
                uint32_t b0, b1, b2, b3;
                ldsm_x4t(b0, b1, b2, b3,
                         BS + row * 256 + (((c & 8) | ((c & 7) ^ (row & 7))) << 4));
#pragma unroll
                for (int mt = 0; mt < 4; mt++) {
                    mma_f16(acc[mt][np * 2],     af[mt][0], af[mt][1], af[mt][2], af[mt][3], b0, b1);
                    mma_f16(acc[mt][np * 2 + 1], af[mt][0], af[mt][1], af[mt][2], af[mt][3], b2, b3);
                }
            }
        }
    }

    const float a_out = 0.9191450300f;
    const float a_x   = 0.3939192986f;
#pragma unroll
    for (int mt = 0; mt < 4; mt++) {
        int r1 = bm0 + m_off + mt * 16 + g;
        int r2 = r1 + 8;
#pragma unroll
        for (int nt = 0; nt < 4; nt++) {
            int col = bn0 + n_off + nt * 8 + 2 * tg;
            float2 v1 = make_float2(acc[mt][nt][0], acc[mt][nt][1]);
            float2 v2 = make_float2(acc[mt][nt][2], acc[mt][nt][3]);
            float2 x1 = *(const float2*)&X[((size_t)b * MD + r1) * ND + col];
            float2 x2 = *(const float2*)&X[((size_t)b * MD + r2) * ND + col];
            v1.x = v1.x * a_out + x1.x * a_x;  v1.y = v1.y * a_out + x1.y * a_x;
            v2.x = v2.x * a_out + x2.x * a_x;  v2.y = v2.y * a_out + x2.y * a_x;
            *(float2*)&Cb[(size_t)r1 * ND + col] = v1;
            *(float2*)&Cb[(size_t)r2 * ND + col] = v2;
        }
    }
}

// ---------------------------------------------------------------------------
// fp16 flash attention, 128-query blocks, 8 warps, cp.async double-buffered K/V.
// smem (dynamic 64KB): Q[0,16K) P[16K,32K) K 2x8K [32K,48K) V 2x8K [48K,64K).
// Per-warp fragment math identical to validated rounds 5-7.
// ---------------------------------------------------------------------------
__global__ void __launch_bounds__(256, 2) attn_f16(const __half* __restrict__ qn,
                                                   const __half* __restrict__ kn,
                                                   const __half* __restrict__ vn,
                                                   const __half* __restrict__ km,
                                                   const __half* __restrict__ vm,
                                                   __half* __restrict__ attn_out)
{
    extern __shared__ char smc[];
    const uint32_t sb = (uint32_t)__cvta_generic_to_shared(smc);
    const uint32_t QS = sb, PS = sb + 16384, KS = sb + 32768, VS = sb + 49152;

    const int b = blockIdx.z, h = blockIdx.y, i0 = blockIdx.x * 128;
    const int tid = threadIdx.x, lane = tid & 31;
    const int g = lane >> 2, tg = lane & 3;
    const int m0 = (tid >> 5) * 16;
    const int mat = lane >> 3, rr = lane & 7;

    const __half* qh = qn + ((size_t)(b * HEADS + h) * NPIX + i0) * DIMH;
    const __half* kh = kn + (size_t)(b * HEADS + h) * NPIX * DIMH;
    const __half* vh = vn + (size_t)(b * HEADS + h) * NPIX * DIMH;

    // per-thread K/V staging coords (2 chunks each of K and V per tile)
    int cr[2], cc[2];
    uint32_t coff[2];
#pragma unroll
    for (int i = 0; i < 2; i++) {
        int idx = tid + i * 256;
        cr[i] = idx >> 3;  cc[i] = idx & 7;
        coff[i] = cr[i] * 128 + ((cc[i] ^ (cr[i] & 7)) << 4);
    }

    // issue tile-0 (mem-kv, zero-filled beyond 4 keys) via cp.async
#pragma unroll
    for (int i = 0; i < 2; i++) {
        int sz = (cr[i] < 4) ? 16 : 0;
        const __half* ks0 = km + ((h * 4 + (cr[i] & 3)) * 64 + cc[i] * 8);
        const __half* vs0 = vm + ((h * 4 + (cr[i] & 3)) * 64 + cc[i] * 8);
        cp16z(KS + coff[i], ks0, sz);
        cp16z(VS + coff[i], vs0, sz);
    }
    asm volatile("cp.async.commit_group;");

    // load Q tile (128 rows x 8 chunks) while tile-0 KV is in flight
    for (int idx = tid; idx < 1024; idx += 256) {
        int r = idx >> 3, c = idx & 7;
        uint4 v = *(const uint4*)(qh + r * 64 + c * 8);
        *(uint4*)(smc + r * 128 + ((c ^ (r & 7)) << 4)) = v;
    }
    __syncthreads();

    // Q fragments (invariant across tiles)
    uint32_t aq[4][4];
    {
        int qrow = m0 + (mat & 1) * 8 + rr;
#pragma unroll
        for (int kc = 0; kc < 4; kc++) {
            int ch = 2 * kc + (mat >> 1);
            ldsm_x4(aq[kc][0], aq[kc][1], aq[kc][2], aq[kc][3],
                    QS + qrow * 128 + ((ch ^ (qrow & 7)) << 4));
        }
    }

    float oacc[8][4];
#pragma unroll
    for (int nt = 0; nt < 8; nt++)
#pragma unroll
        for (int r = 0; r < 4; r++) oacc[nt][r] = 0.f;
    float mrow[2] = {-1e30f, -1e30f};
    float lrow[2] = {0.f, 0.f};

    for (int t = 0; t <= 16; ++t) {
        __syncthreads();   // all warps done with tile t-1 => buffer (t+1)&1 free
        if (t < 16) {
            const __half* kt = kh + (size_t)t * 64 * 64;   // tile t+1 = spatial tile t
            const __half* vt = vh + (size_t)t * 64 * 64;
            uint32_t kb = KS + ((t + 1) & 1) * 8192;
            uint32_t vb = VS + ((t + 1) & 1) * 8192;
#pragma unroll
            for (int i = 0; i < 2; i++) {
                cp16(kb + coff[i], kt + cr[i] * 64 + cc[i] * 8);
                cp16(vb + coff[i], vt + cr[i] * 64 + cc[i] * 8);
            }
            asm volatile("cp.async.commit_group;");
            asm volatile("cp.async.wait_group 1;");
        } else {
            asm volatile("cp.async.wait_group 0;");
        }
        __syncthreads();   // tile t visible to all warps

        const uint32_t kb = KS + (t & 1) * 8192;
        const uint32_t vb = VS + (t & 1) * 8192;

        // ---- S = Q.K^T
        float sacc[8][4];
#pragma unroll
        for (int nt = 0; nt < 8; nt++)
#pragma unroll
            for (int r = 0; r < 4; r++) sacc[nt][r] = 0.f;
#pragma unroll
        for (int np = 0; np < 4; np++) {
            int key = (2 * np + (mat >> 1)) * 8 + rr;
#pragma unroll
            for (int kc = 0; kc < 4; kc++) {
                int ch = 2 * kc + (mat & 1);
                uint32_t addr = kb + key * 128 + ((ch ^ (key & 7)) << 4);
                uint32_t b0, b1, b2, b3;
                ldsm_x4(b0, b1, b2, b3, addr);
                mma_f16(sacc[2 * np],     aq[kc][0], aq[kc][1], aq[kc][2], aq[kc][3], b0, b1);
                mma_f16(sacc[2 * np + 1], aq[kc][0], aq[kc][1], aq[kc][2], aq[kc][3], b2, b3);
            }
        }
        if (t == 0) {
#pragma unroll
            for (int nt = 0; nt < 8; nt++) {
                int c0 = nt * 8 + 2 * tg;
                if (c0 >= 4)     { sacc[nt][0] = -1e30f; sacc[nt][2] = -1e30f; }
                if (c0 + 1 >= 4) { sacc[nt][1] = -1e30f; sacc[nt][3] = -1e30f; }
            }
        }

        // ---- online softmax (rows m0+g and m0+g+8)
        float tm0 = -1e30f, tm1 = -1e30f;
#pragma unroll
        for (int nt = 0; nt < 8; nt++) {
            tm0 = fmaxf(tm0, fmaxf(sacc[nt][0], sacc[nt][1]));
            tm1 = fmaxf(tm1, fmaxf(sacc[nt][2], sacc[nt][3]));
        }
        tm0 = fmaxf(tm0, __shfl_xor_sync(0xffffffffu, tm0, 1));
        tm0 = fmaxf(tm0, __shfl_xor_sync(0xffffffffu, tm0, 2));
        tm1 = fmaxf(tm1, __shfl_xor_sync(0xffffffffu, tm1, 1));
        tm1 = fmaxf(tm1, __shfl_xor_sync(0xffffffffu, tm1, 2));

        float mn0 = fmaxf(mrow[0], tm0), mn1 = fmaxf(mrow[1], tm1);
        float al0 = ex2f(mrow[0] - mn0), al1 = ex2f(mrow[1] - mn1);
        float rs0 = 0.f, rs1 = 0.f;
        const int row0 = m0 + g, row1 = m0 + g + 8;
#pragma unroll
        for (int nt = 0; nt < 8; nt++) {
            float p00 = ex2f(sacc[nt][0] - mn0);
            float p01 = ex2f(sacc[nt][1] - mn0);
            float p10 = ex2f(sacc[nt][2] - mn1);
            float p11 = ex2f(sacc[nt][3] - mn1);
            rs0 += p00 + p01;  rs1 += p10 + p11;
            uint32_t a0 = PS + row0 * 128 + ((nt ^ (row0 & 7)) << 4) + (tg << 2);
            uint32_t a1 = PS + row1 * 128 + ((nt ^ (row1 & 7)) << 4) + (tg << 2);
            __half2 h0 = __floats2half2_rn(p00, p01);
            __half2 h1 = __floats2half2_rn(p10, p11);
            asm volatile("st.shared.b32 [%0], %1;" :: "r"(a0), "r"(*(uint32_t*)&h0));
            asm volatile("st.shared.b32 [%0], %1;" :: "r"(a1), "r"(*(uint32_t*)&h1));
        }
        rs0 += __shfl_xor_sync(0xffffffffu, rs0, 1);
        rs0 += __shfl_xor_sync(0xffffffffu, rs0, 2);
        rs1 += __shfl_xor_sync(0xffffffffu, rs1, 1);
        rs1 += __shfl_xor_sync(0xffffffffu, rs1, 2);
        lrow[0] = lrow[0] * al0 + rs0;  mrow[0] = mn0;
        lrow[1] = lrow[1] * al1 + rs1;  mrow[1] = mn1;
#pragma unroll
        for (int nt = 0; nt < 8; nt++) {
            oacc[nt][0] *= al0;  oacc[nt][1] *= al0;
            oacc[nt][2] *= al1;  oacc[nt][3] *= al1;
        }
        __syncwarp();   // Ps rows m0..m0+15 are warp-private

        // ---- O += P.V
#pragma unroll
        for (int kc = 0; kc < 4; kc++) {
            int prow = m0 + (mat & 1) * 8 + rr;
            int pch = 2 * kc + (mat >> 1);
            uint32_t paddr = PS + prow * 128 + ((pch ^ (prow & 7)) << 4);
            uint32_t a0, a1, a2, a3;
            ldsm_x4(a0, a1, a2, a3, paddr);
            int key = kc * 16 + (mat & 1) * 8 + rr;
#pragma unroll
            for (int np = 0; np < 4; np++) {
                int ch = 2 * np + (mat >> 1);
                uint32_t vaddr = vb + key * 128 + ((ch ^ (key & 7)) << 4);
                uint32_t b0, b1, b2, b3;
                ldsm_x4t(b0, b1, b2, b3, vaddr);
                mma_f16(oacc[2 * np],     a0, a1, a2, a3, b0, b1);
                mma_f16(oacc[2 * np + 1], a0, a1, a2, a3, b2, b3);
            }
        }
    }

    // ---- epilogue: normalize, stage fp32 at smc[0..33792), coalesced store
    __syncthreads();
    float* fs = (float*)smc;   // 128 rows x stride 66
    {
        float il0 = 1.f / lrow[0], il1 = 1.f / lrow[1];
        const int row0 = m0 + g, row1 = m0 + g + 8;
#pragma unroll
        for (int nt = 0; nt < 8; nt++) {
            int c = nt * 8 + 2 * tg;
            fs[row0 * 66 + c]     = oacc[nt][0] * il0;
            fs[row0 * 66 + c + 1] = oacc[nt][1] * il0;
            fs[row1 * 66 + c]     = oacc[nt][2] * il1;
            fs[row1 * 66 + c + 1] = oacc[nt][3] * il1;
        }
    }
    __syncthreads();
    {
        __half* ob = attn_out + ((size_t)b * HID + h * DIMH) * NPIX;
        for (int idx = tid; idx < 128 * 64; idx += 256) {
            int m = idx & 127, d = idx >> 7;
            ob[(size_t)d * NPIX + i0 + m] = __float2half(fs[m * 66 + d]);
        }
    }
}

// ---------------------------------------------------------------------------
extern "C" void kernel_launch(void* const* d_in, const int* in_sizes, int n_in,
                              void* d_out, int out_size)
{
    const float* x      = (const float*)d_in[0];  // [16,512,32,32]
    const float* w_qkv  = (const float*)d_in[1];  // [1536,512]
    const float* w_out  = (const float*)d_in[2];  // [512,512]
    const float* mem_kv = (const float*)d_in[3];  // [2,8,4,64]
    float* out = (float*)d_out;                   // [16,512,32,32]

    __half *wnq, *wno, *attn, *qn, *kn, *vn, *km, *vm;
    cudaGetSymbolAddress((void**)&wnq,  g_wn_qkv);
    cudaGetSymbolAddress((void**)&wno,  g_wn_out);
    cudaGetSymbolAddress((void**)&attn, g_attn);
    cudaGetSymbolAddress((void**)&qn,   g_qn);
    cudaGetSymbolAddress((void**)&kn,   g_kn);
    cudaGetSymbolAddress((void**)&vn,   g_vn);
    cudaGetSymbolAddress((void**)&km,   g_km);
    cudaGetSymbolAddress((void**)&vm,   g_vm);

    cudaFuncSetAttribute(attn_f16, cudaFuncAttributeMaxDynamicSharedMemorySize, 65536);

    // weight norms + mem_kv norm, one launch
    prep_kernel<<<K3 + CIN + 64, 256>>>(w_qkv, w_out, mem_kv, wnq, wno, km, vm);

    // QKV projection with fused pixel-norm -> qn/kn/vn fp16 [b,h,n,d]
    hgemm_qkv<<<dim3(8, K3 / 128, NB), 256>>>(wnq, x, qn, kn, vn);

    // Attention (128-query blocks, cp.async pipeline)
    attn_f16<<<dim3(NPIX / 128, HEADS, NB), 256, 65536>>>(qn, kn, vn, km, vm, attn);

    // Output projection + MPAdd residual
    hgemm_out<<<dim3(8, CIN / 128, NB), 256>>>(wno, attn, out, x);
}

// round 9
// speedup vs baseline: 7.5714x; 1.2109x over previous
#include <cuda_runtime.h>
#include <cuda_fp16.h>
#include <math.h>
#include <stdint.h>

#define NB    16
#define CIN   512
#define NPIX  1024
#define HEADS 8
#define DIMH  64
#define HID   512
#define K3    1536   // 3*HID

// Scratch (allocation-free, device globals)
__device__ __half g_wn_qkv[K3 * CIN];
__device__ __half g_wn_out[CIN * HID];
__device__ __half g_xh[(size_t)NB * CIN * NPIX];          // fp16 copy of x
__device__ __half g_attn[(size_t)NB * HID * NPIX];
__device__ __half g_qn[(size_t)NB * HEADS * NPIX * DIMH];
__device__ __half g_kn[(size_t)NB * HEADS * NPIX * DIMH];
__device__ __half g_vn[(size_t)NB * HEADS * NPIX * DIMH];
__device__ __half g_km[HEADS * 4 * DIMH];
__device__ __half g_vm[HEADS * 4 * DIMH];

// ---------------------------------------------------------------------------
// helpers
// ---------------------------------------------------------------------------
__device__ __forceinline__ float ex2f(float x) {
    float y;
    asm("ex2.approx.f32 %0, %1;" : "=f"(y) : "f"(x));
    return y;
}
__device__ __forceinline__ void mma_f16(float (&d)[4],
                                        uint32_t a0, uint32_t a1, uint32_t a2, uint32_t a3,
                                        uint32_t b0, uint32_t b1) {
    asm volatile(
        "mma.sync.aligned.m16n8k16.row.col.f32.f16.f16.f32 "
        "{%0,%1,%2,%3}, {%4,%5,%6,%7}, {%8,%9}, {%0,%1,%2,%3};"
        : "+f"(d[0]), "+f"(d[1]), "+f"(d[2]), "+f"(d[3])
        : "r"(a0), "r"(a1), "r"(a2), "r"(a3), "r"(b0), "r"(b1));
}
__device__ __forceinline__ void ldsm_x4(uint32_t& r0, uint32_t& r1, uint32_t& r2,
                                        uint32_t& r3, uint32_t addr) {
    asm volatile("ldmatrix.sync.aligned.m8n8.x4.shared.b16 {%0,%1,%2,%3}, [%4];"
                 : "=r"(r0), "=r"(r1), "=r"(r2), "=r"(r3) : "r"(addr));
}
__device__ __forceinline__ void ldsm_x4t(uint32_t& r0, uint32_t& r1, uint32_t& r2,
                                         uint32_t& r3, uint32_t addr) {
    asm volatile("ldmatrix.sync.aligned.m8n8.x4.trans.shared.b16 {%0,%1,%2,%3}, [%4];"
                 : "=r"(r0), "=r"(r1), "=r"(r2), "=r"(r3) : "r"(addr));
}
__device__ __forceinline__ void cp16(uint32_t s, const void* g) {
    asm volatile("cp.async.cg.shared.global [%0], [%1], 16;" :: "r"(s), "l"(g));
}
__device__ __forceinline__ void cp16z(uint32_t s, const void* g, int sz) {
    asm volatile("cp.async.cg.shared.global [%0], [%1], 16, %2;"
                 :: "r"(s), "l"(g), "r"(sz));
}

// ---------------------------------------------------------------------------
// prep: weight norms (fan-in 512) + mem_kv norm + x fp32->fp16 conversion.
// Blocks: [0,K3) w_qkv | [K3,K3+CIN) w_out | [+64) mem_kv | [+2048) x chunks.
// ---------------------------------------------------------------------------
#define PREP_MEMKV (K3 + CIN)
#define PREP_X     (K3 + CIN + 64)

__global__ void __launch_bounds__(256) prep_kernel(const float* __restrict__ w_qkv,
                                                   const float* __restrict__ w_out,
                                                   const float* __restrict__ mem_kv,
                                                   const float* __restrict__ x,
                                                   __half* __restrict__ wnq,
                                                   __half* __restrict__ wno,
                                                   __half* __restrict__ km,
                                                   __half* __restrict__ vm,
                                                   __half* __restrict__ xh)
{
    int r = blockIdx.x;
    if (r >= PREP_X) {
        // convert 4096 consecutive floats of x to fp16
        size_t base = (size_t)(r - PREP_X) * 4096;
#pragma unroll
        for (int j = 0; j < 2; j++) {
            size_t off = base + ((size_t)j * 256 + threadIdx.x) * 8;
            float4 f0 = *(const float4*)(x + off);
            float4 f1 = *(const float4*)(x + off + 4);
            __half2 h0 = __floats2half2_rn(f0.x, f0.y);
            __half2 h1 = __floats2half2_rn(f0.z, f0.w);
            __half2 h2 = __floats2half2_rn(f1.x, f1.y);
            __half2 h3 = __floats2half2_rn(f1.z, f1.w);
            uint4 pk;
            pk.x = *(uint32_t*)&h0; pk.y = *(uint32_t*)&h1;
            pk.z = *(uint32_t*)&h2; pk.w = *(uint32_t*)&h3;
            *(uint4*)(xh + off) = pk;
        }
        return;
    }
    if (r >= PREP_MEMKV) {
        if (threadIdx.x < 32) {
            int row = r - PREP_MEMKV;
            int part = row >> 5, rk = row & 31;
            const float* src = mem_kv + part * 2048 + rk * 64;
            float v0 = src[threadIdx.x], v1 = src[threadIdx.x + 32];
            float s = v0 * v0 + v1 * v1;
#pragma unroll
            for (int off = 16; off; off >>= 1) s += __shfl_xor_sync(0xffffffffu, s, off);
            float sc = 8.f / fmaxf(sqrtf(s), 1e-4f);
            __half* dst = (part ? vm : km) + rk * 64;
            dst[threadIdx.x]      = __float2half(v0 * sc);
            dst[threadIdx.x + 32] = __float2half(v1 * sc);
        }
        return;
    }
    const float* wr;
    __half* out;
    if (r < K3) { wr = w_qkv + (size_t)r * CIN;        out = wnq + (size_t)r * CIN; }
    else        { wr = w_out + (size_t)(r - K3) * HID; out = wno + (size_t)(r - K3) * HID; }
    float s = 0.f;
    for (int i = threadIdx.x; i < 512; i += 256) { float v = wr[i]; s += v * v; }
    __shared__ float red[8];
#pragma unroll
    for (int off = 16; off; off >>= 1) s += __shfl_xor_sync(0xffffffffu, s, off);
    if ((threadIdx.x & 31) == 0) red[threadIdx.x >> 5] = s;
    __syncthreads();
    if (threadIdx.x == 0) {
        float v = 0.f;
#pragma unroll
        for (int i = 0; i < 8; i++) v += red[i];
        red[0] = v;
    }
    __syncthreads();
    float inv = 1.f / (1e-4f * 22.627416998f + sqrtf(red[0]));
    for (int i = threadIdx.x; i < 512; i += 256)
        out[i] = __float2half(wr[i] * inv);
}

// ---------------------------------------------------------------------------
// cp.async double-buffered fp16 GEMM: C[b](MDx1024) = A(MDx512) * B[b](512x1024).
// 2 smem stages of (A 16KB + B 16KB) = 64KB dynamic. __launch_bounds__(256,2).
// QKV=true : fused pixel-norm epilogue -> qn/kn/vn fp16 [b,h,n,d].
// QKV=false: MPAdd residual epilogue -> fp32 Cf.
// ---------------------------------------------------------------------------
template<int MD, bool QKV>
__global__ void __launch_bounds__(256, 2) hgemm_pipe(const __half* __restrict__ A,
                                                     const __half* __restrict__ Bm,
                                                     __half* __restrict__ qn,
                                                     __half* __restrict__ kn,
                                                     __half* __restrict__ vn,
                                                     float* __restrict__ Cf,
                                                     const float* __restrict__ X)
{
    constexpr int ND = 1024, KD = 512;
    extern __shared__ char smc[];
    const uint32_t sb = (uint32_t)__cvta_generic_to_shared(smc);

    const int b   = blockIdx.z;
    const int bm0 = blockIdx.y * 128;
    const int bn0 = blockIdx.x * 128;
    const __half* Bh = Bm + (size_t)b * KD * ND;

    const int tid = threadIdx.x;
    const int w = tid >> 5, lane = tid & 31;
    const int g = lane >> 2, tg = lane & 3;
    const int mat = lane >> 3, rr = lane & 7;
    const int m_off = (w >> 2) * 64;
    const int n_off = (w & 3) * 32;

    float acc[4][4][4];
#pragma unroll
    for (int i = 0; i < 4; i++)
#pragma unroll
        for (int j = 0; j < 4; j++)
#pragma unroll
            for (int r = 0; r < 4; r++) acc[i][j][r] = 0.f;

    int ar[4], ac[4], br_[4], bc[4];
    uint32_t aoff[4], boff[4];
#pragma unroll
    for (int i = 0; i < 4; i++) {
        int cid = i * 256 + tid;
        ar[i] = cid >> 3;  ac[i] = cid & 7;
        br_[i] = cid >> 4; bc[i] = cid & 15;
        aoff[i] = ar[i] * 128 + ((ac[i] ^ (ar[i] & 7)) << 4);
        boff[i] = 16384 + br_[i] * 256 +
                  (((bc[i] & 8) | ((bc[i] & 7) ^ (br_[i] & 7))) << 4);
    }

    // prologue: issue slabs 0 and 1
#pragma unroll
    for (int s = 0; s < 2; s++) {
        int k0 = s * 64;
        uint32_t st = sb + s * 32768;
#pragma unroll
        for (int i = 0; i < 4; i++) {
            cp16(st + aoff[i], A + (size_t)(bm0 + ar[i]) * KD + k0 + ac[i] * 8);
            cp16(st + boff[i], Bh + (size_t)(k0 + br_[i]) * ND + bn0 + bc[i] * 8);
        }
        asm volatile("cp.async.commit_group;");
    }

    for (int it = 0; it < 8; ++it) {
        if (it < 7) asm volatile("cp.async.wait_group 1;");
        else        asm volatile("cp.async.wait_group 0;");
        __syncthreads();

        const uint32_t AS = sb + (it & 1) * 32768;
        const uint32_t BS = AS + 16384;
#pragma unroll
        for (int kk = 0; kk < 4; kk++) {
            uint32_t af[4][4];
#pragma unroll
            for (int mt = 0; mt < 4; mt++) {
                int row = m_off + mt * 16 + (mat & 1) * 8 + rr;
                int ch = kk * 2 + (mat >> 1);
                ldsm_x4(af[mt][0], af[mt][1], af[mt][2], af[mt][3],
                        AS + row * 128 + ((ch ^ (row & 7)) << 4));
            }
#pragma unroll
            for (int np = 0; np < 2; np++) {
                int row = kk * 16 + (mat & 1) * 8 + rr;
                int c = (n_off >> 3) + np * 2 + (mat >> 1);
                uint32_t b0, b1, b2, b3;
                ldsm_x4t(b0, b1, b2, b3,
                         BS + row * 256 + (((c & 8) | ((c & 7) ^ (row & 7))) << 4));
#pragma unroll
                for (int mt = 0; mt < 4; mt++) {
                    mma_f16(acc[mt][np * 2],     af[mt][0], af[mt][1], af[mt][2], af[mt][3], b0, b1);
                    mma_f16(acc[mt][np * 2 + 1], af[mt][0], af[mt][1], af[mt][2], af[mt][3], b2, b3);
                }
            }
        }
        __syncthreads();   // all warps done with this stage buffer

        if (it + 2 < 8) {
            int k0 = (it + 2) * 64;
            uint32_t st = sb + (it & 1) * 32768;
#pragma unroll
            for (int i = 0; i < 4; i++) {
                cp16(st + aoff[i], A + (size_t)(bm0 + ar[i]) * KD + k0 + ac[i] * 8);
                cp16(st + boff[i], Bh + (size_t)(k0 + br_[i]) * ND + bn0 + bc[i] * 8);
            }
            asm volatile("cp.async.commit_group;");
        }
    }

    if (QKV) {
        // fused pixel-norm epilogue (validated round 7/8)
        const int gr0  = bm0 + m_off;
        const int comp = gr0 >> 9;
        const int head = (gr0 & 511) >> 6;
        const float sc_num = (comp == 0) ? 1.4426950408889634f : 8.f;
        __half* st = (__half*)(smc + w * 4096);

#pragma unroll
        for (int nt = 0; nt < 4; nt++) {
            float ss0 = 0.f, ss1 = 0.f;
#pragma unroll
            for (int mt = 0; mt < 4; mt++) {
                ss0 += acc[mt][nt][0] * acc[mt][nt][0] + acc[mt][nt][2] * acc[mt][nt][2];
                ss1 += acc[mt][nt][1] * acc[mt][nt][1] + acc[mt][nt][3] * acc[mt][nt][3];
            }
#pragma unroll
            for (int off = 4; off <= 16; off <<= 1) {
                ss0 += __shfl_xor_sync(0xffffffffu, ss0, off);
                ss1 += __shfl_xor_sync(0xffffffffu, ss1, off);
            }
            float s0 = sc_num / fmaxf(sqrtf(ss0), 1e-4f);
            float s1 = sc_num / fmaxf(sqrtf(ss1), 1e-4f);
            int c0 = nt * 8 + 2 * tg;
#pragma unroll
            for (int mt = 0; mt < 4; mt++) {
                int r = mt * 16 + g;
                st[c0 * 64 + r]           = __float2half(acc[mt][nt][0] * s0);
                st[c0 * 64 + r + 8]       = __float2half(acc[mt][nt][2] * s0);
                st[(c0 + 1) * 64 + r]     = __float2half(acc[mt][nt][1] * s1);
                st[(c0 + 1) * 64 + r + 8] = __float2half(acc[mt][nt][3] * s1);
            }
        }
        __syncwarp();
        __half* dst = (comp == 0 ? qn : comp == 1 ? kn : vn) +
                      ((size_t)(b * HEADS + head) * NPIX + bn0 + n_off) * DIMH;
#pragma unroll 8
        for (int c = 0; c < 32; c++) {
            __half2 v = *(__half2*)(st + c * 64 + lane * 2);
            *(__half2*)(dst + (size_t)c * DIMH + lane * 2) = v;
        }
    } else {
        const float a_out = 0.9191450300f;  // 0.7 / sqrt(0.58)
        const float a_x   = 0.3939192986f;  // 0.3 / sqrt(0.58)
        float* Cb = Cf + (size_t)b * MD * ND;
#pragma unroll
        for (int mt = 0; mt < 4; mt++) {
            int r1 = bm0 + m_off + mt * 16 + g;
            int r2 = r1 + 8;
#pragma unroll
            for (int nt = 0; nt < 4; nt++) {
                int col = bn0 + n_off + nt * 8 + 2 * tg;
                float2 v1 = make_float2(acc[mt][nt][0], acc[mt][nt][1]);
                float2 v2 = make_float2(acc[mt][nt][2], acc[mt][nt][3]);
                float2 x1 = *(const float2*)&X[((size_t)b * MD + r1) * ND + col];
                float2 x2 = *(const float2*)&X[((size_t)b * MD + r2) * ND + col];
                v1.x = v1.x * a_out + x1.x * a_x;  v1.y = v1.y * a_out + x1.y * a_x;
                v2.x = v2.x * a_out + x2.x * a_x;  v2.y = v2.y * a_out + x2.y * a_x;
                *(float2*)&Cb[(size_t)r1 * ND + col] = v1;
                *(float2*)&Cb[(size_t)r2 * ND + col] = v2;
            }
        }
    }
}

// ---------------------------------------------------------------------------
// fp16 flash attention, 128-query blocks, cp.async double-buffered K/V
// (validated round 8, unchanged).
// ---------------------------------------------------------------------------
__global__ void __launch_bounds__(256, 2) attn_f16(const __half* __restrict__ qn,
                                                   const __half* __restrict__ kn,
                                                   const __half* __restrict__ vn,
                                                   const __half* __restrict__ km,
                                                   const __half* __restrict__ vm,
                                                   __half* __restrict__ attn_out)
{
    extern __shared__ char smc[];
    const uint32_t sb = (uint32_t)__cvta_generic_to_shared(smc);
    const uint32_t QS = sb, PS = sb + 16384, KS = sb + 32768, VS = sb + 49152;

    const int b = blockIdx.z, h = blockIdx.y, i0 = blockIdx.x * 128;
    const int tid = threadIdx.x, lane = tid & 31;
    const int g = lane >> 2, tg = lane & 3;
    const int m0 = (tid >> 5) * 16;
    const int mat = lane >> 3, rr = lane & 7;

    const __half* qh = qn + ((size_t)(b * HEADS + h) * NPIX + i0) * DIMH;
    const __half* kh = kn + (size_t)(b * HEADS + h) * NPIX * DIMH;
    const __half* vh = vn + (size_t)(b * HEADS + h) * NPIX * DIMH;

    int cr[2], cc[2];
    uint32_t coff[2];
#pragma unroll
    for (int i = 0; i < 2; i++) {
        int idx = tid + i * 256;
        cr[i] = idx >> 3;  cc[i] = idx & 7;
        coff[i] = cr[i] * 128 + ((cc[i] ^ (cr[i] & 7)) << 4);
    }

#pragma unroll
    for (int i = 0; i < 2; i++) {
        int sz = (cr[i] < 4) ? 16 : 0;
        const __half* ks0 = km + ((h * 4 + (cr[i] & 3)) * 64 + cc[i] * 8);
        const __half* vs0 = vm + ((h * 4 + (cr[i] & 3)) * 64 + cc[i] * 8);
        cp16z(KS + coff[i], ks0, sz);
        cp16z(VS + coff[i], vs0, sz);
    }
    asm volatile("cp.async.commit_group;");

    for (int idx = tid; idx < 1024; idx += 256) {
        int r = idx >> 3, c = idx & 7;
        uint4 v = *(const uint4*)(qh + r * 64 + c * 8);
        *(uint4*)(smc + r * 128 + ((c ^ (r & 7)) << 4)) = v;
    }
    __syncthreads();

    uint32_t aq[4][4];
    {
        int qrow = m0 + (mat & 1) * 8 + rr;
#pragma unroll
        for (int kc = 0; kc < 4; kc++) {
            int ch = 2 * kc + (mat >> 1);
            ldsm_x4(aq[kc][0], aq[kc][1], aq[kc][2], aq[kc][3],
                    QS + qrow * 128 + ((ch ^ (qrow & 7)) << 4));
        }
    }

    float oacc[8][4];
#pragma unroll
    for (int nt = 0; nt < 8; nt++)
#pragma unroll
        for (int r = 0; r < 4; r++) oacc[nt][r] = 0.f;
    float mrow[2] = {-1e30f, -1e30f};
    float lrow[2] = {0.f, 0.f};

    for (int t = 0; t <= 16; ++t) {
        __syncthreads();
        if (t < 16) {
            const __half* kt = kh + (size_t)t * 64 * 64;
            const __half* vt = vh + (size_t)t * 64 * 64;
            uint32_t kb = KS + ((t + 1) & 1) * 8192;
            uint32_t vb = VS + ((t + 1) & 1) * 8192;
#pragma unroll
            for (int i = 0; i < 2; i++) {
                cp16(kb + coff[i], kt + cr[i] * 64 + cc[i] * 8);
                cp16(vb + coff[i], vt + cr[i] * 64 + cc[i] * 8);
            }
            asm volatile("cp.async.commit_group;");
            asm volatile("cp.async.wait_group 1;");
        } else {
            asm volatile("cp.async.wait_group 0;");
        }
        __syncthreads();

        const uint32_t kb = KS + (t & 1) * 8192;
        const uint32_t vb = VS + (t & 1) * 8192;

        float sacc[8][4];
#pragma unroll
        for (int nt = 0; nt < 8; nt++)
#pragma unroll
            for (int r = 0; r < 4; r++) sacc[nt][r] = 0.f;
#pragma unroll
        for (int np = 0; np < 4; np++) {
            int key = (2 * np + (mat >> 1)) * 8 + rr;
#pragma unroll
            for (int kc = 0; kc < 4; kc++) {
                int ch = 2 * kc + (mat & 1);
                uint32_t addr = kb + key * 128 + ((ch ^ (key & 7)) << 4);
                uint32_t b0, b1, b2, b3;
                ldsm_x4(b0, b1, b2, b3, addr);
                mma_f16(sacc[2 * np],     aq[kc][0], aq[kc][1], aq[kc][2], aq[kc][3], b0, b1);
                mma_f16(sacc[2 * np + 1], aq[kc][0], aq[kc][1], aq[kc][2], aq[kc][3], b2, b3);
            }
        }
        if (t == 0) {
#pragma unroll
            for (int nt = 0; nt < 8; nt++) {
                int c0 = nt * 8 + 2 * tg;
                if (c0 >= 4)     { sacc[nt][0] = -1e30f; sacc[nt][2] = -1e30f; }
                if (c0 + 1 >= 4) { sacc[nt][1] = -1e30f; sacc[nt][3] = -1e30f; }
            }
        }

        float tm0 = -1e30f, tm1 = -1e30f;
#pragma unroll
        for (int nt = 0; nt < 8; nt++) {
            tm0 = fmaxf(tm0, fmaxf(sacc[nt][0], sacc[nt][1]));
            tm1 = fmaxf(tm1, fmaxf(sacc[nt][2], sacc[nt][3]));
        }
        tm0 = fmaxf(tm0, __shfl_xor_sync(0xffffffffu, tm0, 1));
        tm0 = fmaxf(tm0, __shfl_xor_sync(0xffffffffu, tm0, 2));
        tm1 = fmaxf(tm1, __shfl_xor_sync(0xffffffffu, tm1, 1));
        tm1 = fmaxf(tm1, __shfl_xor_sync(0xffffffffu, tm1, 2));

        float mn0 = fmaxf(mrow[0], tm0), mn1 = fmaxf(mrow[1], tm1);
        float al0 = ex2f(mrow[0] - mn0), al1 = ex2f(mrow[1] - mn1);
        float rs0 = 0.f, rs1 = 0.f;
        const int row0 = m0 + g, row1 = m0 + g + 8;
#pragma unroll
        for (int nt = 0; nt < 8; nt++) {
            float p00 = ex2f(sacc[nt][0] - mn0);
            float p01 = ex2f(sacc[nt][1] - mn0);
            float p10 = ex2f(sacc[nt][2] - mn1);
            float p11 = ex2f(sacc[nt][3] - mn1);
            rs0 += p00 + p01;  rs1 += p10 + p11;
            uint32_t a0 = PS + row0 * 128 + ((nt ^ (row0 & 7)) << 4) + (tg << 2);
            uint32_t a1 = PS + row1 * 128 + ((nt ^ (row1 & 7)) << 4) + (tg << 2);
            __half2 h0 = __floats2half2_rn(p00, p01);
            __half2 h1 = __floats2half2_rn(p10, p11);
            asm volatile("st.shared.b32 [%0], %1;" :: "r"(a0), "r"(*(uint32_t*)&h0));
            asm volatile("st.shared.b32 [%0], %1;" :: "r"(a1), "r"(*(uint32_t*)&h1));
        }
        rs0 += __shfl_xor_sync(0xffffffffu, rs0, 1);
        rs0 += __shfl_xor_sync(0xffffffffu, rs0, 2);
        rs1 += __shfl_xor_sync(0xffffffffu, rs1, 1);
        rs1 += __shfl_xor_sync(0xffffffffu, rs1, 2);
        lrow[0] = lrow[0] * al0 + rs0;  mrow[0] = mn0;
        lrow[1] = lrow[1] * al1 + rs1;  mrow[1] = mn1;
#pragma unroll
        for (int nt = 0; nt < 8; nt++) {
            oacc[nt][0] *= al0;  oacc[nt][1] *= al0;
            oacc[nt][2] *= al1;  oacc[nt][3] *= al1;
        }
        __syncwarp();

#pragma unroll
        for (int kc = 0; kc < 4; kc++) {
            int prow = m0 + (mat & 1) * 8 + rr;
            int pch = 2 * kc + (mat >> 1);
            uint32_t paddr = PS + prow * 128 + ((pch ^ (prow & 7)) << 4);
            uint32_t a0, a1, a2, a3;
            ldsm_x4(a0, a1, a2, a3, paddr);
            int key = kc * 16 + (mat & 1) * 8 + rr;
#pragma unroll
            for (int np = 0; np < 4; np++) {
                int ch = 2 * np + (mat >> 1);
                uint32_t vaddr = vb + key * 128 + ((ch ^ (key & 7)) << 4);
                uint32_t b0, b1, b2, b3;
                ldsm_x4t(b0, b1, b2, b3, vaddr);
                mma_f16(oacc[2 * np],     a0, a1, a2, a3, b0, b1);
                mma_f16(oacc[2 * np + 1], a0, a1, a2, a3, b2, b3);
            }
        }
    }

    __syncthreads();
    float* fs = (float*)smc;
    {
        float il0 = 1.f / lrow[0], il1 = 1.f / lrow[1];
        const int row0 = m0 + g, row1 = m0 + g + 8;
#pragma unroll
        for (int nt = 0; nt < 8; nt++) {
            int c = nt * 8 + 2 * tg;
            fs[row0 * 66 + c]     = oacc[nt][0] * il0;
            fs[row0 * 66 + c + 1] = oacc[nt][1] * il0;
            fs[row1 * 66 + c]     = oacc[nt][2] * il1;
            fs[row1 * 66 + c + 1] = oacc[nt][3] * il1;
        }
    }
    __syncthreads();
    {
        __half* ob = attn_out + ((size_t)b * HID + h * DIMH) * NPIX;
        for (int idx = tid; idx < 128 * 64; idx += 256) {
            int m = idx & 127, d = idx >> 7;
            ob[(size_t)d * NPIX + i0 + m] = __float2half(fs[m * 66 + d]);
        }
    }
}

// ---------------------------------------------------------------------------
extern "C" void kernel_launch(void* const* d_in, const int* in_sizes, int n_in,
                              void* d_out, int out_size)
{
    const float* x      = (const float*)d_in[0];  // [16,512,32,32]
    const float* w_qkv  = (const float*)d_in[1];  // [1536,512]
    const float* w_out  = (const float*)d_in[2];  // [512,512]
    const float* mem_kv = (const float*)d_in[3];  // [2,8,4,64]
    float* out = (float*)d_out;                   // [16,512,32,32]

    __half *wnq, *wno, *xh, *attn, *qn, *kn, *vn, *km, *vm;
    cudaGetSymbolAddress((void**)&wnq,  g_wn_qkv);
    cudaGetSymbolAddress((void**)&wno,  g_wn_out);
    cudaGetSymbolAddress((void**)&xh,   g_xh);
    cudaGetSymbolAddress((void**)&attn, g_attn);
    cudaGetSymbolAddress((void**)&qn,   g_qn);
    cudaGetSymbolAddress((void**)&kn,   g_kn);
    cudaGetSymbolAddress((void**)&vn,   g_vn);
    cudaGetSymbolAddress((void**)&km,   g_km);
    cudaGetSymbolAddress((void**)&vm,   g_vm);

    cudaFuncSetAttribute(hgemm_pipe<K3, true>,
                         cudaFuncAttributeMaxDynamicSharedMemorySize, 65536);
    cudaFuncSetAttribute(hgemm_pipe<CIN, false>,
                         cudaFuncAttributeMaxDynamicSharedMemorySize, 65536);
    cudaFuncSetAttribute(attn_f16, cudaFuncAttributeMaxDynamicSharedMemorySize, 65536);

    // prep: weight norms + mem_kv norm + x->fp16 (2048 extra blocks)
    prep_kernel<<<PREP_X + 2048, 256>>>(w_qkv, w_out, mem_kv, x,
                                        wnq, wno, km, vm, xh);

    // QKV projection with fused pixel-norm
    hgemm_pipe<K3, true><<<dim3(8, K3 / 128, NB), 256, 65536>>>(
        wnq, xh, qn, kn, vn, nullptr, nullptr);

    // Attention
    attn_f16<<<dim3(NPIX / 128, HEADS, NB), 256, 65536>>>(qn, kn, vn, km, vm, attn);

    // Output projection + MPAdd residual
    hgemm_pipe<CIN, false><<<dim3(8, CIN / 128, NB), 256, 65536>>>(
        wno, attn, nullptr, nullptr, nullptr, out, x);
}

// round 10
// speedup vs baseline: 7.6063x; 1.0046x over previous
#include <cuda_runtime.h>
#include <cuda_fp16.h>
#include <math.h>
#include <stdint.h>

#define NB    16
#define CIN   512
#define NPIX  1024
#define HEADS 8
#define DIMH  64
#define HID   512
#define K3    1536   // 3*HID

// Scratch (allocation-free, device globals)
__device__ __half g_wn_qkv[K3 * CIN];
__device__ __half g_wn_out[CIN * HID];
__device__ __half g_xh[(size_t)NB * CIN * NPIX];          // fp16 copy of x
__device__ __half g_attn[(size_t)NB * HID * NPIX];
__device__ __half g_qn[(size_t)NB * HEADS * NPIX * DIMH];
__device__ __half g_kn[(size_t)NB * HEADS * NPIX * DIMH];
__device__ __half g_vn[(size_t)NB * HEADS * NPIX * DIMH];
__device__ __half g_km[HEADS * 4 * DIMH];
__device__ __half g_vm[HEADS * 4 * DIMH];

// ---------------------------------------------------------------------------
// helpers
// ---------------------------------------------------------------------------
__device__ __forceinline__ float ex2f(float x) {
    float y;
    asm("ex2.approx.f32 %0, %1;" : "=f"(y) : "f"(x));
    return y;
}
__device__ __forceinline__ void mma_f16(float (&d)[4],
                                        uint32_t a0, uint32_t a1, uint32_t a2, uint32_t a3,
                                        uint32_t b0, uint32_t b1) {
    asm volatile(
        "mma.sync.aligned.m16n8k16.row.col.f32.f16.f16.f32 "
        "{%0,%1,%2,%3}, {%4,%5,%6,%7}, {%8,%9}, {%0,%1,%2,%3};"
        : "+f"(d[0]), "+f"(d[1]), "+f"(d[2]), "+f"(d[3])
        : "r"(a0), "r"(a1), "r"(a2), "r"(a3), "r"(b0), "r"(b1));
}
__device__ __forceinline__ void ldsm_x4(uint32_t& r0, uint32_t& r1, uint32_t& r2,
                                        uint32_t& r3, uint32_t addr) {
    asm volatile("ldmatrix.sync.aligned.m8n8.x4.shared.b16 {%0,%1,%2,%3}, [%4];"
                 : "=r"(r0), "=r"(r1), "=r"(r2), "=r"(r3) : "r"(addr));
}
__device__ __forceinline__ void ldsm_x4t(uint32_t& r0, uint32_t& r1, uint32_t& r2,
                                         uint32_t& r3, uint32_t addr) {
    asm volatile("ldmatrix.sync.aligned.m8n8.x4.trans.shared.b16 {%0,%1,%2,%3}, [%4];"
                 : "=r"(r0), "=r"(r1), "=r"(r2), "=r"(r3) : "r"(addr));
}
__device__ __forceinline__ void cp16(uint32_t s, const void* g) {
    asm volatile("cp.async.cg.shared.global [%0], [%1], 16;" :: "r"(s), "l"(g));
}
__device__ __forceinline__ void cp16z(uint32_t s, const void* g, int sz) {
    asm volatile("cp.async.cg.shared.global [%0], [%1], 16, %2;"
                 :: "r"(s), "l"(g), "r"(sz));
}

// ---------------------------------------------------------------------------
// prep: weight norms (fan-in 512) + mem_kv norm + x fp32->fp16 conversion.
// ---------------------------------------------------------------------------
#define PREP_MEMKV (K3 + CIN)
#define PREP_X     (K3 + CIN + 64)

__global__ void __launch_bounds__(256) prep_kernel(const float* __restrict__ w_qkv,
                                                   const float* __restrict__ w_out,
                                                   const float* __restrict__ mem_kv,
                                                   const float* __restrict__ x,
                                                   __half* __restrict__ wnq,
                                                   __half* __restrict__ wno,
                                                   __half* __restrict__ km,
                                                   __half* __restrict__ vm,
                                                   __half* __restrict__ xh)
{
    int r = blockIdx.x;
    if (r >= PREP_X) {
        size_t base = (size_t)(r - PREP_X) * 4096;
#pragma unroll
        for (int j = 0; j < 2; j++) {
            size_t off = base + ((size_t)j * 256 + threadIdx.x) * 8;
            float4 f0 = *(const float4*)(x + off);
            float4 f1 = *(const float4*)(x + off + 4);
            __half2 h0 = __floats2half2_rn(f0.x, f0.y);
            __half2 h1 = __floats2half2_rn(f0.z, f0.w);
            __half2 h2 = __floats2half2_rn(f1.x, f1.y);
            __half2 h3 = __floats2half2_rn(f1.z, f1.w);
            uint4 pk;
            pk.x = *(uint32_t*)&h0; pk.y = *(uint32_t*)&h1;
            pk.z = *(uint32_t*)&h2; pk.w = *(uint32_t*)&h3;
            *(uint4*)(xh + off) = pk;
        }
        return;
    }
    if (r >= PREP_MEMKV) {
        if (threadIdx.x < 32) {
            int row = r - PREP_MEMKV;
            int part = row >> 5, rk = row & 31;
            const float* src = mem_kv + part * 2048 + rk * 64;
            float v0 = src[threadIdx.x], v1 = src[threadIdx.x + 32];
            float s = v0 * v0 + v1 * v1;
#pragma unroll
            for (int off = 16; off; off >>= 1) s += __shfl_xor_sync(0xffffffffu, s, off);
            float sc = 8.f / fmaxf(sqrtf(s), 1e-4f);
            __half* dst = (part ? vm : km) + rk * 64;
            dst[threadIdx.x]      = __float2half(v0 * sc);
            dst[threadIdx.x + 32] = __float2half(v1 * sc);
        }
        return;
    }
    const float* wr;
    __half* out;
    if (r < K3) { wr = w_qkv + (size_t)r * CIN;        out = wnq + (size_t)r * CIN; }
    else        { wr = w_out + (size_t)(r - K3) * HID; out = wno + (size_t)(r - K3) * HID; }
    float s = 0.f;
    for (int i = threadIdx.x; i < 512; i += 256) { float v = wr[i]; s += v * v; }
    __shared__ float red[8];
#pragma unroll
    for (int off = 16; off; off >>= 1) s += __shfl_xor_sync(0xffffffffu, s, off);
    if ((threadIdx.x & 31) == 0) red[threadIdx.x >> 5] = s;
    __syncthreads();
    if (threadIdx.x == 0) {
        float v = 0.f;
#pragma unroll
        for (int i = 0; i < 8; i++) v += red[i];
        red[0] = v;
    }
    __syncthreads();
    float inv = 1.f / (1e-4f * 22.627416998f + sqrtf(red[0]));
    for (int i = threadIdx.x; i < 512; i += 256)
        out[i] = __float2half(wr[i] * inv);
}

// ---------------------------------------------------------------------------
// 3-stage cp.async fp16 GEMM: C[b](MDx1024) = A(MDx512) * B[b](512x1024).
// 3 smem stages of (A 16KB + B 16KB) = 96KB dynamic; ONE sync per k-slab.
// QKV=true : fused pixel-norm epilogue -> qn/kn/vn. QKV=false: MPAdd -> fp32.
// ---------------------------------------------------------------------------
template<int MD, bool QKV>
__global__ void __launch_bounds__(256, 2) hgemm_pipe(const __half* __restrict__ A,
                                                     const __half* __restrict__ Bm,
                                                     __half* __restrict__ qn,
                                                     __half* __restrict__ kn,
                                                     __half* __restrict__ vn,
                                                     float* __restrict__ Cf,
                                                     const float* __restrict__ X)
{
    constexpr int ND = 1024, KD = 512;
    extern __shared__ char smc[];
    const uint32_t sb = (uint32_t)__cvta_generic_to_shared(smc);

    const int b   = blockIdx.z;
    const int bm0 = blockIdx.y * 128;
    const int bn0 = blockIdx.x * 128;
    const __half* Bh = Bm + (size_t)b * KD * ND;

    const int tid = threadIdx.x;
    const int w = tid >> 5, lane = tid & 31;
    const int g = lane >> 2, tg = lane & 3;
    const int mat = lane >> 3, rr = lane & 7;
    const int m_off = (w >> 2) * 64;
    const int n_off = (w & 3) * 32;

    float acc[4][4][4];
#pragma unroll
    for (int i = 0; i < 4; i++)
#pragma unroll
        for (int j = 0; j < 4; j++)
#pragma unroll
            for (int r = 0; r < 4; r++) acc[i][j][r] = 0.f;

    int ar[4], ac[4], br_[4], bc[4];
    uint32_t aoff[4], boff[4];
#pragma unroll
    for (int i = 0; i < 4; i++) {
        int cid = i * 256 + tid;
        ar[i] = cid >> 3;  ac[i] = cid & 7;
        br_[i] = cid >> 4; bc[i] = cid & 15;
        aoff[i] = ar[i] * 128 + ((ac[i] ^ (ar[i] & 7)) << 4);
        boff[i] = 16384 + br_[i] * 256 +
                  (((bc[i] & 8) | ((bc[i] & 7) ^ (br_[i] & 7))) << 4);
    }

    // prologue: slabs 0,1 into stages 0,1
#pragma unroll
    for (int s = 0; s < 2; s++) {
        int k0 = s * 64;
        uint32_t st = sb + s * 32768;
#pragma unroll
        for (int i = 0; i < 4; i++) {
            cp16(st + aoff[i], A + (size_t)(bm0 + ar[i]) * KD + k0 + ac[i] * 8);
            cp16(st + boff[i], Bh + (size_t)(k0 + br_[i]) * ND + bn0 + bc[i] * 8);
        }
        asm volatile("cp.async.commit_group;");
    }

    int s_comp = 0, s_issue = 2;
    for (int it = 0; it < 8; ++it) {
        if (it < 7) asm volatile("cp.async.wait_group 1;");
        else        asm volatile("cp.async.wait_group 0;");
        __syncthreads();   // slab it visible; stage s_issue's old contents consumed

        if (it + 2 < 8) {
            int k0 = (it + 2) * 64;
            uint32_t st = sb + s_issue * 32768;
#pragma unroll
            for (int i = 0; i < 4; i++) {
                cp16(st + aoff[i], A + (size_t)(bm0 + ar[i]) * KD + k0 + ac[i] * 8);
                cp16(st + boff[i], Bh + (size_t)(k0 + br_[i]) * ND + bn0 + bc[i] * 8);
            }
            asm volatile("cp.async.commit_group;");
            s_issue++; if (s_issue == 3) s_issue = 0;
        }

        const uint32_t AS = sb + s_comp * 32768;
        const uint32_t BS = AS + 16384;
        s_comp++; if (s_comp == 3) s_comp = 0;
#pragma unroll
        for (int kk = 0; kk < 4; kk++) {
            uint32_t af[4][4];
#pragma unroll
            for (int mt = 0; mt < 4; mt++) {
                int row = m_off + mt * 16 + (mat & 1) * 8 + rr;
                int ch = kk * 2 + (mat >> 1);
                ldsm_x4(af[mt][0], af[mt][1], af[mt][2], af[mt][3],
                        AS + row * 128 + ((ch ^ (row & 7)) << 4));
            }
#pragma unroll
            for (int np = 0; np < 2; np++) {
                int row = kk * 16 + (mat & 1) * 8 + rr;
                int c = (n_off >> 3) + np * 2 + (mat >> 1);
                uint32_t b0, b1, b2, b3;
                ldsm_x4t(b0, b1, b2, b3,
                         BS + row * 256 + (((c & 8) | ((c & 7) ^ (row & 7))) << 4));
#pragma unroll
                for (int mt = 0; mt < 4; mt++) {
                    mma_f16(acc[mt][np * 2],     af[mt][0], af[mt][1], af[mt][2], af[mt][3], b0, b1);
                    mma_f16(acc[mt][np * 2 + 1], af[mt][0], af[mt][1], af[mt][2], af[mt][3], b2, b3);
                }
            }
        }
    }

    if (QKV) {
        // fused pixel-norm epilogue; staging at smc[w*4096] (stage 0 region,
        // warp-private, last compute used stage 1 -> disjoint)
        __syncthreads();
        const int gr0  = bm0 + m_off;
        const int comp = gr0 >> 9;
        const int head = (gr0 & 511) >> 6;
        const float sc_num = (comp == 0) ? 1.4426950408889634f : 8.f;
        __half* st = (__half*)(smc + w * 4096);

#pragma unroll
        for (int nt = 0; nt < 4; nt++) {
            float ss0 = 0.f, ss1 = 0.f;
#pragma unroll
            for (int mt = 0; mt < 4; mt++) {
                ss0 += acc[mt][nt][0] * acc[mt][nt][0] + acc[mt][nt][2] * acc[mt][nt][2];
                ss1 += acc[mt][nt][1] * acc[mt][nt][1] + acc[mt][nt][3] * acc[mt][nt][3];
            }
#pragma unroll
            for (int off = 4; off <= 16; off <<= 1) {
                ss0 += __shfl_xor_sync(0xffffffffu, ss0, off);
                ss1 += __shfl_xor_sync(0xffffffffu, ss1, off);
            }
            float s0 = sc_num / fmaxf(sqrtf(ss0), 1e-4f);
            float s1 = sc_num / fmaxf(sqrtf(ss1), 1e-4f);
            int c0 = nt * 8 + 2 * tg;
#pragma unroll
            for (int mt = 0; mt < 4; mt++) {
                int r = mt * 16 + g;
                st[c0 * 64 + r]           = __float2half(acc[mt][nt][0] * s0);
                st[c0 * 64 + r + 8]       = __float2half(acc[mt][nt][2] * s0);
                st[(c0 + 1) * 64 + r]     = __float2half(acc[mt][nt][1] * s1);
                st[(c0 + 1) * 64 + r + 8] = __float2half(acc[mt][nt][3] * s1);
            }
        }
        __syncwarp();
        __half* dst = (comp == 0 ? qn : comp == 1 ? kn : vn) +
                      ((size_t)(b * HEADS + head) * NPIX + bn0 + n_off) * DIMH;
#pragma unroll 8
        for (int c = 0; c < 32; c++) {
            __half2 v = *(__half2*)(st + c * 64 + lane * 2);
            *(__half2*)(dst + (size_t)c * DIMH + lane * 2) = v;
        }
    } else {
        const float a_out = 0.9191450300f;  // 0.7 / sqrt(0.58)
        const float a_x   = 0.3939192986f;  // 0.3 / sqrt(0.58)
        float* Cb = Cf + (size_t)b * MD * ND;
#pragma unroll
        for (int mt = 0; mt < 4; mt++) {
            int r1 = bm0 + m_off + mt * 16 + g;
            int r2 = r1 + 8;
#pragma unroll
            for (int nt = 0; nt < 4; nt++) {
                int col = bn0 + n_off + nt * 8 + 2 * tg;
                float2 v1 = make_float2(acc[mt][nt][0], acc[mt][nt][1]);
                float2 v2 = make_float2(acc[mt][nt][2], acc[mt][nt][3]);
                float2 x1 = *(const float2*)&X[((size_t)b * MD + r1) * ND + col];
                float2 x2 = *(const float2*)&X[((size_t)b * MD + r2) * ND + col];
                v1.x = v1.x * a_out + x1.x * a_x;  v1.y = v1.y * a_out + x1.y * a_x;
                v2.x = v2.x * a_out + x2.x * a_x;  v2.y = v2.y * a_out + x2.y * a_x;
                *(float2*)&Cb[(size_t)r1 * ND + col] = v1;
                *(float2*)&Cb[(size_t)r2 * ND + col] = v2;
            }
        }
    }
}

// ---------------------------------------------------------------------------
// fp16 flash attention, 128-query blocks, 3-stage cp.async K/V pipeline,
// ONE sync per key tile. smem 80KB: Q[0,16K) P[16K,32K) K 3x8K [32K,56K)
// V 3x8K [56K,80K).
// ---------------------------------------------------------------------------
__global__ void __launch_bounds__(256, 2) attn_f16(const __half* __restrict__ qn,
                                                   const __half* __restrict__ kn,
                                                   const __half* __restrict__ vn,
                                                   const __half* __restrict__ km,
                                                   const __half* __restrict__ vm,
                                                   __half* __restrict__ attn_out)
{
    extern __shared__ char smc[];
    const uint32_t sb = (uint32_t)__cvta_generic_to_shared(smc);
    const uint32_t QS = sb, PS = sb + 16384, KS = sb + 32768, VS = sb + 57344;

    const int b = blockIdx.z, h = blockIdx.y, i0 = blockIdx.x * 128;
    const int tid = threadIdx.x, lane = tid & 31;
    const int g = lane >> 2, tg = lane & 3;
    const int m0 = (tid >> 5) * 16;
    const int mat = lane >> 3, rr = lane & 7;

    const __half* qh = qn + ((size_t)(b * HEADS + h) * NPIX + i0) * DIMH;
    const __half* kh = kn + (size_t)(b * HEADS + h) * NPIX * DIMH;
    const __half* vh = vn + (size_t)(b * HEADS + h) * NPIX * DIMH;

    int cr[2], cc[2];
    uint32_t coff[2];
#pragma unroll
    for (int i = 0; i < 2; i++) {
        int idx = tid + i * 256;
        cr[i] = idx >> 3;  cc[i] = idx & 7;
        coff[i] = cr[i] * 128 + ((cc[i] ^ (cr[i] & 7)) << 4);
    }

    // prologue: tile 0 (mem-kv) -> buf 0, tile 1 (spatial 0) -> buf 1
#pragma unroll
    for (int i = 0; i < 2; i++) {
        int sz = (cr[i] < 4) ? 16 : 0;
        cp16z(KS + coff[i], km + ((h * 4 + (cr[i] & 3)) * 64 + cc[i] * 8), sz);
        cp16z(VS + coff[i], vm + ((h * 4 + (cr[i] & 3)) * 64 + cc[i] * 8), sz);
    }
    asm volatile("cp.async.commit_group;");
#pragma unroll
    for (int i = 0; i < 2; i++) {
        cp16(KS + 8192 + coff[i], kh + cr[i] * 64 + cc[i] * 8);
        cp16(VS + 8192 + coff[i], vh + cr[i] * 64 + cc[i] * 8);
    }
    asm volatile("cp.async.commit_group;");

    // load Q tile while tiles 0/1 are in flight
    for (int idx = tid; idx < 1024; idx += 256) {
        int r = idx >> 3, c = idx & 7;
        uint4 v = *(const uint4*)(qh + r * 64 + c * 8);
        *(uint4*)(smc + r * 128 + ((c ^ (r & 7)) << 4)) = v;
    }
    __syncthreads();

    uint32_t aq[4][4];
    {
        int qrow = m0 + (mat & 1) * 8 + rr;
#pragma unroll
        for (int kc = 0; kc < 4; kc++) {
            int ch = 2 * kc + (mat >> 1);
            ldsm_x4(aq[kc][0], aq[kc][1], aq[kc][2], aq[kc][3],
                    QS + qrow * 128 + ((ch ^ (qrow & 7)) << 4));
        }
    }

    float oacc[8][4];
#pragma unroll
    for (int nt = 0; nt < 8; nt++)
#pragma unroll
        for (int r = 0; r < 4; r++) oacc[nt][r] = 0.f;
    float mrow[2] = {-1e30f, -1e30f};
    float lrow[2] = {0.f, 0.f};

    int s_comp = 0, s_issue = 2;
    for (int t = 0; t <= 16; ++t) {
        if (t < 16) asm volatile("cp.async.wait_group 1;");
        else        asm volatile("cp.async.wait_group 0;");
        __syncthreads();   // tile t visible; buf s_issue's old contents consumed

        if (t + 2 <= 16) {
            const __half* kt = kh + (size_t)(t + 1) * 64 * 64;
            const __half* vt = vh + (size_t)(t + 1) * 64 * 64;
            uint32_t kb = KS + s_issue * 8192;
            uint32_t vb = VS + s_issue * 8192;
#pragma unroll
            for (int i = 0; i < 2; i++) {
                cp16(kb + coff[i], kt + cr[i] * 64 + cc[i] * 8);
                cp16(vb + coff[i], vt + cr[i] * 64 + cc[i] * 8);
            }
            asm volatile("cp.async.commit_group;");
            s_issue++; if (s_issue == 3) s_issue = 0;
        }

        const uint32_t kb = KS + s_comp * 8192;
        const uint32_t vb = VS + s_comp * 8192;
        s_comp++; if (s_comp == 3) s_comp = 0;

        // ---- S = Q.K^T
        float sacc[8][4];
#pragma unroll
        for (int nt = 0; nt < 8; nt++)
#pragma unroll
            for (int r = 0; r < 4; r++) sacc[nt][r] = 0.f;
#pragma unroll
        for (int np = 0; np < 4; np++) {
            int key = (2 * np + (mat >> 1)) * 8 + rr;
#pragma unroll
            for (int kc = 0; kc < 4; kc++) {
                int ch = 2 * kc + (mat & 1);
                uint32_t addr = kb + key * 128 + ((ch ^ (key & 7)) << 4);
                uint32_t b0, b1, b2, b3;
                ldsm_x4(b0, b1, b2, b3, addr);
                mma_f16(sacc[2 * np],     aq[kc][0], aq[kc][1], aq[kc][2], aq[kc][3], b0, b1);
                mma_f16(sacc[2 * np + 1], aq[kc][0], aq[kc][1], aq[kc][2], aq[kc][3], b2, b3);
            }
        }
        if (t == 0) {
#pragma unroll
            for (int nt = 0; nt < 8; nt++) {
                int c0 = nt * 8 + 2 * tg;
                if (c0 >= 4)     { sacc[nt][0] = -1e30f; sacc[nt][2] = -1e30f; }
                if (c0 + 1 >= 4) { sacc[nt][1] = -1e30f; sacc[nt][3] = -1e30f; }
            }
        }

        // ---- online softmax
        float tm0 = -1e30f, tm1 = -1e30f;
#pragma unroll
        for (int nt = 0; nt < 8; nt++) {
            tm0 = fmaxf(tm0, fmaxf(sacc[nt][0], sacc[nt][1]));
            tm1 = fmaxf(tm1, fmaxf(sacc[nt][2], sacc[nt][3]));
        }
        tm0 = fmaxf(tm0, __shfl_xor_sync(0xffffffffu, tm0, 1));
        tm0 = fmaxf(tm0, __shfl_xor_sync(0xffffffffu, tm0, 2));
        tm1 = fmaxf(tm1, __shfl_xor_sync(0xffffffffu, tm1, 1));
        tm1 = fmaxf(tm1, __shfl_xor_sync(0xffffffffu, tm1, 2));

        float mn0 = fmaxf(mrow[0], tm0), mn1 = fmaxf(mrow[1], tm1);
        float al0 = ex2f(mrow[0] - mn0), al1 = ex2f(mrow[1] - mn1);
        float rs0 = 0.f, rs1 = 0.f;
        const int row0 = m0 + g, row1 = m0 + g + 8;
#pragma unroll
        for (int nt = 0; nt < 8; nt++) {
            float p00 = ex2f(sacc[nt][0] - mn0);
            float p01 = ex2f(sacc[nt][1] - mn0);
            float p10 = ex2f(sacc[nt][2] - mn1);
            float p11 = ex2f(sacc[nt][3] - mn1);
            rs0 += p00 + p01;  rs1 += p10 + p11;
            uint32_t a0 = PS + row0 * 128 + ((nt ^ (row0 & 7)) << 4) + (tg << 2);
            uint32_t a1 = PS + row1 * 128 + ((nt ^ (row1 & 7)) << 4) + (tg << 2);
            __half2 h0 = __floats2half2_rn(p00, p01);
            __half2 h1 = __floats2half2_rn(p10, p11);
            asm volatile("st.shared.b32 [%0], %1;" :: "r"(a0), "r"(*(uint32_t*)&h0));
            asm volatile("st.shared.b32 [%0], %1;" :: "r"(a1), "r"(*(uint32_t*)&h1));
        }
        rs0 += __shfl_xor_sync(0xffffffffu, rs0, 1);
        rs0 += __shfl_xor_sync(0xffffffffu, rs0, 2);
        rs1 += __shfl_xor_sync(0xffffffffu, rs1, 1);
        rs1 += __shfl_xor_sync(0xffffffffu, rs1, 2);
        lrow[0] = lrow[0] * al0 + rs0;  mrow[0] = mn0;
        lrow[1] = lrow[1] * al1 + rs1;  mrow[1] = mn1;
#pragma unroll
        for (int nt = 0; nt < 8; nt++) {
            oacc[nt][0] *= al0;  oacc[nt][1] *= al0;
            oacc[nt][2] *= al1;  oacc[nt][3] *= al1;
        }
        __syncwarp();   // Ps rows m0..m0+15 are warp-private

        // ---- O += P.V
#pragma unroll
        for (int kc = 0; kc < 4; kc++) {
            int prow = m0 + (mat & 1) * 8 + rr;
            int pch = 2 * kc + (mat >> 1);
            uint32_t paddr = PS + prow * 128 + ((pch ^ (prow & 7)) << 4);
            uint32_t a0, a1, a2, a3;
            ldsm_x4(a0, a1, a2, a3, paddr);
            int key = kc * 16 + (mat & 1) * 8 + rr;
#pragma unroll
            for (int np = 0; np < 4; np++) {
                int ch = 2 * np + (mat >> 1);
                uint32_t vaddr = vb + key * 128 + ((ch ^ (key & 7)) << 4);
                uint32_t b0, b1, b2, b3;
                ldsm_x4t(b0, b1, b2, b3, vaddr);
                mma_f16(oacc[2 * np],     a0, a1, a2, a3, b0, b1);
                mma_f16(oacc[2 * np + 1], a0, a1, a2, a3, b2, b3);
            }
        }
    }

    __syncthreads();
    float* fs = (float*)smc;   // 128 x 66 fp32 = 33792B (overlays Q/P/K0 - done)
    {
        float il0 = 1.f / lrow[0], il1 = 1.f / lrow[1];
        const int row0 = m0 + g, row1 = m0 + g + 8;
#pragma unroll
        for (int nt = 0; nt < 8; nt++) {
            int c = nt * 8 + 2 * tg;
            fs[row0 * 66 + c]     = oacc[nt][0] * il0;
            fs[row0 * 66 + c + 1] = oacc[nt][1] * il0;
            fs[row1 * 66 + c]     = oacc[nt][2] * il1;
            fs[row1 * 66 + c + 1] = oacc[nt][3] * il1;
        }
    }
    __syncthreads();
    {
        __half* ob = attn_out + ((size_t)b * HID + h * DIMH) * NPIX;
        for (int idx = tid; idx < 128 * 64; idx += 256) {
            int m = idx & 127, d = idx >> 7;
            ob[(size_t)d * NPIX + i0 + m] = __float2half(fs[m * 66 + d]);
        }
    }
}

// ---------------------------------------------------------------------------
extern "C" void kernel_launch(void* const* d_in, const int* in_sizes, int n_in,
                              void* d_out, int out_size)
{
    const float* x      = (const float*)d_in[0];  // [16,512,32,32]
    const float* w_qkv  = (const float*)d_in[1];  // [1536,512]
    const float* w_out  = (const float*)d_in[2];  // [512,512]
    const float* mem_kv = (const float*)d_in[3];  // [2,8,4,64]
    float* out = (float*)d_out;                   // [16,512,32,32]

    __half *wnq, *wno, *xh, *attn, *qn, *kn, *vn, *km, *vm;
    cudaGetSymbolAddress((void**)&wnq,  g_wn_qkv);
    cudaGetSymbolAddress((void**)&wno,  g_wn_out);
    cudaGetSymbolAddress((void**)&xh,   g_xh);
    cudaGetSymbolAddress((void**)&attn, g_attn);
    cudaGetSymbolAddress((void**)&qn,   g_qn);
    cudaGetSymbolAddress((void**)&kn,   g_kn);
    cudaGetSymbolAddress((void**)&vn,   g_vn);
    cudaGetSymbolAddress((void**)&km,   g_km);
    cudaGetSymbolAddress((void**)&vm,   g_vm);

    cudaFuncSetAttribute(hgemm_pipe<K3, true>,
                         cudaFuncAttributeMaxDynamicSharedMemorySize, 98304);
    cudaFuncSetAttribute(hgemm_pipe<CIN, false>,
                         cudaFuncAttributeMaxDynamicSharedMemorySize, 98304);
    cudaFuncSetAttribute(attn_f16, cudaFuncAttributeMaxDynamicSharedMemorySize, 81920);

    // prep: weight norms + mem_kv norm + x->fp16
    prep_kernel<<<PREP_X + 2048, 256>>>(w_qkv, w_out, mem_kv, x,
                                        wnq, wno, km, vm, xh);

    // QKV projection with fused pixel-norm
    hgemm_pipe<K3, true><<<dim3(8, K3 / 128, NB), 256, 98304>>>(
        wnq, xh, qn, kn, vn, nullptr, nullptr);

    // Attention
    attn_f16<<<dim3(NPIX / 128, HEADS, NB), 256, 81920>>>(qn, kn, vn, km, vm, attn);

    // Output projection + MPAdd residual
    hgemm_pipe<CIN, false><<<dim3(8, CIN / 128, NB), 256, 98304>>>(
        wno, attn, nullptr, nullptr, nullptr, out, x);
}